// round 12
// baseline (speedup 1.0000x reference)
#include <cuda_runtime.h>
#include <cuda_bf16.h>
#include <stdint.h>
#include <math.h>

#define NN 50000
#define EE 800000
#define HH 256
#define GG 64
#define NEXP 4
#define OD 128

// ---------------- scratch (device globals: no allocation allowed) ----------------
__device__ __align__(16) float g_h1[NN*HH];
__device__ __align__(16) float g_h[NN*HH];
__device__ __align__(16) uint32_t g_hp[NN*HH];        // h packed hi/lo
__device__ __align__(16) uint32_t g_agg[NN*HH];       // aggregate(h) packed
__device__ __align__(16) float g_sf[NN*3];
__device__ __align__(16) float g_w[NN*NEXP];
__device__ __align__(16) uint32_t g_hE0[(long)NEXP*NN*HH];   // packed, used as [NN][1024]
__device__ __align__(16) uint32_t g_hE1[(long)NEXP*NN*HH];   // packed per-expert
__device__ __align__(16) uint32_t g_aggE[(long)NEXP*NN*HH];  // packed (aggE, then t_e/agg_te)
__device__ int   g_deg[NN];
__device__ int   g_rowptr[NN+1];
__device__ int   g_cur[NN];
__device__ int   g_esrc[EE];
__device__ int   g_bsum[64];
__device__ int   g_ncnt[GG];
__device__ int   g_ecnt[GG];
__device__ float g_featsn[GG*3];
__device__ float g_lognn[GG];
__device__ float g_zero[HH];                          // stays zero
#define WBUF_ELEMS 2883584
__device__ __align__(16) __nv_bfloat16 g_wbuf[WBUF_ELEMS];
__device__ __align__(16) float g_wt[2*65536];         // fp32 W^T: enc_W2, r_W1[:256]

// wbuf layout (elements):
#define OFF_L0C   0        // L0 rel concat [1024][256] hi + lo (524288)
#define OFF_L0CR  524288   // L0 root concat (524288)
#define OFF_L1    1048576  // per-expert stride 262144 (rel hi/lo, root hi/lo at +131072)
#define OFF_L2    2097152  // per-expert stride 131072 (rel at +0, root at +65536)

// ======================= helpers =======================
__device__ __forceinline__ uint32_t smem_u32(const void* p){
    uint32_t a;
    asm("{ .reg .u64 t; cvta.to.shared.u64 t, %1; cvt.u32.u64 %0, t; }" : "=r"(a) : "l"(p));
    return a;
}
__device__ __forceinline__ void ldm4(uint32_t* r, uint32_t addr){
    asm volatile("ldmatrix.sync.aligned.m8n8.x4.shared.b16 {%0,%1,%2,%3}, [%4];"
        : "=r"(r[0]), "=r"(r[1]), "=r"(r[2]), "=r"(r[3]) : "r"(addr));
}
__device__ __forceinline__ void mma16816(float* c, const uint32_t* a, const uint32_t* b){
    asm volatile("mma.sync.aligned.m16n8k16.row.col.f32.bf16.bf16.f32 "
        "{%0,%1,%2,%3}, {%4,%5,%6,%7}, {%8,%9}, {%0,%1,%2,%3};"
        : "+f"(c[0]), "+f"(c[1]), "+f"(c[2]), "+f"(c[3])
        : "r"(a[0]), "r"(a[1]), "r"(a[2]), "r"(a[3]), "r"(b[0]), "r"(b[1]));
}
__device__ __forceinline__ void mma_tf32(float* c, const uint32_t* a, const uint32_t* b){
    asm volatile("mma.sync.aligned.m16n8k8.row.col.f32.tf32.tf32.f32 "
        "{%0,%1,%2,%3}, {%4,%5,%6,%7}, {%8,%9}, {%0,%1,%2,%3};"
        : "+f"(c[0]), "+f"(c[1]), "+f"(c[2]), "+f"(c[3])
        : "r"(a[0]), "r"(a[1]), "r"(a[2]), "r"(a[3]), "r"(b[0]), "r"(b[1]));
}
__device__ __forceinline__ uint32_t f2tf(float f){
    uint32_t r;
    asm("cvt.rna.tf32.f32 %0, %1;" : "=r"(r) : "f"(f));
    return r;
}
__device__ __forceinline__ void tf_split(float f, uint32_t& hi, uint32_t& lo){
    hi = f2tf(f);
    lo = f2tf(f - __uint_as_float(hi));
}
__device__ __forceinline__ uint32_t pack_hilo(float v){
    __nv_bfloat16 h = __float2bfloat16(v);
    __nv_bfloat16 l = __float2bfloat16(v - __bfloat162float(h));
    return ((uint32_t)__bfloat16_as_ushort(h) << 16) | (uint32_t)__bfloat16_as_ushort(l);
}
__device__ __forceinline__ float unpack_hilo(uint32_t w){
    float h = __bfloat162float(__ushort_as_bfloat16((unsigned short)(w >> 16)));
    float l = __bfloat162float(__ushort_as_bfloat16((unsigned short)(w & 0xFFFFu)));
    return h + l;
}

// ======================= weight prep =======================
__global__ void prep_w(const float* __restrict__ srcp, __nv_bfloat16* __restrict__ dstp,
                       int Ncols, int nSeg, long sstr, long dstr){
    long total = (long)nSeg * Ncols * 256;
    long plane = (long)Ncols * 256;
    for (long i = (long)blockIdx.x*blockDim.x + threadIdx.x; i < total; i += (long)gridDim.x*blockDim.x){
        int k = (int)(i & 255);
        long t = i >> 8;
        int n = (int)(t % Ncols);
        int e = (int)(t / Ncols);
        float v = srcp[e*sstr + (long)k*Ncols + n];
        __nv_bfloat16 h = __float2bfloat16(v);
        float rem = v - __bfloat162float(h);
        dstp[e*dstr + (long)n*256 + k] = h;
        dstp[e*dstr + plane + (long)n*256 + k] = __float2bfloat16(rem);
    }
}

// L0 concat: fp32 [4][256][256] -> bf16 hi [1024][256] + lo plane at +262144
__global__ void prep_wc(const float* __restrict__ src, __nv_bfloat16* __restrict__ dst){
    int i = blockIdx.x*256 + threadIdx.x;       // 0..262143
    int k = i & 255;
    int t = i >> 8;
    int n = t & 255;
    int e = t >> 8;
    float v = src[e*65536 + k*256 + n];
    __nv_bfloat16 h = __float2bfloat16(v);
    long d = ((long)(e*256 + n))*256 + k;
    dst[d] = h;
    dst[262144 + d] = __float2bfloat16(v - __bfloat162float(h));
}

// fp32 [256,256] row-major -> transposed [N][K]
__global__ void prep_wt(const float* __restrict__ src, float* __restrict__ dst){
    int i = blockIdx.x*256 + threadIdx.x;
    int k = i >> 8, n = i & 255;
    dst[(long)n*256 + k] = src[(long)k*256 + n];
}

// ======================= 3-term tf32 GEMM (fp32-exact class) =======================
#define FBM 128
#define FAS 20
__global__ void __launch_bounds__(256) tf32gemm(
    const float* __restrict__ A, const float* __restrict__ Bt,
    const float* __restrict__ bias, float* __restrict__ C,
    uint32_t* __restrict__ Cp, int M)
{
    __shared__ float As[2][128*FAS];
    __shared__ float Bs[2][64*FAS];
    const int tid = threadIdx.x;
    const int wid = tid >> 5, lane = tid & 31;
    const int wr = wid >> 1, wc = wid & 1;
    const int bm = blockIdx.x * FBM, bn = blockIdx.y * 64;
    const int fr = lane >> 2, fc = lane & 3;

    float acc[2][4][4];
#pragma unroll
    for (int i = 0; i < 2; ++i)
#pragma unroll
        for (int j = 0; j < 4; ++j)
#pragma unroll
            for (int q = 0; q < 4; ++q) acc[i][j][q] = 0.f;

    float ar[8];
    float4 br;
    const int arow = tid >> 1, ac8 = (tid & 1) * 8;
    const int bnr = tid >> 2, bk4 = (tid & 3) * 4;

    auto ldg = [&](int ch){
        int k0 = ch * 16;
        int gr = bm + arow;
        if (gr < M){
            const float* ap = A + (long)gr*256 + k0 + ac8;
            float4 f0 = *(const float4*)ap;
            float4 f1 = *(const float4*)(ap + 4);
            ar[0]=f0.x; ar[1]=f0.y; ar[2]=f0.z; ar[3]=f0.w;
            ar[4]=f1.x; ar[5]=f1.y; ar[6]=f1.z; ar[7]=f1.w;
        } else {
#pragma unroll
            for (int q = 0; q < 8; ++q) ar[q] = 0.f;
        }
        br = *(const float4*)(Bt + (long)(bn + bnr)*256 + k0 + bk4);
    };
    auto sts = [&](int buf){
        float* pa = &As[buf][arow*FAS + ac8];
#pragma unroll
        for (int q = 0; q < 8; ++q) pa[q] = ar[q];
        float* pb = &Bs[buf][bnr*FAS + bk4];
        pb[0]=br.x; pb[1]=br.y; pb[2]=br.z; pb[3]=br.w;
    };
    auto compute = [&](int buf){
#pragma unroll
        for (int ks = 0; ks < 2; ++ks){
            int kk = ks * 8;
            uint32_t ah[2][4], al[2][4];
#pragma unroll
            for (int mt = 0; mt < 2; ++mt){
                int r0 = wr*32 + mt*16 + fr;
                float f0 = As[buf][r0*FAS + kk + fc];
                float f1 = As[buf][(r0+8)*FAS + kk + fc];
                float f2 = As[buf][r0*FAS + kk + fc + 4];
                float f3 = As[buf][(r0+8)*FAS + kk + fc + 4];
                tf_split(f0, ah[mt][0], al[mt][0]);
                tf_split(f1, ah[mt][1], al[mt][1]);
                tf_split(f2, ah[mt][2], al[mt][2]);
                tf_split(f3, ah[mt][3], al[mt][3]);
            }
#pragma unroll
            for (int nt = 0; nt < 4; ++nt){
                int n0 = wc*32 + nt*8 + fr;
                float g0 = Bs[buf][n0*FAS + kk + fc];
                float g1 = Bs[buf][n0*FAS + kk + fc + 4];
                uint32_t bh[2], bl[2];
                tf_split(g0, bh[0], bl[0]);
                tf_split(g1, bh[1], bl[1]);
#pragma unroll
                for (int mt = 0; mt < 2; ++mt){
                    mma_tf32(acc[mt][nt], ah[mt], bh);
                    mma_tf32(acc[mt][nt], al[mt], bh);
                    mma_tf32(acc[mt][nt], ah[mt], bl);
                }
            }
        }
    };

    ldg(0); sts(0); __syncthreads();
    for (int c = 0; c < 16; ++c){
        if (c + 1 < 16) ldg(c + 1);
        compute(c & 1);
        if (c + 1 < 16){ sts((c + 1) & 1); __syncthreads(); }
    }

#pragma unroll
    for (int mt = 0; mt < 2; ++mt){
#pragma unroll
        for (int nt = 0; nt < 4; ++nt){
            int row0 = bm + wr*32 + mt*16 + fr;
            int col  = bn + wc*32 + nt*8 + fc*2;
            float b0 = bias[col];
            float b1 = bias[col + 1];
#pragma unroll
            for (int half = 0; half < 2; ++half){
                int row = row0 + half*8;
                if (row < M){
                    float2 o;
                    o.x = acc[mt][nt][half*2 + 0] + b0;
                    o.y = acc[mt][nt][half*2 + 1] + b1;
                    *(float2*)(C + (long)row*256 + col) = o;
                    if (Cp){
                        uint2 po;
                        po.x = pack_hilo(o.x);
                        po.y = pack_hilo(o.y);
                        *(uint2*)(Cp + (long)row*256 + col) = po;
                    }
                }
            }
        }
    }
}

// ======================= mma.sync split-bf16 dual GEMM, 128x128 tile =======================
#define TBM 128
#define TBN 128
#define TBK 32
#define ARS 80
#define AS_PLANE 10240
#define AS_STAGE 20480
#define BS_PLANE 10240
#define BS_STAGE 20480
#define BS_OFF   40960
#define SMEM_DYN 81920

__global__ void __launch_bounds__(256) tgemm(
    const uint32_t* __restrict__ A0, int lda0,
    const uint32_t* __restrict__ A1, int lda1,
    const __nv_bfloat16* __restrict__ B0, const __nv_bfloat16* __restrict__ B1,
    const float* __restrict__ bias, float* __restrict__ C,
    int Nc, int M, int relu, int out_packed, int accum,
    const float* __restrict__ rowscale, int rs_stride,
    const uint32_t* __restrict__ addin)
{
    extern __shared__ char dsm[];
    const uint32_t sbase = smem_u32(dsm);

    const int tid  = threadIdx.x;
    const int wid  = tid >> 5;
    const int lane = tid & 31;
    const int wr   = wid >> 1;           // 0..3: 32-row slice
    const int wc   = wid & 1;            // 0..1: 64-col slice
    const int bm   = blockIdx.x * TBM;
    const int bn   = blockIdx.y * TBN;

    const int nch = (A1 != 0) ? 16 : 8;
    const long bplane = (long)Nc * 256;

    float acc[2][8][4];
#pragma unroll
    for (int i = 0; i < 2; ++i)
#pragma unroll
        for (int j = 0; j < 8; ++j)
#pragma unroll
            for (int q = 0; q < 4; ++q) acc[i][j][q] = 0.f;

    uint32_t aw[16];
    uint4 bh0, bh1, bl0, bl1;
    const int arow_g = tid >> 1;             // 0..127
    const int acol_g = (tid & 1) * 16;       // packed words
    const int brow_g = tid >> 1;             // 0..127
    const int bcol_g = (tid & 1) * 16;       // bf16 elements

    auto ldg_chunk = [&](int c){
        int seg = c >> 3;
        int k0  = (c & 7) * TBK;
        const uint32_t* A = seg ? A1 : A0;
        const int lda = seg ? lda1 : lda0;
        int gr = bm + arow_g;
        if (gr < M){
            const uint32_t* ap = A + (long)gr*lda + k0 + acol_g;
            uint4 u0 = *(const uint4*)ap;
            uint4 u1 = *(const uint4*)(ap + 4);
            uint4 u2 = *(const uint4*)(ap + 8);
            uint4 u3 = *(const uint4*)(ap + 12);
            aw[0]=u0.x; aw[1]=u0.y; aw[2]=u0.z; aw[3]=u0.w;
            aw[4]=u1.x; aw[5]=u1.y; aw[6]=u1.z; aw[7]=u1.w;
            aw[8]=u2.x; aw[9]=u2.y; aw[10]=u2.z; aw[11]=u2.w;
            aw[12]=u3.x; aw[13]=u3.y; aw[14]=u3.z; aw[15]=u3.w;
        } else {
#pragma unroll
            for (int q = 0; q < 16; ++q) aw[q] = 0u;
        }
        const __nv_bfloat16* B = seg ? B1 : B0;
        const __nv_bfloat16* bp = B + (long)(bn + brow_g)*256 + k0 + bcol_g;
        bh0 = *(const uint4*)bp;
        bh1 = *(const uint4*)(bp + 8);
        bl0 = *(const uint4*)(bp + bplane);
        bl1 = *(const uint4*)(bp + bplane + 8);
    };

    auto sts_chunk = [&](int buf){
        uint32_t hh[8], ll[8];
#pragma unroll
        for (int q = 0; q < 8; ++q){
            hh[q] = __byte_perm(aw[2*q], aw[2*q+1], 0x7632);
            ll[q] = __byte_perm(aw[2*q], aw[2*q+1], 0x5410);
        }
        char* pa = dsm + buf*AS_STAGE + arow_g*ARS + acol_g*2;
        *(uint4*)pa        = make_uint4(hh[0], hh[1], hh[2], hh[3]);
        *(uint4*)(pa + 16) = make_uint4(hh[4], hh[5], hh[6], hh[7]);
        *(uint4*)(pa + AS_PLANE)      = make_uint4(ll[0], ll[1], ll[2], ll[3]);
        *(uint4*)(pa + AS_PLANE + 16) = make_uint4(ll[4], ll[5], ll[6], ll[7]);
        char* pb = dsm + BS_OFF + buf*BS_STAGE + brow_g*ARS + bcol_g*2;
        *(uint4*)pb                   = bh0;
        *(uint4*)(pb + 16)            = bh1;
        *(uint4*)(pb + BS_PLANE)      = bl0;
        *(uint4*)(pb + BS_PLANE + 16) = bl1;
    };

    const int tile = lane >> 3;
    const int trr  = lane & 7;
    const int arow = wr*32 + ((tile & 1) << 3) + trr;   // + mt*16
    const int akk0 = ((tile & 2) << 2);
    const int brow = wc*64 + ((tile & 2) << 2) + trr;   // + 16*i
    const int bkk0 = ((tile & 1) << 3);

    auto compute = [&](int buf){
        uint32_t aBase = sbase + (uint32_t)buf*AS_STAGE;
        uint32_t bBase = sbase + BS_OFF + (uint32_t)buf*BS_STAGE;
#pragma unroll
        for (int kt = 0; kt < 2; ++kt){
            uint32_t a_hi[2][4], a_lo[2][4], bb[4][4];
            uint32_t ak = (uint32_t)(akk0 + kt*16)*2;
            uint32_t bk = (uint32_t)(bkk0 + kt*16)*2;
            ldm4(a_hi[0], aBase + (uint32_t)(arow)*ARS + ak);
            ldm4(a_hi[1], aBase + (uint32_t)(arow+16)*ARS + ak);
#pragma unroll
            for (int i = 0; i < 4; ++i)
                ldm4(bb[i], bBase + (uint32_t)(brow + 16*i)*ARS + bk);
#pragma unroll
            for (int mt = 0; mt < 2; ++mt)
#pragma unroll
                for (int nt = 0; nt < 8; ++nt)
                    mma16816(acc[mt][nt], a_hi[mt], &bb[nt>>1][(nt&1)*2]);
            ldm4(a_lo[0], aBase + AS_PLANE + (uint32_t)(arow)*ARS + ak);
            ldm4(a_lo[1], aBase + AS_PLANE + (uint32_t)(arow+16)*ARS + ak);
#pragma unroll
            for (int mt = 0; mt < 2; ++mt)
#pragma unroll
                for (int nt = 0; nt < 8; ++nt)
                    mma16816(acc[mt][nt], a_lo[mt], &bb[nt>>1][(nt&1)*2]);
#pragma unroll
            for (int i = 0; i < 4; ++i)
                ldm4(bb[i], bBase + BS_PLANE + (uint32_t)(brow + 16*i)*ARS + bk);
#pragma unroll
            for (int mt = 0; mt < 2; ++mt)
#pragma unroll
                for (int nt = 0; nt < 8; ++nt)
                    mma16816(acc[mt][nt], a_hi[mt], &bb[nt>>1][(nt&1)*2]);
        }
    };

    ldg_chunk(0);
    sts_chunk(0);
    __syncthreads();
    for (int c = 0; c < nch; ++c){
        if (c + 1 < nch) ldg_chunk(c + 1);
        compute(c & 1);
        if (c + 1 < nch){
            sts_chunk((c + 1) & 1);
            __syncthreads();
        }
    }

#pragma unroll
    for (int mt = 0; mt < 2; ++mt){
#pragma unroll
        for (int nt = 0; nt < 8; ++nt){
            int row0 = bm + wr*32 + mt*16 + (lane >> 2);
            int col  = bn + wc*64 + nt*8 + (lane & 3)*2;
            float b0 = bias[col];
            float b1 = bias[col + 1];
#pragma unroll
            for (int half = 0; half < 2; ++half){
                int row = row0 + half*8;
                if (row < M){
                    float v0 = acc[mt][nt][half*2 + 0] + b0;
                    float v1 = acc[mt][nt][half*2 + 1] + b1;
                    if (relu){ v0 = fmaxf(v0, 0.f); v1 = fmaxf(v1, 0.f); }
                    if (out_packed){
                        uint2 o;
                        o.x = pack_hilo(v0);
                        o.y = pack_hilo(v1);
                        *(uint2*)((uint32_t*)C + (long)row*Nc + col) = o;
                    } else {
                        if (addin){
                            uint2 ai = *(const uint2*)(addin + (long)row*Nc + col);
                            v0 += unpack_hilo(ai.x);
                            v1 += unpack_hilo(ai.y);
                        }
                        if (rowscale){
                            float rs = rowscale[(long)row*rs_stride];
                            v0 *= rs; v1 *= rs;
                        }
                        float* cp = C + (long)row*Nc + col;
                        if (accum){ v0 += cp[0]; v1 += cp[1]; }
                        float2 o; o.x = v0; o.y = v1;
                        *(float2*)cp = o;
                    }
                }
            }
        }
    }
}

// ---------------- histograms ----------------
__global__ void hist_nodes(const int* __restrict__ batch){
    __shared__ int s[GG];
    if(threadIdx.x < GG) s[threadIdx.x] = 0;
    __syncthreads();
    for(int i = blockIdx.x*blockDim.x + threadIdx.x; i < NN; i += gridDim.x*blockDim.x)
        atomicAdd(&s[batch[i]], 1);
    __syncthreads();
    if(threadIdx.x < GG && s[threadIdx.x]) atomicAdd(&g_ncnt[threadIdx.x], s[threadIdx.x]);
}

__global__ void edge_prep(const int* __restrict__ src, const int* __restrict__ dst,
                          const int* __restrict__ batch){
    __shared__ int s[GG];
    if(threadIdx.x < GG) s[threadIdx.x] = 0;
    __syncthreads();
    for(int i = blockIdx.x*blockDim.x + threadIdx.x; i < EE; i += gridDim.x*blockDim.x){
        atomicAdd(&s[batch[src[i]]], 1);
        atomicAdd(&g_deg[dst[i]], 1);
    }
    __syncthreads();
    if(threadIdx.x < GG && s[threadIdx.x]) atomicAdd(&g_ecnt[threadIdx.x], s[threadIdx.x]);
}

// ---------------- graph stats ----------------
__global__ void stats_kernel(){
    int g = threadIdx.x;
    float n   = fmaxf((float)g_ncnt[g], 1.f);
    float e   = (float)g_ecnt[g];
    float den = e / fmaxf(n*(n-1.f), 1.f);
    float ln  = logf(n);
    __shared__ float sn[GG], se[GG], sd[GG], sl[GG];
    sn[g]=n; se[g]=e; sd[g]=den; sl[g]=ln;
    __syncthreads();
    __shared__ float sc[8];
    if(g == 0){
        float mn=sl[0], mx=sl[0], s0=0, s1=0, s2=0;
        for(int i=0;i<GG;i++){ mn=fminf(mn,sl[i]); mx=fmaxf(mx,sl[i]); s0+=sn[i]; s1+=se[i]; s2+=sd[i]; }
        float m0=s0/GG, m1=s1/GG, m2=s2/GG;
        float q0=0,q1=0,q2=0;
        for(int i=0;i<GG;i++){
            float d0=sn[i]-m0, d1=se[i]-m1, d2=sd[i]-m2;
            q0+=d0*d0; q1+=d1*d1; q2+=d2*d2;
        }
        sc[0]=mn; sc[1]=mx; sc[2]=m0; sc[3]=m1; sc[4]=m2;
        sc[5]=sqrtf(q0/GG); sc[6]=sqrtf(q1/GG); sc[7]=sqrtf(q2/GG);
    }
    __syncthreads();
    g_lognn[g]       = (ln  - sc[0])/(sc[1]-sc[0]+1e-6f);
    g_featsn[g*3+0]  = (n   - sc[2])/(sc[5]+1e-6f);
    g_featsn[g*3+1]  = (e   - sc[3])/(sc[6]+1e-6f);
    g_featsn[g*3+2]  = (den - sc[4])/(sc[7]+1e-6f);
}

__global__ void sf_kernel(const int* __restrict__ batch){
    int i = blockIdx.x*blockDim.x + threadIdx.x;
    if(i < NN){
        int g = batch[i];
        g_sf[i*3+0] = g_featsn[g*3+0];
        g_sf[i*3+1] = g_featsn[g*3+1];
        g_sf[i*3+2] = g_featsn[g*3+2];
    }
}

// ---------------- CSR build ----------------
__global__ void scan1(){
    __shared__ int sh[1024];
    int i = blockIdx.x*1024 + threadIdx.x;
    int v = (i < NN) ? g_deg[i] : 0;
    sh[threadIdx.x] = v;
    __syncthreads();
    for(int off=1; off<1024; off<<=1){
        int t = sh[threadIdx.x];
        if(threadIdx.x >= off) t += sh[threadIdx.x - off];
        __syncthreads();
        sh[threadIdx.x] = t;
        __syncthreads();
    }
    if(i < NN) g_rowptr[i] = sh[threadIdx.x] - v;
    if(threadIdx.x == 1023) g_bsum[blockIdx.x] = sh[1023];
}

__global__ void scan2(int nb){
    if(threadIdx.x == 0){
        int run = 0;
        for(int b=0;b<nb;b++){ int v=g_bsum[b]; g_bsum[b]=run; run+=v; }
    }
}

__global__ void scan3(){
    int i = blockIdx.x*blockDim.x + threadIdx.x;
    if(i < NN) g_rowptr[i] += g_bsum[i >> 10];
    if(i == 0) g_rowptr[NN] = EE;
}

__global__ void place_edges(const int* __restrict__ src, const int* __restrict__ dst){
    for(int i = blockIdx.x*blockDim.x + threadIdx.x; i < EE; i += gridDim.x*blockDim.x){
        int d = dst[i];
        int idx = g_rowptr[d] + atomicAdd(&g_cur[d], 1);
        g_esrc[idx] = src[i];
    }
}

// ---------------- CSR gather aggregation (packed, grouped) ----------------
__global__ void aggregate_pg(const uint32_t* __restrict__ in, uint32_t* __restrict__ out,
                             int Win, long in_goff, int Wout, long out_goff){
    int n = blockIdx.x;
    const uint32_t* ip = in + (long)blockIdx.y * in_goff;
    uint32_t* op = out + (long)blockIdx.y * out_goff;
    int s0 = g_rowptr[n], s1 = g_rowptr[n+1];
    float a0=0.f, a1=0.f, a2=0.f, a3=0.f, a4=0.f, a5=0.f, a6=0.f, a7=0.f;
    int j = s0;
    for(; j + 8 <= s1; j += 8){
        int i0 = g_esrc[j],   i1 = g_esrc[j+1], i2 = g_esrc[j+2], i3 = g_esrc[j+3];
        int i4 = g_esrc[j+4], i5 = g_esrc[j+5], i6 = g_esrc[j+6], i7 = g_esrc[j+7];
        a0 += unpack_hilo(ip[(long)i0*Win + threadIdx.x]);
        a1 += unpack_hilo(ip[(long)i1*Win + threadIdx.x]);
        a2 += unpack_hilo(ip[(long)i2*Win + threadIdx.x]);
        a3 += unpack_hilo(ip[(long)i3*Win + threadIdx.x]);
        a4 += unpack_hilo(ip[(long)i4*Win + threadIdx.x]);
        a5 += unpack_hilo(ip[(long)i5*Win + threadIdx.x]);
        a6 += unpack_hilo(ip[(long)i6*Win + threadIdx.x]);
        a7 += unpack_hilo(ip[(long)i7*Win + threadIdx.x]);
    }
    for(; j < s1; ++j)
        a0 += unpack_hilo(ip[(long)g_esrc[j]*Win + threadIdx.x]);
    op[(long)n*Wout + threadIdx.x] = pack_hilo(((a0 + a1) + (a2 + a3)) + ((a4 + a5) + (a6 + a7)));
}

// ---------------- fp32 SIMT dual GEMM (small-K exact paths) ----------------
#define BM 64
#define BN 64
#define BK 16
__global__ void gemm_dual(const float* __restrict__ A0, int lda0, int K0,
                          const float* __restrict__ B0, int ldb0,
                          const float* __restrict__ A1, int lda1, int K1,
                          const float* __restrict__ B1, int ldb1,
                          const float* __restrict__ bias,
                          float* __restrict__ C, int ldc, int M, int Nc,
                          int relu, int accum,
                          const float* __restrict__ rowscale, int rs_stride)
{
    __shared__ float As[BK][BM];
    __shared__ float Bs[BK][BN];
    const int bm = blockIdx.x*BM, bn = blockIdx.y*BN;
    const int tid = threadIdx.x;
    const int tr = tid >> 4, tc = tid & 15;
    float acc[4][4];
#pragma unroll
    for(int i=0;i<4;i++)
#pragma unroll
        for(int j=0;j<4;j++) acc[i][j]=0.f;

    for(int phase=0; phase<2; ++phase){
        const float* A = phase ? A1 : A0;
        const float* B = phase ? B1 : B0;
        const int K   = phase ? K1  : K0;
        const int lda = phase ? lda1: lda0;
        const int ldb = phase ? ldb1: ldb0;
        if(K <= 0 || A == 0) continue;
        for(int k0=0; k0<K; k0+=BK){
#pragma unroll
            for(int l=0;l<4;l++){
                int id = tid + l*256;
                int m = id >> 4, k = id & 15;
                float va = 0.f;
                int gk = k0 + k, gm = bm + m;
                if(gm < M && gk < K) va = A[(long)gm*lda + gk];
                As[k][m] = va;
                int kb = id >> 6, jb = id & 63;
                float vb = 0.f;
                int gkb = k0 + kb, gj = bn + jb;
                if(gkb < K && gj < Nc) vb = B[(long)gkb*ldb + gj];
                Bs[kb][jb] = vb;
            }
            __syncthreads();
#pragma unroll
            for(int kk=0; kk<BK; ++kk){
                float4 a4 = *(const float4*)&As[kk][tr*4];
                float4 b4 = *(const float4*)&Bs[kk][tc*4];
                float av[4] = {a4.x, a4.y, a4.z, a4.w};
                float bv[4] = {b4.x, b4.y, b4.z, b4.w};
#pragma unroll
                for(int i=0;i<4;i++)
#pragma unroll
                    for(int j=0;j<4;j++) acc[i][j] += av[i]*bv[j];
            }
            __syncthreads();
        }
    }
#pragma unroll
    for(int i=0;i<4;i++){
        int row = bm + tr*4 + i;
        if(row >= M) continue;
        float rs = rowscale ? rowscale[(long)row*rs_stride] : 1.f;
#pragma unroll
        for(int j=0;j<4;j++){
            int col = bn + tc*4 + j;
            if(col >= Nc) continue;
            float v = acc[i][j] + (bias ? bias[col] : 0.f);
            if(relu) v = fmaxf(v, 0.f);
            v *= rs;
            if(accum) C[(long)row*ldc + col] += v;
            else      C[(long)row*ldc + col]  = v;
        }
    }
}

// ---------------- router (with fused K=3 sf correction) ----------------
__global__ void router_kernel(const float* __restrict__ t, const int* __restrict__ batch,
                              const float* __restrict__ lng, const float* __restrict__ lnb,
                              const float* __restrict__ W2, const float* __restrict__ b2,
                              const float* __restrict__ centers,
                              const float* __restrict__ sf, const float* __restrict__ W1s)
{
    int n = blockIdx.x; int tid = threadIdx.x;
    int lane = tid & 31, wid = tid >> 5;
    float s0f = sf[n*3+0], s1f = sf[n*3+1], s2f = sf[n*3+2];
    float v = t[(long)n*HH + tid]
            + s0f * W1s[tid] + s1f * W1s[HH + tid] + s2f * W1s[2*HH + tid];
    float s = v, sq = v*v;
#pragma unroll
    for(int o=16;o>0;o>>=1){
        s  += __shfl_down_sync(0xffffffffu, s,  o);
        sq += __shfl_down_sync(0xffffffffu, sq, o);
    }
    __shared__ float red[8*2];
    __shared__ float red4[8*4];
    __shared__ float bc[2];
    if(lane == 0){ red[wid*2]=s; red[wid*2+1]=sq; }
    __syncthreads();
    if(tid == 0){
        float S=0, Q=0;
        for(int w=0;w<8;w++){ S+=red[w*2]; Q+=red[w*2+1]; }
        float mean = S/HH;
        bc[0]=mean; bc[1]=Q/HH - mean*mean;
    }
    __syncthreads();
    float mean = bc[0], var = bc[1];
    float r = (v - mean)*rsqrtf(var + 1e-5f)*lng[tid] + lnb[tid];
    r = fmaxf(r, 0.f);
    float p[4];
#pragma unroll
    for(int e=0;e<4;e++) p[e] = r * W2[tid*4+e];
#pragma unroll
    for(int o=16;o>0;o>>=1)
#pragma unroll
        for(int e=0;e<4;e++) p[e] += __shfl_down_sync(0xffffffffu, p[e], o);
    if(lane == 0)
        for(int e=0;e<4;e++) red4[wid*4+e] = p[e];
    __syncthreads();
    if(tid == 0){
        float logit[4], probs[4];
        float lnode = g_lognn[batch[n]];
        for(int e=0;e<4;e++){
            float sum = 0;
            for(int w=0;w<8;w++) sum += red4[w*4+e];
            float learned = sum + b2[e];
            float d = lnode - centers[e];
            logit[e] = 0.7f*learned - 0.3f*d*d;
        }
        float mx = logit[0];
        for(int e=1;e<4;e++) mx = fmaxf(mx, logit[e]);
        float ssum = 0;
        for(int e=0;e<4;e++){ probs[e] = expf(logit[e]-mx); ssum += probs[e]; }
        for(int e=0;e<4;e++) probs[e] /= ssum;
        int i0 = 0;
        for(int e=1;e<4;e++) if(probs[e] > probs[i0]) i0 = e;
        int i1 = -1;
        for(int e=0;e<4;e++){
            if(e == i0) continue;
            if(i1 < 0 || probs[e] > probs[i1]) i1 = e;
        }
        float denom = probs[i0] + probs[i1] + 1e-8f;
        float wv[4] = {0.f,0.f,0.f,0.f};
        wv[i0] = probs[i0]/denom;
        wv[i1] = probs[i1]/denom;
        for(int e=0;e<4;e++) g_w[(long)n*4+e] = wv[e];
    }
}

// ---------------- host ----------------
extern "C" void kernel_launch(void* const* d_in, const int* in_sizes, int n_in,
                              void* d_out, int out_size)
{
    const float* x       = (const float*)d_in[0];
    const int*   ei      = (const int*)  d_in[1];
    const int*   batch   = (const int*)  d_in[2];
    const float* enc_W1  = (const float*)d_in[3];
    const float* enc_b1  = (const float*)d_in[4];
    const float* enc_W2  = (const float*)d_in[5];
    const float* enc_b2  = (const float*)d_in[6];
    const float* r_W1    = (const float*)d_in[7];
    const float* r_b1    = (const float*)d_in[8];
    const float* ln_g    = (const float*)d_in[9];
    const float* ln_b    = (const float*)d_in[10];
    const float* r_W2    = (const float*)d_in[11];
    const float* r_b2    = (const float*)d_in[12];
    const float* centers = (const float*)d_in[13];
    const float* W0_rel  = (const float*)d_in[14];
    const float* b0_rel  = (const float*)d_in[15];
    const float* W0_root = (const float*)d_in[16];
    const float* W1_rel  = (const float*)d_in[17];
    const float* b1_rel  = (const float*)d_in[18];
    const float* W1_root = (const float*)d_in[19];
    const float* W2_rel  = (const float*)d_in[20];
    const float* b2_rel  = (const float*)d_in[21];
    const float* W2_root = (const float*)d_in[22];
    const int* src = ei;
    const int* dst = ei + EE;
    float* out = (float*)d_out;

    float *p_h1,*p_h,*p_sf,*p_w,*p_wt,*p_zero;
    uint32_t *p_hp,*p_agg,*p_hE0,*p_hE1,*p_aggE;
    int *p_ncnt,*p_ecnt,*p_deg,*p_cur;
    __nv_bfloat16* p_wb;
    cudaGetSymbolAddress((void**)&p_h1,  g_h1);
    cudaGetSymbolAddress((void**)&p_h,   g_h);
    cudaGetSymbolAddress((void**)&p_hp,  g_hp);
    cudaGetSymbolAddress((void**)&p_agg, g_agg);
    cudaGetSymbolAddress((void**)&p_sf,  g_sf);
    cudaGetSymbolAddress((void**)&p_w,   g_w);
    cudaGetSymbolAddress((void**)&p_hE0, g_hE0);
    cudaGetSymbolAddress((void**)&p_hE1, g_hE1);
    cudaGetSymbolAddress((void**)&p_aggE,g_aggE);
    cudaGetSymbolAddress((void**)&p_ncnt,g_ncnt);
    cudaGetSymbolAddress((void**)&p_ecnt,g_ecnt);
    cudaGetSymbolAddress((void**)&p_deg, g_deg);
    cudaGetSymbolAddress((void**)&p_cur, g_cur);
    cudaGetSymbolAddress((void**)&p_wb,  g_wbuf);
    cudaGetSymbolAddress((void**)&p_wt,  g_wt);
    cudaGetSymbolAddress((void**)&p_zero,g_zero);

    cudaFuncSetAttribute(tgemm, cudaFuncAttributeMaxDynamicSharedMemorySize, SMEM_DYN);

    // ---- weight prep ----
    prep_wt<<<256,256>>>(enc_W2, p_wt);
    prep_wt<<<256,256>>>(r_W1,   p_wt + 65536);
    prep_wc<<<1024,256>>>(W0_rel,  p_wb + OFF_L0C);
    prep_wc<<<1024,256>>>(W0_root, p_wb + OFF_L0CR);
    prep_w<<<256,256>>>(W1_rel,  p_wb + OFF_L1,          256, 4, 65536, 262144);
    prep_w<<<256,256>>>(W1_root, p_wb + OFF_L1 + 131072, 256, 4, 65536, 262144);
    prep_w<<<128,256>>>(W2_rel,  p_wb + OFF_L2,          128, 4, 32768, 131072);
    prep_w<<<128,256>>>(W2_root, p_wb + OFF_L2 + 65536,  128, 4, 32768, 131072);

    // ---- stats + CSR prep ----
    cudaMemsetAsync(p_ncnt, 0, GG*sizeof(int));
    cudaMemsetAsync(p_ecnt, 0, GG*sizeof(int));
    cudaMemsetAsync(p_deg,  0, NN*sizeof(int));
    cudaMemsetAsync(p_cur,  0, NN*sizeof(int));
    hist_nodes<<<196, 256>>>(batch);
    edge_prep<<<784, 256>>>(src, dst, batch);
    stats_kernel<<<1, GG>>>();
    sf_kernel<<<(NN+255)/256, 256>>>(batch);
    int nscan = (NN+1023)/1024;
    scan1<<<nscan, 1024>>>();
    scan2<<<1, 32>>>(nscan);
    scan3<<<(NN+255)/256, 256>>>();
    place_edges<<<784, 256>>>(src, dst);

    const int TGRIDX = (NN + TBM - 1) / TBM;
    const dim3 fgrid((NN + FBM - 1) / FBM, 4);

    // ---- encoder (exact-class: K=6 SIMT, then 3xTF32 tensor with fused pack) ----
    {
        dim3 grid((NN+BM-1)/BM, (HH+BN-1)/BN);
        gemm_dual<<<grid, 256>>>(x+4, 16, 6, enc_W1, HH,
                                 (const float*)0,0,0,(const float*)0,0,
                                 enc_b1, p_h1, HH, NN, HH, 1, 0, (const float*)0, 0);
    }
    tf32gemm<<<fgrid, 256>>>(p_h1, p_wt, enc_b2, p_h, p_hp, NN);

    // ---- router (3xTF32 main; K=3 sf correction fused into router kernel) ----
    tf32gemm<<<fgrid, 256>>>(p_h, p_wt + 65536, r_b1, p_h1, (uint32_t*)0, NN);
    router_kernel<<<NN, 256>>>(p_h1, batch, ln_g, ln_b, r_W2, r_b2, centers,
                               p_sf, r_W1 + HH*HH);

    // ---- aggregate h (packed) ----
    aggregate_pg<<<dim3(NN,1), 256>>>(p_hp, p_agg, 256, 0, 256, 0);

    // ---- expert layer 0: single batched GEMM, Nc=1024, output hE0 as [n][1024] ----
    {
        dim3 grid(TGRIDX, 1024 / TBN);
        tgemm<<<grid, 256, SMEM_DYN>>>(p_agg, 256, p_hp, 256,
                                       p_wb + OFF_L0C, p_wb + OFF_L0CR,
                                       b0_rel, (float*)p_hE0, 1024, NN, 1, 1, 0,
                                       (const float*)0, 0, (const uint32_t*)0);
    }
    // aggregate hE0 per expert: in [n][1024] col-block e*256, out aggE[e][n][256]
    aggregate_pg<<<dim3(NN,4), 256>>>(p_hE0, p_aggE, 1024, 256, 256, (long)NN*256);

    // ---- expert layer 1 (A1 = hE0 column block, lda 1024) ----
    for(int e=0;e<NEXP;e++){
        dim3 grid(TGRIDX, 256 / TBN);
        tgemm<<<grid, 256, SMEM_DYN>>>(p_aggE + (long)e*NN*HH, 256,
                                       p_hE0 + e*256, 1024,
                                       p_wb + OFF_L1 + (long)e*262144,
                                       p_wb + OFF_L1 + (long)e*262144 + 131072,
                                       b1_rel + e*HH, (float*)(p_hE1 + (long)e*NN*HH),
                                       HH, NN, 1, 1, 0,
                                       (const float*)0, 0, (const uint32_t*)0);
    }

    // ---- expert layer 2, reassociated: t_e = hE1@W2_rel (128-wide) -> aggregate ->
    //      out (+)= w_e * (agg_te + hE1@W2_root + b2) ----
    for(int e=0;e<NEXP;e++){
        dim3 grid(TGRIDX, OD / TBN);
        tgemm<<<grid, 256, SMEM_DYN>>>(p_hE1 + (long)e*NN*HH, 256,
                                       (const uint32_t*)0, 0,
                                       p_wb + OFF_L2 + (long)e*131072, (const __nv_bfloat16*)0,
                                       p_zero, (float*)(p_aggE + (long)e*NN*HH),
                                       OD, NN, 0, 1, 0,
                                       (const float*)0, 0, (const uint32_t*)0);
    }
    aggregate_pg<<<dim3(NN,4), OD>>>(p_aggE, p_aggE + (long)NN*OD,
                                     128, (long)NN*HH, 128, (long)NN*HH);
    for(int e=0;e<NEXP;e++){
        dim3 grid(TGRIDX, OD / TBN);
        tgemm<<<grid, 256, SMEM_DYN>>>(p_hE1 + (long)e*NN*HH, 256,
                                       (const uint32_t*)0, 0,
                                       p_wb + OFF_L2 + (long)e*131072 + 65536, (const __nv_bfloat16*)0,
                                       b2_rel + e*OD, out, OD, NN, 0, 0, (e > 0),
                                       p_w + e, NEXP,
                                       p_aggE + (long)e*NN*HH + (long)NN*OD);
    }
}

// round 13
// speedup vs baseline: 1.0288x; 1.0288x over previous
#include <cuda_runtime.h>
#include <cuda_bf16.h>
#include <stdint.h>
#include <math.h>

#define NN 50000
#define EE 800000
#define HH 256
#define GG 64
#define NEXP 4
#define OD 128

// ---------------- scratch (device globals: no allocation allowed) ----------------
__device__ __align__(16) float g_h1[NN*HH];
__device__ __align__(16) float g_h[NN*HH];
__device__ __align__(16) uint32_t g_hp[NN*HH];        // h packed hi/lo
__device__ __align__(16) uint32_t g_agg[NN*HH];       // aggregate(h) packed
__device__ __align__(16) float g_sf[NN*3];
__device__ __align__(16) float g_w[NN*NEXP];
__device__ __align__(16) uint32_t g_hE0[(long)NEXP*NN*HH];   // packed, used as [NN][1024]
__device__ __align__(16) uint32_t g_hE1[(long)NEXP*NN*HH];   // packed per-expert
__device__ __align__(16) uint32_t g_aggE[(long)NEXP*NN*HH];  // packed (aggE, then t_e/agg_te)
__device__ int   g_deg[NN];
__device__ int   g_rowptr[NN+1];
__device__ int   g_cur[NN];
__device__ int   g_esrc[EE];
__device__ int   g_bsum[64];
__device__ int   g_ncnt[GG];
__device__ int   g_ecnt[GG];
__device__ float g_featsn[GG*3];
__device__ float g_lognn[GG];
__device__ float g_zero[HH];                          // stays zero
#define WBUF_ELEMS 2883584
__device__ __align__(16) __nv_bfloat16 g_wbuf[WBUF_ELEMS];
__device__ __align__(16) float g_wt[2*65536];         // fp32 W^T: enc_W2, r_W1[:256]

// wbuf layout (elements):
#define OFF_L0C   0        // L0 rel concat [1024][256] hi + lo (524288)
#define OFF_L0CR  524288   // L0 root concat (524288)
#define OFF_L1    1048576  // per-expert stride 262144 (rel hi/lo, root hi/lo at +131072)
#define OFF_L2    2097152  // per-expert stride 131072 (rel at +0, root at +65536)

// ======================= helpers =======================
__device__ __forceinline__ uint32_t smem_u32(const void* p){
    uint32_t a;
    asm("{ .reg .u64 t; cvta.to.shared.u64 t, %1; cvt.u32.u64 %0, t; }" : "=r"(a) : "l"(p));
    return a;
}
__device__ __forceinline__ void ldm4(uint32_t* r, uint32_t addr){
    asm volatile("ldmatrix.sync.aligned.m8n8.x4.shared.b16 {%0,%1,%2,%3}, [%4];"
        : "=r"(r[0]), "=r"(r[1]), "=r"(r[2]), "=r"(r[3]) : "r"(addr));
}
__device__ __forceinline__ void mma16816(float* c, const uint32_t* a, const uint32_t* b){
    asm volatile("mma.sync.aligned.m16n8k16.row.col.f32.bf16.bf16.f32 "
        "{%0,%1,%2,%3}, {%4,%5,%6,%7}, {%8,%9}, {%0,%1,%2,%3};"
        : "+f"(c[0]), "+f"(c[1]), "+f"(c[2]), "+f"(c[3])
        : "r"(a[0]), "r"(a[1]), "r"(a[2]), "r"(a[3]), "r"(b[0]), "r"(b[1]));
}
__device__ __forceinline__ void mma_tf32(float* c, const uint32_t* a, const uint32_t* b){
    asm volatile("mma.sync.aligned.m16n8k8.row.col.f32.tf32.tf32.f32 "
        "{%0,%1,%2,%3}, {%4,%5,%6,%7}, {%8,%9}, {%0,%1,%2,%3};"
        : "+f"(c[0]), "+f"(c[1]), "+f"(c[2]), "+f"(c[3])
        : "r"(a[0]), "r"(a[1]), "r"(a[2]), "r"(a[3]), "r"(b[0]), "r"(b[1]));
}
__device__ __forceinline__ uint32_t f2tf(float f){
    uint32_t r;
    asm("cvt.rna.tf32.f32 %0, %1;" : "=r"(r) : "f"(f));
    return r;
}
__device__ __forceinline__ void tf_split(float f, uint32_t& hi, uint32_t& lo){
    hi = f2tf(f);
    lo = f2tf(f - __uint_as_float(hi));
}
__device__ __forceinline__ uint32_t pack_hilo(float v){
    __nv_bfloat16 h = __float2bfloat16(v);
    __nv_bfloat16 l = __float2bfloat16(v - __bfloat162float(h));
    return ((uint32_t)__bfloat16_as_ushort(h) << 16) | (uint32_t)__bfloat16_as_ushort(l);
}
__device__ __forceinline__ float unpack_hilo(uint32_t w){
    float h = __bfloat162float(__ushort_as_bfloat16((unsigned short)(w >> 16)));
    float l = __bfloat162float(__ushort_as_bfloat16((unsigned short)(w & 0xFFFFu)));
    return h + l;
}

// ======================= weight prep =======================
__global__ void prep_w(const float* __restrict__ srcp, __nv_bfloat16* __restrict__ dstp,
                       int Ncols, int nSeg, long sstr, long dstr){
    long total = (long)nSeg * Ncols * 256;
    long plane = (long)Ncols * 256;
    for (long i = (long)blockIdx.x*blockDim.x + threadIdx.x; i < total; i += (long)gridDim.x*blockDim.x){
        int k = (int)(i & 255);
        long t = i >> 8;
        int n = (int)(t % Ncols);
        int e = (int)(t / Ncols);
        float v = srcp[e*sstr + (long)k*Ncols + n];
        __nv_bfloat16 h = __float2bfloat16(v);
        float rem = v - __bfloat162float(h);
        dstp[e*dstr + (long)n*256 + k] = h;
        dstp[e*dstr + plane + (long)n*256 + k] = __float2bfloat16(rem);
    }
}

// L0 concat: fp32 [4][256][256] -> bf16 hi [1024][256] + lo plane at +262144
__global__ void prep_wc(const float* __restrict__ src, __nv_bfloat16* __restrict__ dst){
    int i = blockIdx.x*256 + threadIdx.x;       // 0..262143
    int k = i & 255;
    int t = i >> 8;
    int n = t & 255;
    int e = t >> 8;
    float v = src[e*65536 + k*256 + n];
    __nv_bfloat16 h = __float2bfloat16(v);
    long d = ((long)(e*256 + n))*256 + k;
    dst[d] = h;
    dst[262144 + d] = __float2bfloat16(v - __bfloat162float(h));
}

// fp32 [256,256] row-major -> transposed [N][K]
__global__ void prep_wt(const float* __restrict__ src, float* __restrict__ dst){
    int i = blockIdx.x*256 + threadIdx.x;
    int k = i >> 8, n = i & 255;
    dst[(long)n*256 + k] = src[(long)k*256 + n];
}

// ======================= encoder layer 1: h1 = relu(xs @ W1 + b1), K=6 exact fp32 =======================
__global__ void enc1_kernel(const float* __restrict__ x, const float* __restrict__ W1,
                            const float* __restrict__ b1, float* __restrict__ out){
    int n = blockIdx.x;
    __shared__ float xs[6];
    if (threadIdx.x < 6) xs[threadIdx.x] = x[n*16 + 4 + threadIdx.x];
    __syncthreads();
    float acc = 0.f;
#pragma unroll
    for (int k = 0; k < 6; ++k)
        acc += xs[k] * W1[k*HH + threadIdx.x];
    acc += b1[threadIdx.x];
    out[(long)n*HH + threadIdx.x] = fmaxf(acc, 0.f);
}

// ======================= 3-term tf32 GEMM (fp32-exact class) =======================
#define FBM 128
#define FAS 20
__global__ void __launch_bounds__(256) tf32gemm(
    const float* __restrict__ A, const float* __restrict__ Bt,
    const float* __restrict__ bias, float* __restrict__ C,
    uint32_t* __restrict__ Cp, int M)
{
    __shared__ float As[2][128*FAS];
    __shared__ float Bs[2][64*FAS];
    const int tid = threadIdx.x;
    const int wid = tid >> 5, lane = tid & 31;
    const int wr = wid >> 1, wc = wid & 1;
    const int bm = blockIdx.x * FBM, bn = blockIdx.y * 64;
    const int fr = lane >> 2, fc = lane & 3;

    float acc[2][4][4];
#pragma unroll
    for (int i = 0; i < 2; ++i)
#pragma unroll
        for (int j = 0; j < 4; ++j)
#pragma unroll
            for (int q = 0; q < 4; ++q) acc[i][j][q] = 0.f;

    float ar[8];
    float4 br;
    const int arow = tid >> 1, ac8 = (tid & 1) * 8;
    const int bnr = tid >> 2, bk4 = (tid & 3) * 4;

    auto ldg = [&](int ch){
        int k0 = ch * 16;
        int gr = bm + arow;
        if (gr < M){
            const float* ap = A + (long)gr*256 + k0 + ac8;
            float4 f0 = *(const float4*)ap;
            float4 f1 = *(const float4*)(ap + 4);
            ar[0]=f0.x; ar[1]=f0.y; ar[2]=f0.z; ar[3]=f0.w;
            ar[4]=f1.x; ar[5]=f1.y; ar[6]=f1.z; ar[7]=f1.w;
        } else {
#pragma unroll
            for (int q = 0; q < 8; ++q) ar[q] = 0.f;
        }
        br = *(const float4*)(Bt + (long)(bn + bnr)*256 + k0 + bk4);
    };
    auto sts = [&](int buf){
        float* pa = &As[buf][arow*FAS + ac8];
#pragma unroll
        for (int q = 0; q < 8; ++q) pa[q] = ar[q];
        float* pb = &Bs[buf][bnr*FAS + bk4];
        pb[0]=br.x; pb[1]=br.y; pb[2]=br.z; pb[3]=br.w;
    };
    auto compute = [&](int buf){
#pragma unroll
        for (int ks = 0; ks < 2; ++ks){
            int kk = ks * 8;
            uint32_t ah[2][4], al[2][4];
#pragma unroll
            for (int mt = 0; mt < 2; ++mt){
                int r0 = wr*32 + mt*16 + fr;
                float f0 = As[buf][r0*FAS + kk + fc];
                float f1 = As[buf][(r0+8)*FAS + kk + fc];
                float f2 = As[buf][r0*FAS + kk + fc + 4];
                float f3 = As[buf][(r0+8)*FAS + kk + fc + 4];
                tf_split(f0, ah[mt][0], al[mt][0]);
                tf_split(f1, ah[mt][1], al[mt][1]);
                tf_split(f2, ah[mt][2], al[mt][2]);
                tf_split(f3, ah[mt][3], al[mt][3]);
            }
#pragma unroll
            for (int nt = 0; nt < 4; ++nt){
                int n0 = wc*32 + nt*8 + fr;
                float g0 = Bs[buf][n0*FAS + kk + fc];
                float g1 = Bs[buf][n0*FAS + kk + fc + 4];
                uint32_t bh[2], bl[2];
                tf_split(g0, bh[0], bl[0]);
                tf_split(g1, bh[1], bl[1]);
#pragma unroll
                for (int mt = 0; mt < 2; ++mt){
                    mma_tf32(acc[mt][nt], ah[mt], bh);
                    mma_tf32(acc[mt][nt], al[mt], bh);
                    mma_tf32(acc[mt][nt], ah[mt], bl);
                }
            }
        }
    };

    ldg(0); sts(0); __syncthreads();
    for (int c = 0; c < 16; ++c){
        if (c + 1 < 16) ldg(c + 1);
        compute(c & 1);
        if (c + 1 < 16){ sts((c + 1) & 1); __syncthreads(); }
    }

#pragma unroll
    for (int mt = 0; mt < 2; ++mt){
#pragma unroll
        for (int nt = 0; nt < 4; ++nt){
            int row0 = bm + wr*32 + mt*16 + fr;
            int col  = bn + wc*32 + nt*8 + fc*2;
            float b0 = bias[col];
            float b1 = bias[col + 1];
#pragma unroll
            for (int half = 0; half < 2; ++half){
                int row = row0 + half*8;
                if (row < M){
                    float2 o;
                    o.x = acc[mt][nt][half*2 + 0] + b0;
                    o.y = acc[mt][nt][half*2 + 1] + b1;
                    *(float2*)(C + (long)row*256 + col) = o;
                    if (Cp){
                        uint2 po;
                        po.x = pack_hilo(o.x);
                        po.y = pack_hilo(o.y);
                        *(uint2*)(Cp + (long)row*256 + col) = po;
                    }
                }
            }
        }
    }
}

// ======================= mma.sync split-bf16 dual GEMM, 128x64 tile (proven R10) =======================
#define TBM 128
#define TBN 64
#define TBK 32
#define ARS 80
#define AS_PLANE 10240
#define AS_STAGE 20480
#define BS_PLANE 5120
#define BS_STAGE 10240
#define BS_OFF   40960
#define SMEM_DYN 61440

__global__ void __launch_bounds__(256) tgemm(
    const uint32_t* __restrict__ A0, int lda0,
    const uint32_t* __restrict__ A1, int lda1,
    const __nv_bfloat16* __restrict__ B0, const __nv_bfloat16* __restrict__ B1,
    const float* __restrict__ bias, float* __restrict__ C,
    int Nc, int M, int relu, int out_packed, int accum,
    const float* __restrict__ rowscale, int rs_stride,
    const uint32_t* __restrict__ addin)
{
    extern __shared__ char dsm[];
    const uint32_t sbase = smem_u32(dsm);

    const int tid  = threadIdx.x;
    const int wid  = tid >> 5;
    const int lane = tid & 31;
    const int wr   = wid >> 1;
    const int wc   = wid & 1;
    const int bm   = blockIdx.x * TBM;
    const int bn   = blockIdx.y * TBN;

    const int nch = (A1 != 0) ? 16 : 8;
    const long bplane = (long)Nc * 256;

    float acc[2][4][4];
#pragma unroll
    for (int i = 0; i < 2; ++i)
#pragma unroll
        for (int j = 0; j < 4; ++j)
#pragma unroll
            for (int q = 0; q < 4; ++q) acc[i][j][q] = 0.f;

    uint32_t aw[16];
    uint4 bh, bl;
    const int arow_g = tid >> 1;
    const int acol_g = (tid & 1) * 16;
    const int brow_g = tid >> 2;
    const int bcol_g = (tid & 3) * 8;

    auto ldg_chunk = [&](int c){
        int seg = c >> 3;
        int k0  = (c & 7) * TBK;
        const uint32_t* A = seg ? A1 : A0;
        const int lda = seg ? lda1 : lda0;
        int gr = bm + arow_g;
        if (gr < M){
            const uint32_t* ap = A + (long)gr*lda + k0 + acol_g;
            uint4 u0 = *(const uint4*)ap;
            uint4 u1 = *(const uint4*)(ap + 4);
            uint4 u2 = *(const uint4*)(ap + 8);
            uint4 u3 = *(const uint4*)(ap + 12);
            aw[0]=u0.x; aw[1]=u0.y; aw[2]=u0.z; aw[3]=u0.w;
            aw[4]=u1.x; aw[5]=u1.y; aw[6]=u1.z; aw[7]=u1.w;
            aw[8]=u2.x; aw[9]=u2.y; aw[10]=u2.z; aw[11]=u2.w;
            aw[12]=u3.x; aw[13]=u3.y; aw[14]=u3.z; aw[15]=u3.w;
        } else {
#pragma unroll
            for (int q = 0; q < 16; ++q) aw[q] = 0u;
        }
        const __nv_bfloat16* B = seg ? B1 : B0;
        const __nv_bfloat16* bp = B + (long)(bn + brow_g)*256 + k0 + bcol_g;
        bh = *(const uint4*)bp;
        bl = *(const uint4*)(bp + bplane);
    };

    auto sts_chunk = [&](int buf){
        uint32_t hh[8], ll[8];
#pragma unroll
        for (int q = 0; q < 8; ++q){
            hh[q] = __byte_perm(aw[2*q], aw[2*q+1], 0x7632);
            ll[q] = __byte_perm(aw[2*q], aw[2*q+1], 0x5410);
        }
        char* pa = dsm + buf*AS_STAGE + arow_g*ARS + acol_g*2;
        *(uint4*)pa        = make_uint4(hh[0], hh[1], hh[2], hh[3]);
        *(uint4*)(pa + 16) = make_uint4(hh[4], hh[5], hh[6], hh[7]);
        *(uint4*)(pa + AS_PLANE)      = make_uint4(ll[0], ll[1], ll[2], ll[3]);
        *(uint4*)(pa + AS_PLANE + 16) = make_uint4(ll[4], ll[5], ll[6], ll[7]);
        char* pb = dsm + BS_OFF + buf*BS_STAGE + brow_g*ARS + bcol_g*2;
        *(uint4*)pb              = bh;
        *(uint4*)(pb + BS_PLANE) = bl;
    };

    const int tile = lane >> 3;
    const int trr  = lane & 7;
    const int arow = wr*32 + ((tile & 1) << 3) + trr;
    const int akk0 = ((tile & 2) << 2);
    const int brow = wc*32 + ((tile & 2) << 2) + trr;
    const int bkk0 = ((tile & 1) << 3);

    auto compute = [&](int buf){
        uint32_t aBase = sbase + (uint32_t)buf*AS_STAGE;
        uint32_t bBase = sbase + BS_OFF + (uint32_t)buf*BS_STAGE;
#pragma unroll
        for (int kt = 0; kt < 2; ++kt){
            uint32_t a_hi[2][4], a_lo[2][4], bb[2][4];
            uint32_t ak = (uint32_t)(akk0 + kt*16)*2;
            uint32_t bk = (uint32_t)(bkk0 + kt*16)*2;
            ldm4(a_hi[0], aBase + (uint32_t)(arow)*ARS + ak);
            ldm4(a_hi[1], aBase + (uint32_t)(arow+16)*ARS + ak);
            ldm4(bb[0],   bBase + (uint32_t)(brow)*ARS + bk);
            ldm4(bb[1],   bBase + (uint32_t)(brow+16)*ARS + bk);
#pragma unroll
            for (int mt = 0; mt < 2; ++mt)
#pragma unroll
                for (int nt = 0; nt < 4; ++nt)
                    mma16816(acc[mt][nt], a_hi[mt], &bb[nt>>1][(nt&1)*2]);
            ldm4(a_lo[0], aBase + AS_PLANE + (uint32_t)(arow)*ARS + ak);
            ldm4(a_lo[1], aBase + AS_PLANE + (uint32_t)(arow+16)*ARS + ak);
#pragma unroll
            for (int mt = 0; mt < 2; ++mt)
#pragma unroll
                for (int nt = 0; nt < 4; ++nt)
                    mma16816(acc[mt][nt], a_lo[mt], &bb[nt>>1][(nt&1)*2]);
            ldm4(bb[0],   bBase + BS_PLANE + (uint32_t)(brow)*ARS + bk);
            ldm4(bb[1],   bBase + BS_PLANE + (uint32_t)(brow+16)*ARS + bk);
#pragma unroll
            for (int mt = 0; mt < 2; ++mt)
#pragma unroll
                for (int nt = 0; nt < 4; ++nt)
                    mma16816(acc[mt][nt], a_hi[mt], &bb[nt>>1][(nt&1)*2]);
        }
    };

    ldg_chunk(0);
    sts_chunk(0);
    __syncthreads();
    for (int c = 0; c < nch; ++c){
        if (c + 1 < nch) ldg_chunk(c + 1);
        compute(c & 1);
        if (c + 1 < nch){
            sts_chunk((c + 1) & 1);
            __syncthreads();
        }
    }

#pragma unroll
    for (int mt = 0; mt < 2; ++mt){
#pragma unroll
        for (int nt = 0; nt < 4; ++nt){
            int row0 = bm + wr*32 + mt*16 + (lane >> 2);
            int col  = bn + wc*32 + nt*8 + (lane & 3)*2;
            float b0 = bias[col];
            float b1 = bias[col + 1];
#pragma unroll
            for (int half = 0; half < 2; ++half){
                int row = row0 + half*8;
                if (row < M){
                    float v0 = acc[mt][nt][half*2 + 0] + b0;
                    float v1 = acc[mt][nt][half*2 + 1] + b1;
                    if (relu){ v0 = fmaxf(v0, 0.f); v1 = fmaxf(v1, 0.f); }
                    if (out_packed){
                        uint2 o;
                        o.x = pack_hilo(v0);
                        o.y = pack_hilo(v1);
                        *(uint2*)((uint32_t*)C + (long)row*Nc + col) = o;
                    } else {
                        if (addin){
                            uint2 ai = *(const uint2*)(addin + (long)row*Nc + col);
                            v0 += unpack_hilo(ai.x);
                            v1 += unpack_hilo(ai.y);
                        }
                        if (rowscale){
                            float rs = rowscale[(long)row*rs_stride];
                            v0 *= rs; v1 *= rs;
                        }
                        float* cp = C + (long)row*Nc + col;
                        if (accum){ v0 += cp[0]; v1 += cp[1]; }
                        float2 o; o.x = v0; o.y = v1;
                        *(float2*)cp = o;
                    }
                }
            }
        }
    }
}

// ---------------- histograms ----------------
__global__ void hist_nodes(const int* __restrict__ batch){
    __shared__ int s[GG];
    if(threadIdx.x < GG) s[threadIdx.x] = 0;
    __syncthreads();
    for(int i = blockIdx.x*blockDim.x + threadIdx.x; i < NN; i += gridDim.x*blockDim.x)
        atomicAdd(&s[batch[i]], 1);
    __syncthreads();
    if(threadIdx.x < GG && s[threadIdx.x]) atomicAdd(&g_ncnt[threadIdx.x], s[threadIdx.x]);
}

__global__ void edge_prep(const int* __restrict__ src, const int* __restrict__ dst,
                          const int* __restrict__ batch){
    __shared__ int s[GG];
    if(threadIdx.x < GG) s[threadIdx.x] = 0;
    __syncthreads();
    for(int i = blockIdx.x*blockDim.x + threadIdx.x; i < EE; i += gridDim.x*blockDim.x){
        atomicAdd(&s[batch[src[i]]], 1);
        atomicAdd(&g_deg[dst[i]], 1);
    }
    __syncthreads();
    if(threadIdx.x < GG && s[threadIdx.x]) atomicAdd(&g_ecnt[threadIdx.x], s[threadIdx.x]);
}

// ---------------- graph stats ----------------
__global__ void stats_kernel(){
    int g = threadIdx.x;
    float n   = fmaxf((float)g_ncnt[g], 1.f);
    float e   = (float)g_ecnt[g];
    float den = e / fmaxf(n*(n-1.f), 1.f);
    float ln  = logf(n);
    __shared__ float sn[GG], se[GG], sd[GG], sl[GG];
    sn[g]=n; se[g]=e; sd[g]=den; sl[g]=ln;
    __syncthreads();
    __shared__ float sc[8];
    if(g == 0){
        float mn=sl[0], mx=sl[0], s0=0, s1=0, s2=0;
        for(int i=0;i<GG;i++){ mn=fminf(mn,sl[i]); mx=fmaxf(mx,sl[i]); s0+=sn[i]; s1+=se[i]; s2+=sd[i]; }
        float m0=s0/GG, m1=s1/GG, m2=s2/GG;
        float q0=0,q1=0,q2=0;
        for(int i=0;i<GG;i++){
            float d0=sn[i]-m0, d1=se[i]-m1, d2=sd[i]-m2;
            q0+=d0*d0; q1+=d1*d1; q2+=d2*d2;
        }
        sc[0]=mn; sc[1]=mx; sc[2]=m0; sc[3]=m1; sc[4]=m2;
        sc[5]=sqrtf(q0/GG); sc[6]=sqrtf(q1/GG); sc[7]=sqrtf(q2/GG);
    }
    __syncthreads();
    g_lognn[g]       = (ln  - sc[0])/(sc[1]-sc[0]+1e-6f);
    g_featsn[g*3+0]  = (n   - sc[2])/(sc[5]+1e-6f);
    g_featsn[g*3+1]  = (e   - sc[3])/(sc[6]+1e-6f);
    g_featsn[g*3+2]  = (den - sc[4])/(sc[7]+1e-6f);
}

__global__ void sf_kernel(const int* __restrict__ batch){
    int i = blockIdx.x*blockDim.x + threadIdx.x;
    if(i < NN){
        int g = batch[i];
        g_sf[i*3+0] = g_featsn[g*3+0];
        g_sf[i*3+1] = g_featsn[g*3+1];
        g_sf[i*3+2] = g_featsn[g*3+2];
    }
}

// ---------------- CSR build ----------------
__global__ void scan1(){
    __shared__ int sh[1024];
    int i = blockIdx.x*1024 + threadIdx.x;
    int v = (i < NN) ? g_deg[i] : 0;
    sh[threadIdx.x] = v;
    __syncthreads();
    for(int off=1; off<1024; off<<=1){
        int t = sh[threadIdx.x];
        if(threadIdx.x >= off) t += sh[threadIdx.x - off];
        __syncthreads();
        sh[threadIdx.x] = t;
        __syncthreads();
    }
    if(i < NN) g_rowptr[i] = sh[threadIdx.x] - v;
    if(threadIdx.x == 1023) g_bsum[blockIdx.x] = sh[1023];
}

__global__ void scan2(int nb){
    if(threadIdx.x == 0){
        int run = 0;
        for(int b=0;b<nb;b++){ int v=g_bsum[b]; g_bsum[b]=run; run+=v; }
    }
}

__global__ void scan3(){
    int i = blockIdx.x*blockDim.x + threadIdx.x;
    if(i < NN) g_rowptr[i] += g_bsum[i >> 10];
    if(i == 0) g_rowptr[NN] = EE;
}

__global__ void place_edges(const int* __restrict__ src, const int* __restrict__ dst){
    for(int i = blockIdx.x*blockDim.x + threadIdx.x; i < EE; i += gridDim.x*blockDim.x){
        int d = dst[i];
        int idx = g_rowptr[d] + atomicAdd(&g_cur[d], 1);
        g_esrc[idx] = src[i];
    }
}

// ---------------- CSR gather aggregation (packed, grouped) ----------------
__global__ void aggregate_pg(const uint32_t* __restrict__ in, uint32_t* __restrict__ out,
                             int Win, long in_goff, int Wout, long out_goff){
    int n = blockIdx.x;
    const uint32_t* ip = in + (long)blockIdx.y * in_goff;
    uint32_t* op = out + (long)blockIdx.y * out_goff;
    int s0 = g_rowptr[n], s1 = g_rowptr[n+1];
    float a0=0.f, a1=0.f, a2=0.f, a3=0.f, a4=0.f, a5=0.f, a6=0.f, a7=0.f;
    int j = s0;
    for(; j + 8 <= s1; j += 8){
        int i0 = g_esrc[j],   i1 = g_esrc[j+1], i2 = g_esrc[j+2], i3 = g_esrc[j+3];
        int i4 = g_esrc[j+4], i5 = g_esrc[j+5], i6 = g_esrc[j+6], i7 = g_esrc[j+7];
        a0 += unpack_hilo(ip[(long)i0*Win + threadIdx.x]);
        a1 += unpack_hilo(ip[(long)i1*Win + threadIdx.x]);
        a2 += unpack_hilo(ip[(long)i2*Win + threadIdx.x]);
        a3 += unpack_hilo(ip[(long)i3*Win + threadIdx.x]);
        a4 += unpack_hilo(ip[(long)i4*Win + threadIdx.x]);
        a5 += unpack_hilo(ip[(long)i5*Win + threadIdx.x]);
        a6 += unpack_hilo(ip[(long)i6*Win + threadIdx.x]);
        a7 += unpack_hilo(ip[(long)i7*Win + threadIdx.x]);
    }
    for(; j < s1; ++j)
        a0 += unpack_hilo(ip[(long)g_esrc[j]*Win + threadIdx.x]);
    op[(long)n*Wout + threadIdx.x] = pack_hilo(((a0 + a1) + (a2 + a3)) + ((a4 + a5) + (a6 + a7)));
}

// ---------------- router (with fused K=3 sf correction) ----------------
__global__ void router_kernel(const float* __restrict__ t, const int* __restrict__ batch,
                              const float* __restrict__ lng, const float* __restrict__ lnb,
                              const float* __restrict__ W2, const float* __restrict__ b2,
                              const float* __restrict__ centers,
                              const float* __restrict__ sf, const float* __restrict__ W1s)
{
    int n = blockIdx.x; int tid = threadIdx.x;
    int lane = tid & 31, wid = tid >> 5;
    float s0f = sf[n*3+0], s1f = sf[n*3+1], s2f = sf[n*3+2];
    float v = t[(long)n*HH + tid]
            + s0f * W1s[tid] + s1f * W1s[HH + tid] + s2f * W1s[2*HH + tid];
    float s = v, sq = v*v;
#pragma unroll
    for(int o=16;o>0;o>>=1){
        s  += __shfl_down_sync(0xffffffffu, s,  o);
        sq += __shfl_down_sync(0xffffffffu, sq, o);
    }
    __shared__ float red[8*2];
    __shared__ float red4[8*4];
    __shared__ float bc[2];
    if(lane == 0){ red[wid*2]=s; red[wid*2+1]=sq; }
    __syncthreads();
    if(tid == 0){
        float S=0, Q=0;
        for(int w=0;w<8;w++){ S+=red[w*2]; Q+=red[w*2+1]; }
        float mean = S/HH;
        bc[0]=mean; bc[1]=Q/HH - mean*mean;
    }
    __syncthreads();
    float mean = bc[0], var = bc[1];
    float r = (v - mean)*rsqrtf(var + 1e-5f)*lng[tid] + lnb[tid];
    r = fmaxf(r, 0.f);
    float p[4];
#pragma unroll
    for(int e=0;e<4;e++) p[e] = r * W2[tid*4+e];
#pragma unroll
    for(int o=16;o>0;o>>=1)
#pragma unroll
        for(int e=0;e<4;e++) p[e] += __shfl_down_sync(0xffffffffu, p[e], o);
    if(lane == 0)
        for(int e=0;e<4;e++) red4[wid*4+e] = p[e];
    __syncthreads();
    if(tid == 0){
        float logit[4], probs[4];
        float lnode = g_lognn[batch[n]];
        for(int e=0;e<4;e++){
            float sum = 0;
            for(int w=0;w<8;w++) sum += red4[w*4+e];
            float learned = sum + b2[e];
            float d = lnode - centers[e];
            logit[e] = 0.7f*learned - 0.3f*d*d;
        }
        float mx = logit[0];
        for(int e=1;e<4;e++) mx = fmaxf(mx, logit[e]);
        float ssum = 0;
        for(int e=0;e<4;e++){ probs[e] = expf(logit[e]-mx); ssum += probs[e]; }
        for(int e=0;e<4;e++) probs[e] /= ssum;
        int i0 = 0;
        for(int e=1;e<4;e++) if(probs[e] > probs[i0]) i0 = e;
        int i1 = -1;
        for(int e=0;e<4;e++){
            if(e == i0) continue;
            if(i1 < 0 || probs[e] > probs[i1]) i1 = e;
        }
        float denom = probs[i0] + probs[i1] + 1e-8f;
        float wv[4] = {0.f,0.f,0.f,0.f};
        wv[i0] = probs[i0]/denom;
        wv[i1] = probs[i1]/denom;
        for(int e=0;e<4;e++) g_w[(long)n*4+e] = wv[e];
    }
}

// ---------------- host ----------------
extern "C" void kernel_launch(void* const* d_in, const int* in_sizes, int n_in,
                              void* d_out, int out_size)
{
    const float* x       = (const float*)d_in[0];
    const int*   ei      = (const int*)  d_in[1];
    const int*   batch   = (const int*)  d_in[2];
    const float* enc_W1  = (const float*)d_in[3];
    const float* enc_b1  = (const float*)d_in[4];
    const float* enc_W2  = (const float*)d_in[5];
    const float* enc_b2  = (const float*)d_in[6];
    const float* r_W1    = (const float*)d_in[7];
    const float* r_b1    = (const float*)d_in[8];
    const float* ln_g    = (const float*)d_in[9];
    const float* ln_b    = (const float*)d_in[10];
    const float* r_W2    = (const float*)d_in[11];
    const float* r_b2    = (const float*)d_in[12];
    const float* centers = (const float*)d_in[13];
    const float* W0_rel  = (const float*)d_in[14];
    const float* b0_rel  = (const float*)d_in[15];
    const float* W0_root = (const float*)d_in[16];
    const float* W1_rel  = (const float*)d_in[17];
    const float* b1_rel  = (const float*)d_in[18];
    const float* W1_root = (const float*)d_in[19];
    const float* W2_rel  = (const float*)d_in[20];
    const float* b2_rel  = (const float*)d_in[21];
    const float* W2_root = (const float*)d_in[22];
    const int* src = ei;
    const int* dst = ei + EE;
    float* out = (float*)d_out;

    float *p_h1,*p_h,*p_sf,*p_w,*p_wt,*p_zero;
    uint32_t *p_hp,*p_agg,*p_hE0,*p_hE1,*p_aggE;
    int *p_ncnt,*p_ecnt,*p_deg,*p_cur;
    __nv_bfloat16* p_wb;
    cudaGetSymbolAddress((void**)&p_h1,  g_h1);
    cudaGetSymbolAddress((void**)&p_h,   g_h);
    cudaGetSymbolAddress((void**)&p_hp,  g_hp);
    cudaGetSymbolAddress((void**)&p_agg, g_agg);
    cudaGetSymbolAddress((void**)&p_sf,  g_sf);
    cudaGetSymbolAddress((void**)&p_w,   g_w);
    cudaGetSymbolAddress((void**)&p_hE0, g_hE0);
    cudaGetSymbolAddress((void**)&p_hE1, g_hE1);
    cudaGetSymbolAddress((void**)&p_aggE,g_aggE);
    cudaGetSymbolAddress((void**)&p_ncnt,g_ncnt);
    cudaGetSymbolAddress((void**)&p_ecnt,g_ecnt);
    cudaGetSymbolAddress((void**)&p_deg, g_deg);
    cudaGetSymbolAddress((void**)&p_cur, g_cur);
    cudaGetSymbolAddress((void**)&p_wb,  g_wbuf);
    cudaGetSymbolAddress((void**)&p_wt,  g_wt);
    cudaGetSymbolAddress((void**)&p_zero,g_zero);

    cudaFuncSetAttribute(tgemm, cudaFuncAttributeMaxDynamicSharedMemorySize, SMEM_DYN);

    // ---- weight prep ----
    prep_wt<<<256,256>>>(enc_W2, p_wt);
    prep_wt<<<256,256>>>(r_W1,   p_wt + 65536);
    prep_wc<<<1024,256>>>(W0_rel,  p_wb + OFF_L0C);
    prep_wc<<<1024,256>>>(W0_root, p_wb + OFF_L0CR);
    prep_w<<<256,256>>>(W1_rel,  p_wb + OFF_L1,          256, 4, 65536, 262144);
    prep_w<<<256,256>>>(W1_root, p_wb + OFF_L1 + 131072, 256, 4, 65536, 262144);
    prep_w<<<128,256>>>(W2_rel,  p_wb + OFF_L2,          128, 4, 32768, 131072);
    prep_w<<<128,256>>>(W2_root, p_wb + OFF_L2 + 65536,  128, 4, 32768, 131072);

    // ---- stats + CSR prep ----
    cudaMemsetAsync(p_ncnt, 0, GG*sizeof(int));
    cudaMemsetAsync(p_ecnt, 0, GG*sizeof(int));
    cudaMemsetAsync(p_deg,  0, NN*sizeof(int));
    cudaMemsetAsync(p_cur,  0, NN*sizeof(int));
    hist_nodes<<<196, 256>>>(batch);
    edge_prep<<<784, 256>>>(src, dst, batch);
    stats_kernel<<<1, GG>>>();
    sf_kernel<<<(NN+255)/256, 256>>>(batch);
    int nscan = (NN+1023)/1024;
    scan1<<<nscan, 1024>>>();
    scan2<<<1, 32>>>(nscan);
    scan3<<<(NN+255)/256, 256>>>();
    place_edges<<<784, 256>>>(src, dst);

    const int TGRIDX = (NN + TBM - 1) / TBM;
    const dim3 fgrid((NN + FBM - 1) / FBM, 4);

    // ---- encoder (exact-class: fused K=6 kernel, then 3xTF32 tensor with fused pack) ----
    enc1_kernel<<<NN, 256>>>(x, enc_W1, enc_b1, p_h1);
    tf32gemm<<<fgrid, 256>>>(p_h1, p_wt, enc_b2, p_h, p_hp, NN);

    // ---- router (3xTF32 main; K=3 sf correction fused into router kernel) ----
    tf32gemm<<<fgrid, 256>>>(p_h, p_wt + 65536, r_b1, p_h1, (uint32_t*)0, NN);
    router_kernel<<<NN, 256>>>(p_h1, batch, ln_g, ln_b, r_W2, r_b2, centers,
                               p_sf, r_W1 + HH*HH);

    // ---- aggregate h (packed) ----
    aggregate_pg<<<dim3(NN,1), 256>>>(p_hp, p_agg, 256, 0, 256, 0);

    // ---- expert layer 0: single batched GEMM, Nc=1024, output hE0 as [n][1024] ----
    {
        dim3 grid(TGRIDX, 1024 / TBN);
        tgemm<<<grid, 256, SMEM_DYN>>>(p_agg, 256, p_hp, 256,
                                       p_wb + OFF_L0C, p_wb + OFF_L0CR,
                                       b0_rel, (float*)p_hE0, 1024, NN, 1, 1, 0,
                                       (const float*)0, 0, (const uint32_t*)0);
    }
    // aggregate hE0 per expert: in [n][1024] col-block e*256, out aggE[e][n][256]
    aggregate_pg<<<dim3(NN,4), 256>>>(p_hE0, p_aggE, 1024, 256, 256, (long)NN*256);

    // ---- expert layer 1 (A1 = hE0 column block, lda 1024) ----
    for(int e=0;e<NEXP;e++){
        dim3 grid(TGRIDX, 256 / TBN);
        tgemm<<<grid, 256, SMEM_DYN>>>(p_aggE + (long)e*NN*HH, 256,
                                       p_hE0 + e*256, 1024,
                                       p_wb + OFF_L1 + (long)e*262144,
                                       p_wb + OFF_L1 + (long)e*262144 + 131072,
                                       b1_rel + e*HH, (float*)(p_hE1 + (long)e*NN*HH),
                                       HH, NN, 1, 1, 0,
                                       (const float*)0, 0, (const uint32_t*)0);
    }

    // ---- expert layer 2, reassociated: t_e = hE1@W2_rel (128-wide) -> aggregate ->
    //      out (+)= w_e * (agg_te + hE1@W2_root + b2) ----
    for(int e=0;e<NEXP;e++){
        dim3 grid(TGRIDX, OD / TBN);
        tgemm<<<grid, 256, SMEM_DYN>>>(p_hE1 + (long)e*NN*HH, 256,
                                       (const uint32_t*)0, 0,
                                       p_wb + OFF_L2 + (long)e*131072, (const __nv_bfloat16*)0,
                                       p_zero, (float*)(p_aggE + (long)e*NN*HH),
                                       OD, NN, 0, 1, 0,
                                       (const float*)0, 0, (const uint32_t*)0);
    }
    aggregate_pg<<<dim3(NN,4), OD>>>(p_aggE, p_aggE + (long)NN*OD,
                                     128, (long)NN*HH, 128, (long)NN*HH);
    for(int e=0;e<NEXP;e++){
        dim3 grid(TGRIDX, OD / TBN);
        tgemm<<<grid, 256, SMEM_DYN>>>(p_hE1 + (long)e*NN*HH, 256,
                                       (const uint32_t*)0, 0,
                                       p_wb + OFF_L2 + (long)e*131072 + 65536, (const __nv_bfloat16*)0,
                                       b2_rel + e*OD, out, OD, NN, 0, 0, (e > 0),
                                       p_w + e, NEXP,
                                       p_aggE + (long)e*NN*HH + (long)NN*OD);
    }
}

// round 14
// speedup vs baseline: 1.0372x; 1.0082x over previous
#include <cuda_runtime.h>
#include <cuda_bf16.h>
#include <stdint.h>
#include <math.h>

#define NN 50000
#define EE 800000
#define HH 256
#define GG 64
#define NEXP 4
#define OD 128

// ---------------- scratch (device globals: no allocation allowed) ----------------
__device__ __align__(16) float g_h1[NN*HH];
__device__ __align__(16) float g_h[NN*HH];
__device__ __align__(16) uint32_t g_hp[NN*HH];        // h packed hi/lo
__device__ __align__(16) uint32_t g_agg[NN*HH];       // aggregate(h) packed
__device__ __align__(16) float g_sf[NN*3];
__device__ __align__(16) float g_w[NN*NEXP];
__device__ __align__(16) uint32_t g_hE0[(long)NEXP*NN*HH];   // packed, used as [NN][1024]
__device__ __align__(16) uint32_t g_hE1[(long)NEXP*NN*HH];   // packed per-expert
__device__ __align__(16) uint32_t g_aggE[(long)NEXP*NN*HH];  // packed (aggE, then te|root)
__device__ int   g_deg[NN];
__device__ int   g_rowptr[NN+1];
__device__ int   g_cur[NN];
__device__ int   g_esrc[EE];
__device__ int   g_bsum[64];
__device__ int   g_ncnt[GG];
__device__ int   g_ecnt[GG];
__device__ float g_featsn[GG*3];
__device__ float g_lognn[GG];
__device__ float g_zero[HH];                          // stays zero
#define WBUF_ELEMS 2883584
__device__ __align__(16) __nv_bfloat16 g_wbuf[WBUF_ELEMS];
__device__ __align__(16) float g_wt[2*65536];         // fp32 W^T: enc_W2, r_W1[:256]

// wbuf layout (elements):
#define OFF_L0C   0        // L0 rel concat [1024][256] hi + lo (524288)
#define OFF_L0CR  524288   // L0 root concat (524288)
#define OFF_L1    1048576  // per-expert stride 262144 (rel hi/lo, root hi/lo at +131072)
#define OFF_L2    2097152  // per-expert stride 131072: concat [256][256] hi + lo at +65536

// ======================= helpers =======================
__device__ __forceinline__ uint32_t smem_u32(const void* p){
    uint32_t a;
    asm("{ .reg .u64 t; cvta.to.shared.u64 t, %1; cvt.u32.u64 %0, t; }" : "=r"(a) : "l"(p));
    return a;
}
__device__ __forceinline__ void ldm4(uint32_t* r, uint32_t addr){
    asm volatile("ldmatrix.sync.aligned.m8n8.x4.shared.b16 {%0,%1,%2,%3}, [%4];"
        : "=r"(r[0]), "=r"(r[1]), "=r"(r[2]), "=r"(r[3]) : "r"(addr));
}
__device__ __forceinline__ void mma16816(float* c, const uint32_t* a, const uint32_t* b){
    asm volatile("mma.sync.aligned.m16n8k16.row.col.f32.bf16.bf16.f32 "
        "{%0,%1,%2,%3}, {%4,%5,%6,%7}, {%8,%9}, {%0,%1,%2,%3};"
        : "+f"(c[0]), "+f"(c[1]), "+f"(c[2]), "+f"(c[3])
        : "r"(a[0]), "r"(a[1]), "r"(a[2]), "r"(a[3]), "r"(b[0]), "r"(b[1]));
}
__device__ __forceinline__ void mma_tf32(float* c, const uint32_t* a, const uint32_t* b){
    asm volatile("mma.sync.aligned.m16n8k8.row.col.f32.tf32.tf32.f32 "
        "{%0,%1,%2,%3}, {%4,%5,%6,%7}, {%8,%9}, {%0,%1,%2,%3};"
        : "+f"(c[0]), "+f"(c[1]), "+f"(c[2]), "+f"(c[3])
        : "r"(a[0]), "r"(a[1]), "r"(a[2]), "r"(a[3]), "r"(b[0]), "r"(b[1]));
}
__device__ __forceinline__ uint32_t f2tf(float f){
    uint32_t r;
    asm("cvt.rna.tf32.f32 %0, %1;" : "=r"(r) : "f"(f));
    return r;
}
__device__ __forceinline__ void tf_split(float f, uint32_t& hi, uint32_t& lo){
    hi = f2tf(f);
    lo = f2tf(f - __uint_as_float(hi));
}
__device__ __forceinline__ uint32_t pack_hilo(float v){
    __nv_bfloat16 h = __float2bfloat16(v);
    __nv_bfloat16 l = __float2bfloat16(v - __bfloat162float(h));
    return ((uint32_t)__bfloat16_as_ushort(h) << 16) | (uint32_t)__bfloat16_as_ushort(l);
}
__device__ __forceinline__ float unpack_hilo(uint32_t w){
    float h = __bfloat162float(__ushort_as_bfloat16((unsigned short)(w >> 16)));
    float l = __bfloat162float(__ushort_as_bfloat16((unsigned short)(w & 0xFFFFu)));
    return h + l;
}

// ======================= weight prep =======================
__global__ void prep_w(const float* __restrict__ srcp, __nv_bfloat16* __restrict__ dstp,
                       int Ncols, int nSeg, long sstr, long dstr){
    long total = (long)nSeg * Ncols * 256;
    long plane = (long)Ncols * 256;
    for (long i = (long)blockIdx.x*blockDim.x + threadIdx.x; i < total; i += (long)gridDim.x*blockDim.x){
        int k = (int)(i & 255);
        long t = i >> 8;
        int n = (int)(t % Ncols);
        int e = (int)(t / Ncols);
        float v = srcp[e*sstr + (long)k*Ncols + n];
        __nv_bfloat16 h = __float2bfloat16(v);
        float rem = v - __bfloat162float(h);
        dstp[e*dstr + (long)n*256 + k] = h;
        dstp[e*dstr + plane + (long)n*256 + k] = __float2bfloat16(rem);
    }
}

// L0 concat: fp32 [4][256][256] -> bf16 hi [1024][256] + lo plane at +262144
__global__ void prep_wc(const float* __restrict__ src, __nv_bfloat16* __restrict__ dst){
    int i = blockIdx.x*256 + threadIdx.x;       // 0..262143
    int k = i & 255;
    int t = i >> 8;
    int n = t & 255;
    int e = t >> 8;
    float v = src[e*65536 + k*256 + n];
    __nv_bfloat16 h = __float2bfloat16(v);
    long d = ((long)(e*256 + n))*256 + k;
    dst[d] = h;
    dst[262144 + d] = __float2bfloat16(v - __bfloat162float(h));
}

// L2 concat per expert: [W2_rel | W2_root] -> bf16 hi [256][256] + lo at +65536, stride 131072
__global__ void prep_w2c(const float* __restrict__ rel, const float* __restrict__ root,
                         __nv_bfloat16* __restrict__ dst){
    int i = blockIdx.x*256 + threadIdx.x;       // 0..262143 (4 experts x 256 n x 256 k)
    int k = i & 255;
    int t = i >> 8;
    int n = t & 255;
    int e = t >> 8;
    float v = (n < 128) ? rel[e*32768 + k*128 + n] : root[e*32768 + k*128 + (n-128)];
    __nv_bfloat16 h = __float2bfloat16(v);
    long d = (long)e*131072 + (long)n*256 + k;
    dst[d] = h;
    dst[d + 65536] = __float2bfloat16(v - __bfloat162float(h));
}

// fp32 [256,256] row-major -> transposed [N][K]
__global__ void prep_wt(const float* __restrict__ src, float* __restrict__ dst){
    int i = blockIdx.x*256 + threadIdx.x;
    int k = i >> 8, n = i & 255;
    dst[(long)n*256 + k] = src[(long)k*256 + n];
}

// ======================= encoder layer 1: h1 = relu(xs @ W1 + b1), K=6 exact fp32 =======================
__global__ void enc1_kernel(const float* __restrict__ x, const float* __restrict__ W1,
                            const float* __restrict__ b1, float* __restrict__ out){
    int n = blockIdx.x;
    __shared__ float xs[6];
    if (threadIdx.x < 6) xs[threadIdx.x] = x[n*16 + 4 + threadIdx.x];
    __syncthreads();
    float acc = 0.f;
#pragma unroll
    for (int k = 0; k < 6; ++k)
        acc += xs[k] * W1[k*HH + threadIdx.x];
    acc += b1[threadIdx.x];
    out[(long)n*HH + threadIdx.x] = fmaxf(acc, 0.f);
}

// ======================= 3-term tf32 GEMM (fp32-exact class) =======================
#define FBM 128
#define FAS 20
__global__ void __launch_bounds__(256) tf32gemm(
    const float* __restrict__ A, const float* __restrict__ Bt,
    const float* __restrict__ bias, float* __restrict__ C,
    uint32_t* __restrict__ Cp, int M)
{
    __shared__ float As[2][128*FAS];
    __shared__ float Bs[2][64*FAS];
    const int tid = threadIdx.x;
    const int wid = tid >> 5, lane = tid & 31;
    const int wr = wid >> 1, wc = wid & 1;
    const int bm = blockIdx.x * FBM, bn = blockIdx.y * 64;
    const int fr = lane >> 2, fc = lane & 3;

    float acc[2][4][4];
#pragma unroll
    for (int i = 0; i < 2; ++i)
#pragma unroll
        for (int j = 0; j < 4; ++j)
#pragma unroll
            for (int q = 0; q < 4; ++q) acc[i][j][q] = 0.f;

    float ar[8];
    float4 br;
    const int arow = tid >> 1, ac8 = (tid & 1) * 8;
    const int bnr = tid >> 2, bk4 = (tid & 3) * 4;

    auto ldg = [&](int ch){
        int k0 = ch * 16;
        int gr = bm + arow;
        if (gr < M){
            const float* ap = A + (long)gr*256 + k0 + ac8;
            float4 f0 = *(const float4*)ap;
            float4 f1 = *(const float4*)(ap + 4);
            ar[0]=f0.x; ar[1]=f0.y; ar[2]=f0.z; ar[3]=f0.w;
            ar[4]=f1.x; ar[5]=f1.y; ar[6]=f1.z; ar[7]=f1.w;
        } else {
#pragma unroll
            for (int q = 0; q < 8; ++q) ar[q] = 0.f;
        }
        br = *(const float4*)(Bt + (long)(bn + bnr)*256 + k0 + bk4);
    };
    auto sts = [&](int buf){
        float* pa = &As[buf][arow*FAS + ac8];
#pragma unroll
        for (int q = 0; q < 8; ++q) pa[q] = ar[q];
        float* pb = &Bs[buf][bnr*FAS + bk4];
        pb[0]=br.x; pb[1]=br.y; pb[2]=br.z; pb[3]=br.w;
    };
    auto compute = [&](int buf){
#pragma unroll
        for (int ks = 0; ks < 2; ++ks){
            int kk = ks * 8;
            uint32_t ah[2][4], al[2][4];
#pragma unroll
            for (int mt = 0; mt < 2; ++mt){
                int r0 = wr*32 + mt*16 + fr;
                float f0 = As[buf][r0*FAS + kk + fc];
                float f1 = As[buf][(r0+8)*FAS + kk + fc];
                float f2 = As[buf][r0*FAS + kk + fc + 4];
                float f3 = As[buf][(r0+8)*FAS + kk + fc + 4];
                tf_split(f0, ah[mt][0], al[mt][0]);
                tf_split(f1, ah[mt][1], al[mt][1]);
                tf_split(f2, ah[mt][2], al[mt][2]);
                tf_split(f3, ah[mt][3], al[mt][3]);
            }
#pragma unroll
            for (int nt = 0; nt < 4; ++nt){
                int n0 = wc*32 + nt*8 + fr;
                float g0 = Bs[buf][n0*FAS + kk + fc];
                float g1 = Bs[buf][n0*FAS + kk + fc + 4];
                uint32_t bh[2], bl[2];
                tf_split(g0, bh[0], bl[0]);
                tf_split(g1, bh[1], bl[1]);
#pragma unroll
                for (int mt = 0; mt < 2; ++mt){
                    mma_tf32(acc[mt][nt], ah[mt], bh);
                    mma_tf32(acc[mt][nt], al[mt], bh);
                    mma_tf32(acc[mt][nt], ah[mt], bl);
                }
            }
        }
    };

    ldg(0); sts(0); __syncthreads();
    for (int c = 0; c < 16; ++c){
        if (c + 1 < 16) ldg(c + 1);
        compute(c & 1);
        if (c + 1 < 16){ sts((c + 1) & 1); __syncthreads(); }
    }

#pragma unroll
    for (int mt = 0; mt < 2; ++mt){
#pragma unroll
        for (int nt = 0; nt < 4; ++nt){
            int row0 = bm + wr*32 + mt*16 + fr;
            int col  = bn + wc*32 + nt*8 + fc*2;
            float b0 = bias[col];
            float b1 = bias[col + 1];
#pragma unroll
            for (int half = 0; half < 2; ++half){
                int row = row0 + half*8;
                if (row < M){
                    float2 o;
                    o.x = acc[mt][nt][half*2 + 0] + b0;
                    o.y = acc[mt][nt][half*2 + 1] + b1;
                    *(float2*)(C + (long)row*256 + col) = o;
                    if (Cp){
                        uint2 po;
                        po.x = pack_hilo(o.x);
                        po.y = pack_hilo(o.y);
                        *(uint2*)(Cp + (long)row*256 + col) = po;
                    }
                }
            }
        }
    }
}

// ======================= mma.sync split-bf16 dual GEMM, 128x64 tile (proven R10) =======================
#define TBM 128
#define TBN 64
#define TBK 32
#define ARS 80
#define AS_PLANE 10240
#define AS_STAGE 20480
#define BS_PLANE 5120
#define BS_STAGE 10240
#define BS_OFF   40960
#define SMEM_DYN 61440

__global__ void __launch_bounds__(256) tgemm(
    const uint32_t* __restrict__ A0, int lda0,
    const uint32_t* __restrict__ A1, int lda1,
    const __nv_bfloat16* __restrict__ B0, const __nv_bfloat16* __restrict__ B1,
    const float* __restrict__ bias, float* __restrict__ C,
    int Nc, int M, int relu, int out_packed, int accum,
    const float* __restrict__ rowscale, int rs_stride,
    const uint32_t* __restrict__ addin)
{
    extern __shared__ char dsm[];
    const uint32_t sbase = smem_u32(dsm);

    const int tid  = threadIdx.x;
    const int wid  = tid >> 5;
    const int lane = tid & 31;
    const int wr   = wid >> 1;
    const int wc   = wid & 1;
    const int bm   = blockIdx.x * TBM;
    const int bn   = blockIdx.y * TBN;

    const int nch = (A1 != 0) ? 16 : 8;
    const long bplane = (long)Nc * 256;

    float acc[2][4][4];
#pragma unroll
    for (int i = 0; i < 2; ++i)
#pragma unroll
        for (int j = 0; j < 4; ++j)
#pragma unroll
            for (int q = 0; q < 4; ++q) acc[i][j][q] = 0.f;

    uint32_t aw[16];
    uint4 bh, bl;
    const int arow_g = tid >> 1;
    const int acol_g = (tid & 1) * 16;
    const int brow_g = tid >> 2;
    const int bcol_g = (tid & 3) * 8;

    auto ldg_chunk = [&](int c){
        int seg = c >> 3;
        int k0  = (c & 7) * TBK;
        const uint32_t* A = seg ? A1 : A0;
        const int lda = seg ? lda1 : lda0;
        int gr = bm + arow_g;
        if (gr < M){
            const uint32_t* ap = A + (long)gr*lda + k0 + acol_g;
            uint4 u0 = *(const uint4*)ap;
            uint4 u1 = *(const uint4*)(ap + 4);
            uint4 u2 = *(const uint4*)(ap + 8);
            uint4 u3 = *(const uint4*)(ap + 12);
            aw[0]=u0.x; aw[1]=u0.y; aw[2]=u0.z; aw[3]=u0.w;
            aw[4]=u1.x; aw[5]=u1.y; aw[6]=u1.z; aw[7]=u1.w;
            aw[8]=u2.x; aw[9]=u2.y; aw[10]=u2.z; aw[11]=u2.w;
            aw[12]=u3.x; aw[13]=u3.y; aw[14]=u3.z; aw[15]=u3.w;
        } else {
#pragma unroll
            for (int q = 0; q < 16; ++q) aw[q] = 0u;
        }
        const __nv_bfloat16* B = seg ? B1 : B0;
        const __nv_bfloat16* bp = B + (long)(bn + brow_g)*256 + k0 + bcol_g;
        bh = *(const uint4*)bp;
        bl = *(const uint4*)(bp + bplane);
    };

    auto sts_chunk = [&](int buf){
        uint32_t hh[8], ll[8];
#pragma unroll
        for (int q = 0; q < 8; ++q){
            hh[q] = __byte_perm(aw[2*q], aw[2*q+1], 0x7632);
            ll[q] = __byte_perm(aw[2*q], aw[2*q+1], 0x5410);
        }
        char* pa = dsm + buf*AS_STAGE + arow_g*ARS + acol_g*2;
        *(uint4*)pa        = make_uint4(hh[0], hh[1], hh[2], hh[3]);
        *(uint4*)(pa + 16) = make_uint4(hh[4], hh[5], hh[6], hh[7]);
        *(uint4*)(pa + AS_PLANE)      = make_uint4(ll[0], ll[1], ll[2], ll[3]);
        *(uint4*)(pa + AS_PLANE + 16) = make_uint4(ll[4], ll[5], ll[6], ll[7]);
        char* pb = dsm + BS_OFF + buf*BS_STAGE + brow_g*ARS + bcol_g*2;
        *(uint4*)pb              = bh;
        *(uint4*)(pb + BS_PLANE) = bl;
    };

    const int tile = lane >> 3;
    const int trr  = lane & 7;
    const int arow = wr*32 + ((tile & 1) << 3) + trr;
    const int akk0 = ((tile & 2) << 2);
    const int brow = wc*32 + ((tile & 2) << 2) + trr;
    const int bkk0 = ((tile & 1) << 3);

    auto compute = [&](int buf){
        uint32_t aBase = sbase + (uint32_t)buf*AS_STAGE;
        uint32_t bBase = sbase + BS_OFF + (uint32_t)buf*BS_STAGE;
#pragma unroll
        for (int kt = 0; kt < 2; ++kt){
            uint32_t a_hi[2][4], a_lo[2][4], bb[2][4];
            uint32_t ak = (uint32_t)(akk0 + kt*16)*2;
            uint32_t bk = (uint32_t)(bkk0 + kt*16)*2;
            ldm4(a_hi[0], aBase + (uint32_t)(arow)*ARS + ak);
            ldm4(a_hi[1], aBase + (uint32_t)(arow+16)*ARS + ak);
            ldm4(bb[0],   bBase + (uint32_t)(brow)*ARS + bk);
            ldm4(bb[1],   bBase + (uint32_t)(brow+16)*ARS + bk);
#pragma unroll
            for (int mt = 0; mt < 2; ++mt)
#pragma unroll
                for (int nt = 0; nt < 4; ++nt)
                    mma16816(acc[mt][nt], a_hi[mt], &bb[nt>>1][(nt&1)*2]);
            ldm4(a_lo[0], aBase + AS_PLANE + (uint32_t)(arow)*ARS + ak);
            ldm4(a_lo[1], aBase + AS_PLANE + (uint32_t)(arow+16)*ARS + ak);
#pragma unroll
            for (int mt = 0; mt < 2; ++mt)
#pragma unroll
                for (int nt = 0; nt < 4; ++nt)
                    mma16816(acc[mt][nt], a_lo[mt], &bb[nt>>1][(nt&1)*2]);
            ldm4(bb[0],   bBase + BS_PLANE + (uint32_t)(brow)*ARS + bk);
            ldm4(bb[1],   bBase + BS_PLANE + (uint32_t)(brow+16)*ARS + bk);
#pragma unroll
            for (int mt = 0; mt < 2; ++mt)
#pragma unroll
                for (int nt = 0; nt < 4; ++nt)
                    mma16816(acc[mt][nt], a_hi[mt], &bb[nt>>1][(nt&1)*2]);
        }
    };

    ldg_chunk(0);
    sts_chunk(0);
    __syncthreads();
    for (int c = 0; c < nch; ++c){
        if (c + 1 < nch) ldg_chunk(c + 1);
        compute(c & 1);
        if (c + 1 < nch){
            sts_chunk((c + 1) & 1);
            __syncthreads();
        }
    }

#pragma unroll
    for (int mt = 0; mt < 2; ++mt){
#pragma unroll
        for (int nt = 0; nt < 4; ++nt){
            int row0 = bm + wr*32 + mt*16 + (lane >> 2);
            int col  = bn + wc*32 + nt*8 + (lane & 3)*2;
            float b0 = bias[col];
            float b1 = bias[col + 1];
#pragma unroll
            for (int half = 0; half < 2; ++half){
                int row = row0 + half*8;
                if (row < M){
                    float v0 = acc[mt][nt][half*2 + 0] + b0;
                    float v1 = acc[mt][nt][half*2 + 1] + b1;
                    if (relu){ v0 = fmaxf(v0, 0.f); v1 = fmaxf(v1, 0.f); }
                    if (out_packed){
                        uint2 o;
                        o.x = pack_hilo(v0);
                        o.y = pack_hilo(v1);
                        *(uint2*)((uint32_t*)C + (long)row*Nc + col) = o;
                    } else {
                        if (addin){
                            uint2 ai = *(const uint2*)(addin + (long)row*Nc + col);
                            v0 += unpack_hilo(ai.x);
                            v1 += unpack_hilo(ai.y);
                        }
                        if (rowscale){
                            float rs = rowscale[(long)row*rs_stride];
                            v0 *= rs; v1 *= rs;
                        }
                        float* cp = C + (long)row*Nc + col;
                        if (accum){ v0 += cp[0]; v1 += cp[1]; }
                        float2 o; o.x = v0; o.y = v1;
                        *(float2*)cp = o;
                    }
                }
            }
        }
    }
}

// ---------------- histograms ----------------
__global__ void hist_nodes(const int* __restrict__ batch){
    __shared__ int s[GG];
    if(threadIdx.x < GG) s[threadIdx.x] = 0;
    __syncthreads();
    for(int i = blockIdx.x*blockDim.x + threadIdx.x; i < NN; i += gridDim.x*blockDim.x)
        atomicAdd(&s[batch[i]], 1);
    __syncthreads();
    if(threadIdx.x < GG && s[threadIdx.x]) atomicAdd(&g_ncnt[threadIdx.x], s[threadIdx.x]);
}

__global__ void edge_prep(const int* __restrict__ src, const int* __restrict__ dst,
                          const int* __restrict__ batch){
    __shared__ int s[GG];
    if(threadIdx.x < GG) s[threadIdx.x] = 0;
    __syncthreads();
    for(int i = blockIdx.x*blockDim.x + threadIdx.x; i < EE; i += gridDim.x*blockDim.x){
        atomicAdd(&s[batch[src[i]]], 1);
        atomicAdd(&g_deg[dst[i]], 1);
    }
    __syncthreads();
    if(threadIdx.x < GG && s[threadIdx.x]) atomicAdd(&g_ecnt[threadIdx.x], s[threadIdx.x]);
}

// ---------------- graph stats ----------------
__global__ void stats_kernel(){
    int g = threadIdx.x;
    float n   = fmaxf((float)g_ncnt[g], 1.f);
    float e   = (float)g_ecnt[g];
    float den = e / fmaxf(n*(n-1.f), 1.f);
    float ln  = logf(n);
    __shared__ float sn[GG], se[GG], sd[GG], sl[GG];
    sn[g]=n; se[g]=e; sd[g]=den; sl[g]=ln;
    __syncthreads();
    __shared__ float sc[8];
    if(g == 0){
        float mn=sl[0], mx=sl[0], s0=0, s1=0, s2=0;
        for(int i=0;i<GG;i++){ mn=fminf(mn,sl[i]); mx=fmaxf(mx,sl[i]); s0+=sn[i]; s1+=se[i]; s2+=sd[i]; }
        float m0=s0/GG, m1=s1/GG, m2=s2/GG;
        float q0=0,q1=0,q2=0;
        for(int i=0;i<GG;i++){
            float d0=sn[i]-m0, d1=se[i]-m1, d2=sd[i]-m2;
            q0+=d0*d0; q1+=d1*d1; q2+=d2*d2;
        }
        sc[0]=mn; sc[1]=mx; sc[2]=m0; sc[3]=m1; sc[4]=m2;
        sc[5]=sqrtf(q0/GG); sc[6]=sqrtf(q1/GG); sc[7]=sqrtf(q2/GG);
    }
    __syncthreads();
    g_lognn[g]       = (ln  - sc[0])/(sc[1]-sc[0]+1e-6f);
    g_featsn[g*3+0]  = (n   - sc[2])/(sc[5]+1e-6f);
    g_featsn[g*3+1]  = (e   - sc[3])/(sc[6]+1e-6f);
    g_featsn[g*3+2]  = (den - sc[4])/(sc[7]+1e-6f);
}

__global__ void sf_kernel(const int* __restrict__ batch){
    int i = blockIdx.x*blockDim.x + threadIdx.x;
    if(i < NN){
        int g = batch[i];
        g_sf[i*3+0] = g_featsn[g*3+0];
        g_sf[i*3+1] = g_featsn[g*3+1];
        g_sf[i*3+2] = g_featsn[g*3+2];
    }
}

// ---------------- CSR build ----------------
__global__ void scan1(){
    __shared__ int sh[1024];
    int i = blockIdx.x*1024 + threadIdx.x;
    int v = (i < NN) ? g_deg[i] : 0;
    sh[threadIdx.x] = v;
    __syncthreads();
    for(int off=1; off<1024; off<<=1){
        int t = sh[threadIdx.x];
        if(threadIdx.x >= off) t += sh[threadIdx.x - off];
        __syncthreads();
        sh[threadIdx.x] = t;
        __syncthreads();
    }
    if(i < NN) g_rowptr[i] = sh[threadIdx.x] - v;
    if(threadIdx.x == 1023) g_bsum[blockIdx.x] = sh[1023];
}

__global__ void scan2(int nb){
    if(threadIdx.x == 0){
        int run = 0;
        for(int b=0;b<nb;b++){ int v=g_bsum[b]; g_bsum[b]=run; run+=v; }
    }
}

__global__ void scan3(){
    int i = blockIdx.x*blockDim.x + threadIdx.x;
    if(i < NN) g_rowptr[i] += g_bsum[i >> 10];
    if(i == 0) g_rowptr[NN] = EE;
}

__global__ void place_edges(const int* __restrict__ src, const int* __restrict__ dst){
    for(int i = blockIdx.x*blockDim.x + threadIdx.x; i < EE; i += gridDim.x*blockDim.x){
        int d = dst[i];
        int idx = g_rowptr[d] + atomicAdd(&g_cur[d], 1);
        g_esrc[idx] = src[i];
    }
}

// ---------------- CSR gather aggregation (packed, grouped) ----------------
__global__ void aggregate_pg(const uint32_t* __restrict__ in, uint32_t* __restrict__ out,
                             int Win, long in_goff, int Wout, long out_goff){
    int n = blockIdx.x;
    const uint32_t* ip = in + (long)blockIdx.y * in_goff;
    uint32_t* op = out + (long)blockIdx.y * out_goff;
    int s0 = g_rowptr[n], s1 = g_rowptr[n+1];
    float a0=0.f, a1=0.f, a2=0.f, a3=0.f, a4=0.f, a5=0.f, a6=0.f, a7=0.f;
    int j = s0;
    for(; j + 8 <= s1; j += 8){
        int i0 = g_esrc[j],   i1 = g_esrc[j+1], i2 = g_esrc[j+2], i3 = g_esrc[j+3];
        int i4 = g_esrc[j+4], i5 = g_esrc[j+5], i6 = g_esrc[j+6], i7 = g_esrc[j+7];
        a0 += unpack_hilo(ip[(long)i0*Win + threadIdx.x]);
        a1 += unpack_hilo(ip[(long)i1*Win + threadIdx.x]);
        a2 += unpack_hilo(ip[(long)i2*Win + threadIdx.x]);
        a3 += unpack_hilo(ip[(long)i3*Win + threadIdx.x]);
        a4 += unpack_hilo(ip[(long)i4*Win + threadIdx.x]);
        a5 += unpack_hilo(ip[(long)i5*Win + threadIdx.x]);
        a6 += unpack_hilo(ip[(long)i6*Win + threadIdx.x]);
        a7 += unpack_hilo(ip[(long)i7*Win + threadIdx.x]);
    }
    for(; j < s1; ++j)
        a0 += unpack_hilo(ip[(long)g_esrc[j]*Win + threadIdx.x]);
    op[(long)n*Wout + threadIdx.x] = pack_hilo(((a0 + a1) + (a2 + a3)) + ((a4 + a5) + (a6 + a7)));
}

// ---------------- final: aggregate t_e + combine across experts ----------------
// te buffers: per expert at te + e*NN*256, row layout [256]: cols 0-127 t_e, 128-255 root
__global__ void agg_combine(const uint32_t* __restrict__ te, const float* __restrict__ w,
                            const float* __restrict__ b2, float* __restrict__ out){
    int n = blockIdx.x;
    int c = threadIdx.x;          // 0..127
    int s0 = g_rowptr[n], s1 = g_rowptr[n+1];
    float res = 0.f;
#pragma unroll
    for (int e = 0; e < NEXP; ++e){
        const uint32_t* tp = te + (long)e*NN*256;
        float a0=0.f, a1=0.f, a2=0.f, a3=0.f;
        int j = s0;
        for(; j + 4 <= s1; j += 4){
            int i0 = g_esrc[j], i1 = g_esrc[j+1], i2 = g_esrc[j+2], i3 = g_esrc[j+3];
            a0 += unpack_hilo(tp[(long)i0*256 + c]);
            a1 += unpack_hilo(tp[(long)i1*256 + c]);
            a2 += unpack_hilo(tp[(long)i2*256 + c]);
            a3 += unpack_hilo(tp[(long)i3*256 + c]);
        }
        for(; j < s1; ++j)
            a0 += unpack_hilo(tp[(long)g_esrc[j]*256 + c]);
        float agg = (a0 + a1) + (a2 + a3);
        float root = unpack_hilo(tp[(long)n*256 + 128 + c]);
        res += w[n*NEXP + e] * (agg + root + b2[e*OD + c]);
    }
    out[(long)n*OD + c] = res;
}

// ---------------- router (with fused K=3 sf correction) ----------------
__global__ void router_kernel(const float* __restrict__ t, const int* __restrict__ batch,
                              const float* __restrict__ lng, const float* __restrict__ lnb,
                              const float* __restrict__ W2, const float* __restrict__ b2,
                              const float* __restrict__ centers,
                              const float* __restrict__ sf, const float* __restrict__ W1s)
{
    int n = blockIdx.x; int tid = threadIdx.x;
    int lane = tid & 31, wid = tid >> 5;
    float s0f = sf[n*3+0], s1f = sf[n*3+1], s2f = sf[n*3+2];
    float v = t[(long)n*HH + tid]
            + s0f * W1s[tid] + s1f * W1s[HH + tid] + s2f * W1s[2*HH + tid];
    float s = v, sq = v*v;
#pragma unroll
    for(int o=16;o>0;o>>=1){
        s  += __shfl_down_sync(0xffffffffu, s,  o);
        sq += __shfl_down_sync(0xffffffffu, sq, o);
    }
    __shared__ float red[8*2];
    __shared__ float red4[8*4];
    __shared__ float bc[2];
    if(lane == 0){ red[wid*2]=s; red[wid*2+1]=sq; }
    __syncthreads();
    if(tid == 0){
        float S=0, Q=0;
        for(int w=0;w<8;w++){ S+=red[w*2]; Q+=red[w*2+1]; }
        float mean = S/HH;
        bc[0]=mean; bc[1]=Q/HH - mean*mean;
    }
    __syncthreads();
    float mean = bc[0], var = bc[1];
    float r = (v - mean)*rsqrtf(var + 1e-5f)*lng[tid] + lnb[tid];
    r = fmaxf(r, 0.f);
    float p[4];
#pragma unroll
    for(int e=0;e<4;e++) p[e] = r * W2[tid*4+e];
#pragma unroll
    for(int o=16;o>0;o>>=1)
#pragma unroll
        for(int e=0;e<4;e++) p[e] += __shfl_down_sync(0xffffffffu, p[e], o);
    if(lane == 0)
        for(int e=0;e<4;e++) red4[wid*4+e] = p[e];
    __syncthreads();
    if(tid == 0){
        float logit[4], probs[4];
        float lnode = g_lognn[batch[n]];
        for(int e=0;e<4;e++){
            float sum = 0;
            for(int w=0;w<8;w++) sum += red4[w*4+e];
            float learned = sum + b2[e];
            float d = lnode - centers[e];
            logit[e] = 0.7f*learned - 0.3f*d*d;
        }
        float mx = logit[0];
        for(int e=1;e<4;e++) mx = fmaxf(mx, logit[e]);
        float ssum = 0;
        for(int e=0;e<4;e++){ probs[e] = expf(logit[e]-mx); ssum += probs[e]; }
        for(int e=0;e<4;e++) probs[e] /= ssum;
        int i0 = 0;
        for(int e=1;e<4;e++) if(probs[e] > probs[i0]) i0 = e;
        int i1 = -1;
        for(int e=0;e<4;e++){
            if(e == i0) continue;
            if(i1 < 0 || probs[e] > probs[i1]) i1 = e;
        }
        float denom = probs[i0] + probs[i1] + 1e-8f;
        float wv[4] = {0.f,0.f,0.f,0.f};
        wv[i0] = probs[i0]/denom;
        wv[i1] = probs[i1]/denom;
        for(int e=0;e<4;e++) g_w[(long)n*4+e] = wv[e];
    }
}

// ---------------- host ----------------
extern "C" void kernel_launch(void* const* d_in, const int* in_sizes, int n_in,
                              void* d_out, int out_size)
{
    const float* x       = (const float*)d_in[0];
    const int*   ei      = (const int*)  d_in[1];
    const int*   batch   = (const int*)  d_in[2];
    const float* enc_W1  = (const float*)d_in[3];
    const float* enc_b1  = (const float*)d_in[4];
    const float* enc_W2  = (const float*)d_in[5];
    const float* enc_b2  = (const float*)d_in[6];
    const float* r_W1    = (const float*)d_in[7];
    const float* r_b1    = (const float*)d_in[8];
    const float* ln_g    = (const float*)d_in[9];
    const float* ln_b    = (const float*)d_in[10];
    const float* r_W2    = (const float*)d_in[11];
    const float* r_b2    = (const float*)d_in[12];
    const float* centers = (const float*)d_in[13];
    const float* W0_rel  = (const float*)d_in[14];
    const float* b0_rel  = (const float*)d_in[15];
    const float* W0_root = (const float*)d_in[16];
    const float* W1_rel  = (const float*)d_in[17];
    const float* b1_rel  = (const float*)d_in[18];
    const float* W1_root = (const float*)d_in[19];
    const float* W2_rel  = (const float*)d_in[20];
    const float* b2_rel  = (const float*)d_in[21];
    const float* W2_root = (const float*)d_in[22];
    const int* src = ei;
    const int* dst = ei + EE;
    float* out = (float*)d_out;

    float *p_h1,*p_h,*p_sf,*p_w,*p_wt,*p_zero;
    uint32_t *p_hp,*p_agg,*p_hE0,*p_hE1,*p_aggE;
    int *p_ncnt,*p_ecnt,*p_deg,*p_cur;
    __nv_bfloat16* p_wb;
    cudaGetSymbolAddress((void**)&p_h1,  g_h1);
    cudaGetSymbolAddress((void**)&p_h,   g_h);
    cudaGetSymbolAddress((void**)&p_hp,  g_hp);
    cudaGetSymbolAddress((void**)&p_agg, g_agg);
    cudaGetSymbolAddress((void**)&p_sf,  g_sf);
    cudaGetSymbolAddress((void**)&p_w,   g_w);
    cudaGetSymbolAddress((void**)&p_hE0, g_hE0);
    cudaGetSymbolAddress((void**)&p_hE1, g_hE1);
    cudaGetSymbolAddress((void**)&p_aggE,g_aggE);
    cudaGetSymbolAddress((void**)&p_ncnt,g_ncnt);
    cudaGetSymbolAddress((void**)&p_ecnt,g_ecnt);
    cudaGetSymbolAddress((void**)&p_deg, g_deg);
    cudaGetSymbolAddress((void**)&p_cur, g_cur);
    cudaGetSymbolAddress((void**)&p_wb,  g_wbuf);
    cudaGetSymbolAddress((void**)&p_wt,  g_wt);
    cudaGetSymbolAddress((void**)&p_zero,g_zero);

    cudaFuncSetAttribute(tgemm, cudaFuncAttributeMaxDynamicSharedMemorySize, SMEM_DYN);

    // ---- weight prep ----
    prep_wt<<<256,256>>>(enc_W2, p_wt);
    prep_wt<<<256,256>>>(r_W1,   p_wt + 65536);
    prep_wc<<<1024,256>>>(W0_rel,  p_wb + OFF_L0C);
    prep_wc<<<1024,256>>>(W0_root, p_wb + OFF_L0CR);
    prep_w<<<256,256>>>(W1_rel,  p_wb + OFF_L1,          256, 4, 65536, 262144);
    prep_w<<<256,256>>>(W1_root, p_wb + OFF_L1 + 131072, 256, 4, 65536, 262144);
    prep_w2c<<<1024,256>>>(W2_rel, W2_root, p_wb + OFF_L2);

    // ---- stats + CSR prep ----
    cudaMemsetAsync(p_ncnt, 0, GG*sizeof(int));
    cudaMemsetAsync(p_ecnt, 0, GG*sizeof(int));
    cudaMemsetAsync(p_deg,  0, NN*sizeof(int));
    cudaMemsetAsync(p_cur,  0, NN*sizeof(int));
    hist_nodes<<<196, 256>>>(batch);
    edge_prep<<<784, 256>>>(src, dst, batch);
    stats_kernel<<<1, GG>>>();
    sf_kernel<<<(NN+255)/256, 256>>>(batch);
    int nscan = (NN+1023)/1024;
    scan1<<<nscan, 1024>>>();
    scan2<<<1, 32>>>(nscan);
    scan3<<<(NN+255)/256, 256>>>();
    place_edges<<<784, 256>>>(src, dst);

    const int TGRIDX = (NN + TBM - 1) / TBM;
    const dim3 fgrid((NN + FBM - 1) / FBM, 4);

    // ---- encoder (exact-class: fused K=6 kernel, then 3xTF32 tensor with fused pack) ----
    enc1_kernel<<<NN, 256>>>(x, enc_W1, enc_b1, p_h1);
    tf32gemm<<<fgrid, 256>>>(p_h1, p_wt, enc_b2, p_h, p_hp, NN);

    // ---- router (3xTF32 main; K=3 sf correction fused into router kernel) ----
    tf32gemm<<<fgrid, 256>>>(p_h, p_wt + 65536, r_b1, p_h1, (uint32_t*)0, NN);
    router_kernel<<<NN, 256>>>(p_h1, batch, ln_g, ln_b, r_W2, r_b2, centers,
                               p_sf, r_W1 + HH*HH);

    // ---- aggregate h (packed) ----
    aggregate_pg<<<dim3(NN,1), 256>>>(p_hp, p_agg, 256, 0, 256, 0);

    // ---- expert layer 0: single batched GEMM, Nc=1024, output hE0 as [n][1024] ----
    {
        dim3 grid(TGRIDX, 1024 / TBN);
        tgemm<<<grid, 256, SMEM_DYN>>>(p_agg, 256, p_hp, 256,
                                       p_wb + OFF_L0C, p_wb + OFF_L0CR,
                                       b0_rel, (float*)p_hE0, 1024, NN, 1, 1, 0,
                                       (const float*)0, 0, (const uint32_t*)0);
    }
    // aggregate hE0 per expert: in [n][1024] col-block e*256, out aggE[e][n][256]
    aggregate_pg<<<dim3(NN,4), 256>>>(p_hE0, p_aggE, 1024, 256, 256, (long)NN*256);

    // ---- expert layer 1 (A1 = hE0 column block, lda 1024) ----
    for(int e=0;e<NEXP;e++){
        dim3 grid(TGRIDX, 256 / TBN);
        tgemm<<<grid, 256, SMEM_DYN>>>(p_aggE + (long)e*NN*HH, 256,
                                       p_hE0 + e*256, 1024,
                                       p_wb + OFF_L1 + (long)e*262144,
                                       p_wb + OFF_L1 + (long)e*262144 + 131072,
                                       b1_rel + e*HH, (float*)(p_hE1 + (long)e*NN*HH),
                                       HH, NN, 1, 1, 0,
                                       (const float*)0, 0, (const uint32_t*)0);
    }

    // ---- expert layer 2, merged: [t_e | root_e] = hE1 @ [W2_rel|W2_root] (Nc=256, packed) ----
    for(int e=0;e<NEXP;e++){
        dim3 grid(TGRIDX, 256 / TBN);
        tgemm<<<grid, 256, SMEM_DYN>>>(p_hE1 + (long)e*NN*HH, 256,
                                       (const uint32_t*)0, 0,
                                       p_wb + OFF_L2 + (long)e*131072, (const __nv_bfloat16*)0,
                                       p_zero, (float*)(p_aggE + (long)e*NN*HH),
                                       256, NN, 0, 1, 0,
                                       (const float*)0, 0, (const uint32_t*)0);
    }
    // ---- aggregate t_e + combine across experts -> out (no memset, no RMW) ----
    agg_combine<<<NN, OD>>>(p_aggE, p_w, b2_rel, out);
}

// round 15
// speedup vs baseline: 1.0790x; 1.0403x over previous
#include <cuda_runtime.h>
#include <cuda_bf16.h>
#include <stdint.h>
#include <math.h>

#define NN 50000
#define EE 800000
#define HH 256
#define GG 64
#define NEXP 4
#define OD 128

// ---------------- scratch (device globals: no allocation allowed) ----------------
__device__ __align__(16) float g_h1[NN*HH];
__device__ __align__(16) float g_h[NN*HH];
__device__ __align__(16) uint32_t g_hp[NN*HH];        // h packed hi/lo
__device__ __align__(16) uint32_t g_agg[NN*HH];       // aggregate(h) packed
__device__ __align__(16) float g_sf[NN*3];
__device__ __align__(16) float g_w[NN*NEXP];
__device__ __align__(16) uint32_t g_hE0[(long)NEXP*NN*HH];   // packed, used as [NN][1024]
__device__ __align__(16) uint32_t g_hE1[(long)NEXP*NN*HH];   // packed per-expert
__device__ __align__(16) uint32_t g_aggE[(long)NEXP*NN*HH];  // packed (aggE, then te|root)
__device__ int   g_deg[NN];
__device__ int   g_rowptr[NN+1];
__device__ int   g_cur[NN];
__device__ int   g_esrc[EE];
__device__ int   g_bsum[64];
__device__ int   g_ncnt[GG];
__device__ int   g_ecnt[GG];
__device__ float g_featsn[GG*3];
__device__ float g_lognn[GG];
__device__ float g_zero[HH];                          // stays zero
#define WBUF_ELEMS 2883584
__device__ __align__(16) __nv_bfloat16 g_wbuf[WBUF_ELEMS];
__device__ __align__(16) float g_wt[2*65536];         // fp32 W^T: enc_W2, r_W1[:256]

// wbuf layout (elements):
#define OFF_L0C   0        // L0 rel concat [1024][256] hi + lo (524288)
#define OFF_L0CR  524288   // L0 root concat (524288)
#define OFF_L1    1048576  // per-expert stride 262144 (rel hi/lo, root hi/lo at +131072)
#define OFF_L2    2097152  // per-expert stride 131072: concat [256][256] hi + lo at +65536

// ======================= helpers =======================
__device__ __forceinline__ uint32_t smem_u32(const void* p){
    uint32_t a;
    asm("{ .reg .u64 t; cvta.to.shared.u64 t, %1; cvt.u32.u64 %0, t; }" : "=r"(a) : "l"(p));
    return a;
}
__device__ __forceinline__ void ldm4(uint32_t* r, uint32_t addr){
    asm volatile("ldmatrix.sync.aligned.m8n8.x4.shared.b16 {%0,%1,%2,%3}, [%4];"
        : "=r"(r[0]), "=r"(r[1]), "=r"(r[2]), "=r"(r[3]) : "r"(addr));
}
__device__ __forceinline__ void mma16816(float* c, const uint32_t* a, const uint32_t* b){
    asm volatile("mma.sync.aligned.m16n8k16.row.col.f32.bf16.bf16.f32 "
        "{%0,%1,%2,%3}, {%4,%5,%6,%7}, {%8,%9}, {%0,%1,%2,%3};"
        : "+f"(c[0]), "+f"(c[1]), "+f"(c[2]), "+f"(c[3])
        : "r"(a[0]), "r"(a[1]), "r"(a[2]), "r"(a[3]), "r"(b[0]), "r"(b[1]));
}
__device__ __forceinline__ void mma_tf32(float* c, const uint32_t* a, const uint32_t* b){
    asm volatile("mma.sync.aligned.m16n8k8.row.col.f32.tf32.tf32.f32 "
        "{%0,%1,%2,%3}, {%4,%5,%6,%7}, {%8,%9}, {%0,%1,%2,%3};"
        : "+f"(c[0]), "+f"(c[1]), "+f"(c[2]), "+f"(c[3])
        : "r"(a[0]), "r"(a[1]), "r"(a[2]), "r"(a[3]), "r"(b[0]), "r"(b[1]));
}
__device__ __forceinline__ uint32_t f2tf(float f){
    uint32_t r;
    asm("cvt.rna.tf32.f32 %0, %1;" : "=r"(r) : "f"(f));
    return r;
}
__device__ __forceinline__ void tf_split(float f, uint32_t& hi, uint32_t& lo){
    hi = f2tf(f);
    lo = f2tf(f - __uint_as_float(hi));
}
__device__ __forceinline__ uint32_t pack_hilo(float v){
    __nv_bfloat16 h = __float2bfloat16(v);
    __nv_bfloat16 l = __float2bfloat16(v - __bfloat162float(h));
    return ((uint32_t)__bfloat16_as_ushort(h) << 16) | (uint32_t)__bfloat16_as_ushort(l);
}
__device__ __forceinline__ float unpack_hilo(uint32_t w){
    float h = __bfloat162float(__ushort_as_bfloat16((unsigned short)(w >> 16)));
    float l = __bfloat162float(__ushort_as_bfloat16((unsigned short)(w & 0xFFFFu)));
    return h + l;
}

// ======================= weight prep =======================
__global__ void prep_w(const float* __restrict__ srcp, __nv_bfloat16* __restrict__ dstp,
                       int Ncols, int nSeg, long sstr, long dstr){
    long total = (long)nSeg * Ncols * 256;
    long plane = (long)Ncols * 256;
    for (long i = (long)blockIdx.x*blockDim.x + threadIdx.x; i < total; i += (long)gridDim.x*blockDim.x){
        int k = (int)(i & 255);
        long t = i >> 8;
        int n = (int)(t % Ncols);
        int e = (int)(t / Ncols);
        float v = srcp[e*sstr + (long)k*Ncols + n];
        __nv_bfloat16 h = __float2bfloat16(v);
        float rem = v - __bfloat162float(h);
        dstp[e*dstr + (long)n*256 + k] = h;
        dstp[e*dstr + plane + (long)n*256 + k] = __float2bfloat16(rem);
    }
}

// L0 concat: fp32 [4][256][256] -> bf16 hi [1024][256] + lo plane at +262144
__global__ void prep_wc(const float* __restrict__ src, __nv_bfloat16* __restrict__ dst){
    int i = blockIdx.x*256 + threadIdx.x;       // 0..262143
    int k = i & 255;
    int t = i >> 8;
    int n = t & 255;
    int e = t >> 8;
    float v = src[e*65536 + k*256 + n];
    __nv_bfloat16 h = __float2bfloat16(v);
    long d = ((long)(e*256 + n))*256 + k;
    dst[d] = h;
    dst[262144 + d] = __float2bfloat16(v - __bfloat162float(h));
}

// L2 concat per expert: [W2_rel | W2_root] -> bf16 hi [256][256] + lo at +65536, stride 131072
__global__ void prep_w2c(const float* __restrict__ rel, const float* __restrict__ root,
                         __nv_bfloat16* __restrict__ dst){
    int i = blockIdx.x*256 + threadIdx.x;       // 0..262143 (4 experts x 256 n x 256 k)
    int k = i & 255;
    int t = i >> 8;
    int n = t & 255;
    int e = t >> 8;
    float v = (n < 128) ? rel[e*32768 + k*128 + n] : root[e*32768 + k*128 + (n-128)];
    __nv_bfloat16 h = __float2bfloat16(v);
    long d = (long)e*131072 + (long)n*256 + k;
    dst[d] = h;
    dst[d + 65536] = __float2bfloat16(v - __bfloat162float(h));
}

// fp32 [256,256] row-major -> transposed [N][K]
__global__ void prep_wt(const float* __restrict__ src, float* __restrict__ dst){
    int i = blockIdx.x*256 + threadIdx.x;
    int k = i >> 8, n = i & 255;
    dst[(long)n*256 + k] = src[(long)k*256 + n];
}

// ======================= encoder layer 1: h1 = relu(xs @ W1 + b1), K=6 exact fp32 =======================
__global__ void enc1_kernel(const float* __restrict__ x, const float* __restrict__ W1,
                            const float* __restrict__ b1, float* __restrict__ out){
    int n = blockIdx.x;
    __shared__ float xs[6];
    if (threadIdx.x < 6) xs[threadIdx.x] = x[n*16 + 4 + threadIdx.x];
    __syncthreads();
    float acc = 0.f;
#pragma unroll
    for (int k = 0; k < 6; ++k)
        acc += xs[k] * W1[k*HH + threadIdx.x];
    acc += b1[threadIdx.x];
    out[(long)n*HH + threadIdx.x] = fmaxf(acc, 0.f);
}

// ======================= 3-term tf32 GEMM (fp32-exact class) =======================
#define FBM 128
#define FAS 20
__global__ void __launch_bounds__(256) tf32gemm(
    const float* __restrict__ A, const float* __restrict__ Bt,
    const float* __restrict__ bias, float* __restrict__ C,
    uint32_t* __restrict__ Cp, int M)
{
    __shared__ float As[2][128*FAS];
    __shared__ float Bs[2][64*FAS];
    const int tid = threadIdx.x;
    const int wid = tid >> 5, lane = tid & 31;
    const int wr = wid >> 1, wc = wid & 1;
    const int bm = blockIdx.x * FBM, bn = blockIdx.y * 64;
    const int fr = lane >> 2, fc = lane & 3;

    float acc[2][4][4];
#pragma unroll
    for (int i = 0; i < 2; ++i)
#pragma unroll
        for (int j = 0; j < 4; ++j)
#pragma unroll
            for (int q = 0; q < 4; ++q) acc[i][j][q] = 0.f;

    float ar[8];
    float4 br;
    const int arow = tid >> 1, ac8 = (tid & 1) * 8;
    const int bnr = tid >> 2, bk4 = (tid & 3) * 4;

    auto ldg = [&](int ch){
        int k0 = ch * 16;
        int gr = bm + arow;
        if (gr < M){
            const float* ap = A + (long)gr*256 + k0 + ac8;
            float4 f0 = *(const float4*)ap;
            float4 f1 = *(const float4*)(ap + 4);
            ar[0]=f0.x; ar[1]=f0.y; ar[2]=f0.z; ar[3]=f0.w;
            ar[4]=f1.x; ar[5]=f1.y; ar[6]=f1.z; ar[7]=f1.w;
        } else {
#pragma unroll
            for (int q = 0; q < 8; ++q) ar[q] = 0.f;
        }
        br = *(const float4*)(Bt + (long)(bn + bnr)*256 + k0 + bk4);
    };
    auto sts = [&](int buf){
        float* pa = &As[buf][arow*FAS + ac8];
#pragma unroll
        for (int q = 0; q < 8; ++q) pa[q] = ar[q];
        float* pb = &Bs[buf][bnr*FAS + bk4];
        pb[0]=br.x; pb[1]=br.y; pb[2]=br.z; pb[3]=br.w;
    };
    auto compute = [&](int buf){
#pragma unroll
        for (int ks = 0; ks < 2; ++ks){
            int kk = ks * 8;
            uint32_t ah[2][4], al[2][4];
#pragma unroll
            for (int mt = 0; mt < 2; ++mt){
                int r0 = wr*32 + mt*16 + fr;
                float f0 = As[buf][r0*FAS + kk + fc];
                float f1 = As[buf][(r0+8)*FAS + kk + fc];
                float f2 = As[buf][r0*FAS + kk + fc + 4];
                float f3 = As[buf][(r0+8)*FAS + kk + fc + 4];
                tf_split(f0, ah[mt][0], al[mt][0]);
                tf_split(f1, ah[mt][1], al[mt][1]);
                tf_split(f2, ah[mt][2], al[mt][2]);
                tf_split(f3, ah[mt][3], al[mt][3]);
            }
#pragma unroll
            for (int nt = 0; nt < 4; ++nt){
                int n0 = wc*32 + nt*8 + fr;
                float g0 = Bs[buf][n0*FAS + kk + fc];
                float g1 = Bs[buf][n0*FAS + kk + fc + 4];
                uint32_t bh[2], bl[2];
                tf_split(g0, bh[0], bl[0]);
                tf_split(g1, bh[1], bl[1]);
#pragma unroll
                for (int mt = 0; mt < 2; ++mt){
                    mma_tf32(acc[mt][nt], ah[mt], bh);
                    mma_tf32(acc[mt][nt], al[mt], bh);
                    mma_tf32(acc[mt][nt], ah[mt], bl);
                }
            }
        }
    };

    ldg(0); sts(0); __syncthreads();
    for (int c = 0; c < 16; ++c){
        if (c + 1 < 16) ldg(c + 1);
        compute(c & 1);
        if (c + 1 < 16){ sts((c + 1) & 1); __syncthreads(); }
    }

#pragma unroll
    for (int mt = 0; mt < 2; ++mt){
#pragma unroll
        for (int nt = 0; nt < 4; ++nt){
            int row0 = bm + wr*32 + mt*16 + fr;
            int col  = bn + wc*32 + nt*8 + fc*2;
            float b0 = bias[col];
            float b1 = bias[col + 1];
#pragma unroll
            for (int half = 0; half < 2; ++half){
                int row = row0 + half*8;
                if (row < M){
                    float2 o;
                    o.x = acc[mt][nt][half*2 + 0] + b0;
                    o.y = acc[mt][nt][half*2 + 1] + b1;
                    *(float2*)(C + (long)row*256 + col) = o;
                    if (Cp){
                        uint2 po;
                        po.x = pack_hilo(o.x);
                        po.y = pack_hilo(o.y);
                        *(uint2*)(Cp + (long)row*256 + col) = po;
                    }
                }
            }
        }
    }
}

// ======================= mma.sync split-bf16 dual GEMM, 128x64 tile, expert-batched =======================
#define TBM 128
#define TBN 64
#define TBK 32
#define ARS 80
#define AS_PLANE 10240
#define AS_STAGE 20480
#define BS_PLANE 5120
#define BS_STAGE 10240
#define BS_OFF   40960
#define SMEM_DYN 61440

__global__ void __launch_bounds__(256) tgemm(
    const uint32_t* __restrict__ A0, int lda0,
    const uint32_t* __restrict__ A1, int lda1,
    const __nv_bfloat16* __restrict__ B0, const __nv_bfloat16* __restrict__ B1,
    const float* __restrict__ bias, float* __restrict__ C,
    int Nc, int M, int relu, int out_packed, int accum,
    const float* __restrict__ rowscale, int rs_stride,
    const uint32_t* __restrict__ addin,
    long a0_es, long a1_es, long b_es, long bias_es, long c_es)
{
    extern __shared__ char dsm[];
    const uint32_t sbase = smem_u32(dsm);

    // expert offset via blockIdx.z
    {
        long ex = (long)blockIdx.z;
        A0 += ex * a0_es;
        if (A1) A1 += ex * a1_es;
        B0 += ex * b_es;
        if (B1) B1 += ex * b_es;
        bias += ex * bias_es;
        C += ex * c_es;
    }

    const int tid  = threadIdx.x;
    const int wid  = tid >> 5;
    const int lane = tid & 31;
    const int wr   = wid >> 1;
    const int wc   = wid & 1;
    const int bm   = blockIdx.x * TBM;
    const int bn   = blockIdx.y * TBN;

    const int nch = (A1 != 0) ? 16 : 8;
    const long bplane = (long)Nc * 256;

    float acc[2][4][4];
#pragma unroll
    for (int i = 0; i < 2; ++i)
#pragma unroll
        for (int j = 0; j < 4; ++j)
#pragma unroll
            for (int q = 0; q < 4; ++q) acc[i][j][q] = 0.f;

    uint32_t aw[16];
    uint4 bh, bl;
    const int arow_g = tid >> 1;
    const int acol_g = (tid & 1) * 16;
    const int brow_g = tid >> 2;
    const int bcol_g = (tid & 3) * 8;

    auto ldg_chunk = [&](int c){
        int seg = c >> 3;
        int k0  = (c & 7) * TBK;
        const uint32_t* A = seg ? A1 : A0;
        const int lda = seg ? lda1 : lda0;
        int gr = bm + arow_g;
        if (gr < M){
            const uint32_t* ap = A + (long)gr*lda + k0 + acol_g;
            uint4 u0 = *(const uint4*)ap;
            uint4 u1 = *(const uint4*)(ap + 4);
            uint4 u2 = *(const uint4*)(ap + 8);
            uint4 u3 = *(const uint4*)(ap + 12);
            aw[0]=u0.x; aw[1]=u0.y; aw[2]=u0.z; aw[3]=u0.w;
            aw[4]=u1.x; aw[5]=u1.y; aw[6]=u1.z; aw[7]=u1.w;
            aw[8]=u2.x; aw[9]=u2.y; aw[10]=u2.z; aw[11]=u2.w;
            aw[12]=u3.x; aw[13]=u3.y; aw[14]=u3.z; aw[15]=u3.w;
        } else {
#pragma unroll
            for (int q = 0; q < 16; ++q) aw[q] = 0u;
        }
        const __nv_bfloat16* B = seg ? B1 : B0;
        const __nv_bfloat16* bp = B + (long)(bn + brow_g)*256 + k0 + bcol_g;
        bh = *(const uint4*)bp;
        bl = *(const uint4*)(bp + bplane);
    };

    auto sts_chunk = [&](int buf){
        uint32_t hh[8], ll[8];
#pragma unroll
        for (int q = 0; q < 8; ++q){
            hh[q] = __byte_perm(aw[2*q], aw[2*q+1], 0x7632);
            ll[q] = __byte_perm(aw[2*q], aw[2*q+1], 0x5410);
        }
        char* pa = dsm + buf*AS_STAGE + arow_g*ARS + acol_g*2;
        *(uint4*)pa        = make_uint4(hh[0], hh[1], hh[2], hh[3]);
        *(uint4*)(pa + 16) = make_uint4(hh[4], hh[5], hh[6], hh[7]);
        *(uint4*)(pa + AS_PLANE)      = make_uint4(ll[0], ll[1], ll[2], ll[3]);
        *(uint4*)(pa + AS_PLANE + 16) = make_uint4(ll[4], ll[5], ll[6], ll[7]);
        char* pb = dsm + BS_OFF + buf*BS_STAGE + brow_g*ARS + bcol_g*2;
        *(uint4*)pb              = bh;
        *(uint4*)(pb + BS_PLANE) = bl;
    };

    const int tile = lane >> 3;
    const int trr  = lane & 7;
    const int arow = wr*32 + ((tile & 1) << 3) + trr;
    const int akk0 = ((tile & 2) << 2);
    const int brow = wc*32 + ((tile & 2) << 2) + trr;
    const int bkk0 = ((tile & 1) << 3);

    auto compute = [&](int buf){
        uint32_t aBase = sbase + (uint32_t)buf*AS_STAGE;
        uint32_t bBase = sbase + BS_OFF + (uint32_t)buf*BS_STAGE;
#pragma unroll
        for (int kt = 0; kt < 2; ++kt){
            uint32_t a_hi[2][4], a_lo[2][4], bb[2][4];
            uint32_t ak = (uint32_t)(akk0 + kt*16)*2;
            uint32_t bk = (uint32_t)(bkk0 + kt*16)*2;
            ldm4(a_hi[0], aBase + (uint32_t)(arow)*ARS + ak);
            ldm4(a_hi[1], aBase + (uint32_t)(arow+16)*ARS + ak);
            ldm4(bb[0],   bBase + (uint32_t)(brow)*ARS + bk);
            ldm4(bb[1],   bBase + (uint32_t)(brow+16)*ARS + bk);
#pragma unroll
            for (int mt = 0; mt < 2; ++mt)
#pragma unroll
                for (int nt = 0; nt < 4; ++nt)
                    mma16816(acc[mt][nt], a_hi[mt], &bb[nt>>1][(nt&1)*2]);
            ldm4(a_lo[0], aBase + AS_PLANE + (uint32_t)(arow)*ARS + ak);
            ldm4(a_lo[1], aBase + AS_PLANE + (uint32_t)(arow+16)*ARS + ak);
#pragma unroll
            for (int mt = 0; mt < 2; ++mt)
#pragma unroll
                for (int nt = 0; nt < 4; ++nt)
                    mma16816(acc[mt][nt], a_lo[mt], &bb[nt>>1][(nt&1)*2]);
            ldm4(bb[0],   bBase + BS_PLANE + (uint32_t)(brow)*ARS + bk);
            ldm4(bb[1],   bBase + BS_PLANE + (uint32_t)(brow+16)*ARS + bk);
#pragma unroll
            for (int mt = 0; mt < 2; ++mt)
#pragma unroll
                for (int nt = 0; nt < 4; ++nt)
                    mma16816(acc[mt][nt], a_hi[mt], &bb[nt>>1][(nt&1)*2]);
        }
    };

    ldg_chunk(0);
    sts_chunk(0);
    __syncthreads();
    for (int c = 0; c < nch; ++c){
        if (c + 1 < nch) ldg_chunk(c + 1);
        compute(c & 1);
        if (c + 1 < nch){
            sts_chunk((c + 1) & 1);
            __syncthreads();
        }
    }

#pragma unroll
    for (int mt = 0; mt < 2; ++mt){
#pragma unroll
        for (int nt = 0; nt < 4; ++nt){
            int row0 = bm + wr*32 + mt*16 + (lane >> 2);
            int col  = bn + wc*32 + nt*8 + (lane & 3)*2;
            float b0 = bias[col];
            float b1 = bias[col + 1];
#pragma unroll
            for (int half = 0; half < 2; ++half){
                int row = row0 + half*8;
                if (row < M){
                    float v0 = acc[mt][nt][half*2 + 0] + b0;
                    float v1 = acc[mt][nt][half*2 + 1] + b1;
                    if (relu){ v0 = fmaxf(v0, 0.f); v1 = fmaxf(v1, 0.f); }
                    if (out_packed){
                        uint2 o;
                        o.x = pack_hilo(v0);
                        o.y = pack_hilo(v1);
                        *(uint2*)((uint32_t*)C + (long)row*Nc + col) = o;
                    } else {
                        if (addin){
                            uint2 ai = *(const uint2*)(addin + (long)row*Nc + col);
                            v0 += unpack_hilo(ai.x);
                            v1 += unpack_hilo(ai.y);
                        }
                        if (rowscale){
                            float rs = rowscale[(long)row*rs_stride];
                            v0 *= rs; v1 *= rs;
                        }
                        float* cp = C + (long)row*Nc + col;
                        if (accum){ v0 += cp[0]; v1 += cp[1]; }
                        float2 o; o.x = v0; o.y = v1;
                        *(float2*)cp = o;
                    }
                }
            }
        }
    }
}

// ---------------- histograms ----------------
__global__ void hist_nodes(const int* __restrict__ batch){
    __shared__ int s[GG];
    if(threadIdx.x < GG) s[threadIdx.x] = 0;
    __syncthreads();
    for(int i = blockIdx.x*blockDim.x + threadIdx.x; i < NN; i += gridDim.x*blockDim.x)
        atomicAdd(&s[batch[i]], 1);
    __syncthreads();
    if(threadIdx.x < GG && s[threadIdx.x]) atomicAdd(&g_ncnt[threadIdx.x], s[threadIdx.x]);
}

__global__ void edge_prep(const int* __restrict__ src, const int* __restrict__ dst,
                          const int* __restrict__ batch){
    __shared__ int s[GG];
    if(threadIdx.x < GG) s[threadIdx.x] = 0;
    __syncthreads();
    for(int i = blockIdx.x*blockDim.x + threadIdx.x; i < EE; i += gridDim.x*blockDim.x){
        atomicAdd(&s[batch[src[i]]], 1);
        atomicAdd(&g_deg[dst[i]], 1);
    }
    __syncthreads();
    if(threadIdx.x < GG && s[threadIdx.x]) atomicAdd(&g_ecnt[threadIdx.x], s[threadIdx.x]);
}

// ---------------- graph stats ----------------
__global__ void stats_kernel(){
    int g = threadIdx.x;
    float n   = fmaxf((float)g_ncnt[g], 1.f);
    float e   = (float)g_ecnt[g];
    float den = e / fmaxf(n*(n-1.f), 1.f);
    float ln  = logf(n);
    __shared__ float sn[GG], se[GG], sd[GG], sl[GG];
    sn[g]=n; se[g]=e; sd[g]=den; sl[g]=ln;
    __syncthreads();
    __shared__ float sc[8];
    if(g == 0){
        float mn=sl[0], mx=sl[0], s0=0, s1=0, s2=0;
        for(int i=0;i<GG;i++){ mn=fminf(mn,sl[i]); mx=fmaxf(mx,sl[i]); s0+=sn[i]; s1+=se[i]; s2+=sd[i]; }
        float m0=s0/GG, m1=s1/GG, m2=s2/GG;
        float q0=0,q1=0,q2=0;
        for(int i=0;i<GG;i++){
            float d0=sn[i]-m0, d1=se[i]-m1, d2=sd[i]-m2;
            q0+=d0*d0; q1+=d1*d1; q2+=d2*d2;
        }
        sc[0]=mn; sc[1]=mx; sc[2]=m0; sc[3]=m1; sc[4]=m2;
        sc[5]=sqrtf(q0/GG); sc[6]=sqrtf(q1/GG); sc[7]=sqrtf(q2/GG);
    }
    __syncthreads();
    g_lognn[g]       = (ln  - sc[0])/(sc[1]-sc[0]+1e-6f);
    g_featsn[g*3+0]  = (n   - sc[2])/(sc[5]+1e-6f);
    g_featsn[g*3+1]  = (e   - sc[3])/(sc[6]+1e-6f);
    g_featsn[g*3+2]  = (den - sc[4])/(sc[7]+1e-6f);
}

__global__ void sf_kernel(const int* __restrict__ batch){
    int i = blockIdx.x*blockDim.x + threadIdx.x;
    if(i < NN){
        int g = batch[i];
        g_sf[i*3+0] = g_featsn[g*3+0];
        g_sf[i*3+1] = g_featsn[g*3+1];
        g_sf[i*3+2] = g_featsn[g*3+2];
    }
}

// ---------------- CSR build ----------------
__global__ void scan1(){
    __shared__ int sh[1024];
    int i = blockIdx.x*1024 + threadIdx.x;
    int v = (i < NN) ? g_deg[i] : 0;
    sh[threadIdx.x] = v;
    __syncthreads();
    for(int off=1; off<1024; off<<=1){
        int t = sh[threadIdx.x];
        if(threadIdx.x >= off) t += sh[threadIdx.x - off];
        __syncthreads();
        sh[threadIdx.x] = t;
        __syncthreads();
    }
    if(i < NN) g_rowptr[i] = sh[threadIdx.x] - v;
    if(threadIdx.x == 1023) g_bsum[blockIdx.x] = sh[1023];
}

__global__ void scan2(int nb){
    if(threadIdx.x == 0){
        int run = 0;
        for(int b=0;b<nb;b++){ int v=g_bsum[b]; g_bsum[b]=run; run+=v; }
    }
}

__global__ void scan3(){
    int i = blockIdx.x*blockDim.x + threadIdx.x;
    if(i < NN) g_rowptr[i] += g_bsum[i >> 10];
    if(i == 0) g_rowptr[NN] = EE;
}

__global__ void place_edges(const int* __restrict__ src, const int* __restrict__ dst){
    for(int i = blockIdx.x*blockDim.x + threadIdx.x; i < EE; i += gridDim.x*blockDim.x){
        int d = dst[i];
        int idx = g_rowptr[d] + atomicAdd(&g_cur[d], 1);
        g_esrc[idx] = src[i];
    }
}

// ---------------- CSR gather aggregation (packed, grouped) ----------------
__global__ void aggregate_pg(const uint32_t* __restrict__ in, uint32_t* __restrict__ out,
                             int Win, long in_goff, int Wout, long out_goff){
    int n = blockIdx.x;
    const uint32_t* ip = in + (long)blockIdx.y * in_goff;
    uint32_t* op = out + (long)blockIdx.y * out_goff;
    int s0 = g_rowptr[n], s1 = g_rowptr[n+1];
    float a0=0.f, a1=0.f, a2=0.f, a3=0.f, a4=0.f, a5=0.f, a6=0.f, a7=0.f;
    int j = s0;
    for(; j + 8 <= s1; j += 8){
        int i0 = g_esrc[j],   i1 = g_esrc[j+1], i2 = g_esrc[j+2], i3 = g_esrc[j+3];
        int i4 = g_esrc[j+4], i5 = g_esrc[j+5], i6 = g_esrc[j+6], i7 = g_esrc[j+7];
        a0 += unpack_hilo(ip[(long)i0*Win + threadIdx.x]);
        a1 += unpack_hilo(ip[(long)i1*Win + threadIdx.x]);
        a2 += unpack_hilo(ip[(long)i2*Win + threadIdx.x]);
        a3 += unpack_hilo(ip[(long)i3*Win + threadIdx.x]);
        a4 += unpack_hilo(ip[(long)i4*Win + threadIdx.x]);
        a5 += unpack_hilo(ip[(long)i5*Win + threadIdx.x]);
        a6 += unpack_hilo(ip[(long)i6*Win + threadIdx.x]);
        a7 += unpack_hilo(ip[(long)i7*Win + threadIdx.x]);
    }
    for(; j < s1; ++j)
        a0 += unpack_hilo(ip[(long)g_esrc[j]*Win + threadIdx.x]);
    op[(long)n*Wout + threadIdx.x] = pack_hilo(((a0 + a1) + (a2 + a3)) + ((a4 + a5) + (a6 + a7)));
}

// ---------------- final: aggregate t_e + combine across experts ----------------
// te buffers: per expert at te + e*NN*256, row layout [256]: cols 0-127 t_e, 128-255 root
__global__ void agg_combine(const uint32_t* __restrict__ te, const float* __restrict__ w,
                            const float* __restrict__ b2, float* __restrict__ out){
    int n = blockIdx.x;
    int c = threadIdx.x;          // 0..127
    int s0 = g_rowptr[n], s1 = g_rowptr[n+1];
    float res = 0.f;
#pragma unroll
    for (int e = 0; e < NEXP; ++e){
        const uint32_t* tp = te + (long)e*NN*256;
        float a0=0.f, a1=0.f, a2=0.f, a3=0.f;
        int j = s0;
        for(; j + 4 <= s1; j += 4){
            int i0 = g_esrc[j], i1 = g_esrc[j+1], i2 = g_esrc[j+2], i3 = g_esrc[j+3];
            a0 += unpack_hilo(tp[(long)i0*256 + c]);
            a1 += unpack_hilo(tp[(long)i1*256 + c]);
            a2 += unpack_hilo(tp[(long)i2*256 + c]);
            a3 += unpack_hilo(tp[(long)i3*256 + c]);
        }
        for(; j < s1; ++j)
            a0 += unpack_hilo(tp[(long)g_esrc[j]*256 + c]);
        float agg = (a0 + a1) + (a2 + a3);
        float root = unpack_hilo(tp[(long)n*256 + 128 + c]);
        res += w[n*NEXP + e] * (agg + root + b2[e*OD + c]);
    }
    out[(long)n*OD + c] = res;
}

// ---------------- router (with fused K=3 sf correction) ----------------
__global__ void router_kernel(const float* __restrict__ t, const int* __restrict__ batch,
                              const float* __restrict__ lng, const float* __restrict__ lnb,
                              const float* __restrict__ W2, const float* __restrict__ b2,
                              const float* __restrict__ centers,
                              const float* __restrict__ sf, const float* __restrict__ W1s)
{
    int n = blockIdx.x; int tid = threadIdx.x;
    int lane = tid & 31, wid = tid >> 5;
    float s0f = sf[n*3+0], s1f = sf[n*3+1], s2f = sf[n*3+2];
    float v = t[(long)n*HH + tid]
            + s0f * W1s[tid] + s1f * W1s[HH + tid] + s2f * W1s[2*HH + tid];
    float s = v, sq = v*v;
#pragma unroll
    for(int o=16;o>0;o>>=1){
        s  += __shfl_down_sync(0xffffffffu, s,  o);
        sq += __shfl_down_sync(0xffffffffu, sq, o);
    }
    __shared__ float red[8*2];
    __shared__ float red4[8*4];
    __shared__ float bc[2];
    if(lane == 0){ red[wid*2]=s; red[wid*2+1]=sq; }
    __syncthreads();
    if(tid == 0){
        float S=0, Q=0;
        for(int w=0;w<8;w++){ S+=red[w*2]; Q+=red[w*2+1]; }
        float mean = S/HH;
        bc[0]=mean; bc[1]=Q/HH - mean*mean;
    }
    __syncthreads();
    float mean = bc[0], var = bc[1];
    float r = (v - mean)*rsqrtf(var + 1e-5f)*lng[tid] + lnb[tid];
    r = fmaxf(r, 0.f);
    float p[4];
#pragma unroll
    for(int e=0;e<4;e++) p[e] = r * W2[tid*4+e];
#pragma unroll
    for(int o=16;o>0;o>>=1)
#pragma unroll
        for(int e=0;e<4;e++) p[e] += __shfl_down_sync(0xffffffffu, p[e], o);
    if(lane == 0)
        for(int e=0;e<4;e++) red4[wid*4+e] = p[e];
    __syncthreads();
    if(tid == 0){
        float logit[4], probs[4];
        float lnode = g_lognn[batch[n]];
        for(int e=0;e<4;e++){
            float sum = 0;
            for(int w=0;w<8;w++) sum += red4[w*4+e];
            float learned = sum + b2[e];
            float d = lnode - centers[e];
            logit[e] = 0.7f*learned - 0.3f*d*d;
        }
        float mx = logit[0];
        for(int e=1;e<4;e++) mx = fmaxf(mx, logit[e]);
        float ssum = 0;
        for(int e=0;e<4;e++){ probs[e] = expf(logit[e]-mx); ssum += probs[e]; }
        for(int e=0;e<4;e++) probs[e] /= ssum;
        int i0 = 0;
        for(int e=1;e<4;e++) if(probs[e] > probs[i0]) i0 = e;
        int i1 = -1;
        for(int e=0;e<4;e++){
            if(e == i0) continue;
            if(i1 < 0 || probs[e] > probs[i1]) i1 = e;
        }
        float denom = probs[i0] + probs[i1] + 1e-8f;
        float wv[4] = {0.f,0.f,0.f,0.f};
        wv[i0] = probs[i0]/denom;
        wv[i1] = probs[i1]/denom;
        for(int e=0;e<4;e++) g_w[(long)n*4+e] = wv[e];
    }
}

// ---------------- host ----------------
extern "C" void kernel_launch(void* const* d_in, const int* in_sizes, int n_in,
                              void* d_out, int out_size)
{
    const float* x       = (const float*)d_in[0];
    const int*   ei      = (const int*)  d_in[1];
    const int*   batch   = (const int*)  d_in[2];
    const float* enc_W1  = (const float*)d_in[3];
    const float* enc_b1  = (const float*)d_in[4];
    const float* enc_W2  = (const float*)d_in[5];
    const float* enc_b2  = (const float*)d_in[6];
    const float* r_W1    = (const float*)d_in[7];
    const float* r_b1    = (const float*)d_in[8];
    const float* ln_g    = (const float*)d_in[9];
    const float* ln_b    = (const float*)d_in[10];
    const float* r_W2    = (const float*)d_in[11];
    const float* r_b2    = (const float*)d_in[12];
    const float* centers = (const float*)d_in[13];
    const float* W0_rel  = (const float*)d_in[14];
    const float* b0_rel  = (const float*)d_in[15];
    const float* W0_root = (const float*)d_in[16];
    const float* W1_rel  = (const float*)d_in[17];
    const float* b1_rel  = (const float*)d_in[18];
    const float* W1_root = (const float*)d_in[19];
    const float* W2_rel  = (const float*)d_in[20];
    const float* b2_rel  = (const float*)d_in[21];
    const float* W2_root = (const float*)d_in[22];
    const int* src = ei;
    const int* dst = ei + EE;
    float* out = (float*)d_out;

    float *p_h1,*p_h,*p_sf,*p_w,*p_wt,*p_zero;
    uint32_t *p_hp,*p_agg,*p_hE0,*p_hE1,*p_aggE;
    int *p_ncnt,*p_ecnt,*p_deg,*p_cur;
    __nv_bfloat16* p_wb;
    cudaGetSymbolAddress((void**)&p_h1,  g_h1);
    cudaGetSymbolAddress((void**)&p_h,   g_h);
    cudaGetSymbolAddress((void**)&p_hp,  g_hp);
    cudaGetSymbolAddress((void**)&p_agg, g_agg);
    cudaGetSymbolAddress((void**)&p_sf,  g_sf);
    cudaGetSymbolAddress((void**)&p_w,   g_w);
    cudaGetSymbolAddress((void**)&p_hE0, g_hE0);
    cudaGetSymbolAddress((void**)&p_hE1, g_hE1);
    cudaGetSymbolAddress((void**)&p_aggE,g_aggE);
    cudaGetSymbolAddress((void**)&p_ncnt,g_ncnt);
    cudaGetSymbolAddress((void**)&p_ecnt,g_ecnt);
    cudaGetSymbolAddress((void**)&p_deg, g_deg);
    cudaGetSymbolAddress((void**)&p_cur, g_cur);
    cudaGetSymbolAddress((void**)&p_wb,  g_wbuf);
    cudaGetSymbolAddress((void**)&p_wt,  g_wt);
    cudaGetSymbolAddress((void**)&p_zero,g_zero);

    cudaFuncSetAttribute(tgemm, cudaFuncAttributeMaxDynamicSharedMemorySize, SMEM_DYN);

    // ---- weight prep ----
    prep_wt<<<256,256>>>(enc_W2, p_wt);
    prep_wt<<<256,256>>>(r_W1,   p_wt + 65536);
    prep_wc<<<1024,256>>>(W0_rel,  p_wb + OFF_L0C);
    prep_wc<<<1024,256>>>(W0_root, p_wb + OFF_L0CR);
    prep_w<<<256,256>>>(W1_rel,  p_wb + OFF_L1,          256, 4, 65536, 262144);
    prep_w<<<256,256>>>(W1_root, p_wb + OFF_L1 + 131072, 256, 4, 65536, 262144);
    prep_w2c<<<1024,256>>>(W2_rel, W2_root, p_wb + OFF_L2);

    // ---- stats + CSR prep ----
    cudaMemsetAsync(p_ncnt, 0, GG*sizeof(int));
    cudaMemsetAsync(p_ecnt, 0, GG*sizeof(int));
    cudaMemsetAsync(p_deg,  0, NN*sizeof(int));
    cudaMemsetAsync(p_cur,  0, NN*sizeof(int));
    hist_nodes<<<196, 256>>>(batch);
    edge_prep<<<784, 256>>>(src, dst, batch);
    stats_kernel<<<1, GG>>>();
    sf_kernel<<<(NN+255)/256, 256>>>(batch);
    int nscan = (NN+1023)/1024;
    scan1<<<nscan, 1024>>>();
    scan2<<<1, 32>>>(nscan);
    scan3<<<(NN+255)/256, 256>>>();
    place_edges<<<784, 256>>>(src, dst);

    const int TGRIDX = (NN + TBM - 1) / TBM;
    const dim3 fgrid((NN + FBM - 1) / FBM, 4);

    // ---- encoder (exact-class: fused K=6 kernel, then 3xTF32 tensor with fused pack) ----
    enc1_kernel<<<NN, 256>>>(x, enc_W1, enc_b1, p_h1);
    tf32gemm<<<fgrid, 256>>>(p_h1, p_wt, enc_b2, p_h, p_hp, NN);

    // ---- router (3xTF32 main; K=3 sf correction fused into router kernel) ----
    tf32gemm<<<fgrid, 256>>>(p_h, p_wt + 65536, r_b1, p_h1, (uint32_t*)0, NN);
    router_kernel<<<NN, 256>>>(p_h1, batch, ln_g, ln_b, r_W2, r_b2, centers,
                               p_sf, r_W1 + HH*HH);

    // ---- aggregate h (packed) ----
    aggregate_pg<<<dim3(NN,1), 256>>>(p_hp, p_agg, 256, 0, 256, 0);

    // ---- expert layer 0: single batched GEMM, Nc=1024, output hE0 as [n][1024] ----
    {
        dim3 grid(TGRIDX, 1024 / TBN, 1);
        tgemm<<<grid, 256, SMEM_DYN>>>(p_agg, 256, p_hp, 256,
                                       p_wb + OFF_L0C, p_wb + OFF_L0CR,
                                       b0_rel, (float*)p_hE0, 1024, NN, 1, 1, 0,
                                       (const float*)0, 0, (const uint32_t*)0,
                                       0, 0, 0, 0, 0);
    }
    // aggregate hE0 per expert: in [n][1024] col-block e*256, out aggE[e][n][256]
    aggregate_pg<<<dim3(NN,4), 256>>>(p_hE0, p_aggE, 1024, 256, 256, (long)NN*256);

    // ---- expert layer 1: one batched launch over 4 experts (blockIdx.z) ----
    {
        dim3 grid(TGRIDX, 256 / TBN, NEXP);
        tgemm<<<grid, 256, SMEM_DYN>>>(p_aggE, 256,
                                       p_hE0, 1024,
                                       p_wb + OFF_L1,
                                       p_wb + OFF_L1 + 131072,
                                       b1_rel, (float*)p_hE1,
                                       HH, NN, 1, 1, 0,
                                       (const float*)0, 0, (const uint32_t*)0,
                                       (long)NN*HH, 256, 262144, HH, (long)NN*HH);
    }

    // ---- expert layer 2, merged, batched: [t_e | root_e] = hE1 @ [W2_rel|W2_root] ----
    {
        dim3 grid(TGRIDX, 256 / TBN, NEXP);
        tgemm<<<grid, 256, SMEM_DYN>>>(p_hE1, 256,
                                       (const uint32_t*)0, 0,
                                       p_wb + OFF_L2, (const __nv_bfloat16*)0,
                                       p_zero, (float*)p_aggE,
                                       256, NN, 0, 1, 0,
                                       (const float*)0, 0, (const uint32_t*)0,
                                       (long)NN*HH, 0, 131072, 0, (long)NN*HH);
    }
    // ---- aggregate t_e + combine across experts -> out (no memset, no RMW) ----
    agg_combine<<<NN, OD>>>(p_aggE, p_w, b2_rel, out);
}

// round 16
// speedup vs baseline: 1.0811x; 1.0019x over previous
#include <cuda_runtime.h>
#include <cuda_bf16.h>
#include <stdint.h>
#include <math.h>

#define NN 50000
#define EE 800000
#define HH 256
#define GG 64
#define NEXP 4
#define OD 128

// ---------------- scratch (device globals: no allocation allowed) ----------------
__device__ __align__(16) float g_h1[NN*HH];
__device__ __align__(16) float g_h[NN*HH];
__device__ __align__(16) uint32_t g_hp[NN*HH];        // h packed hi/lo
__device__ __align__(16) uint32_t g_agg[NN*HH];       // aggregate(h) packed
__device__ __align__(16) float g_w[NN*NEXP];
__device__ __align__(16) uint32_t g_hE0[(long)NEXP*NN*HH];   // packed, used as [NN][1024]
__device__ __align__(16) uint32_t g_hE1[(long)NEXP*NN*HH];   // packed per-expert
__device__ __align__(16) uint32_t g_aggE[(long)NEXP*NN*HH];  // packed (aggE, then te|root)
__device__ int   g_deg[NN];
__device__ int   g_rowptr[NN+1];
__device__ int   g_cur[NN];
__device__ int   g_esrc[EE];
__device__ int   g_bsum[64];
__device__ int   g_ncnt[GG];
__device__ int   g_ecnt[GG];
__device__ float g_featsn[GG*3];
__device__ float g_lognn[GG];
__device__ float g_zero[HH];                          // stays zero
#define WBUF_ELEMS 2883584
__device__ __align__(16) __nv_bfloat16 g_wbuf[WBUF_ELEMS];
__device__ __align__(16) float g_wt[2*65536];         // fp32 W^T: enc_W2, r_W1[:256]

// wbuf layout (elements):
#define OFF_L0C   0        // L0 rel concat [1024][256] hi + lo (524288)
#define OFF_L0CR  524288   // L0 root concat (524288)
#define OFF_L1    1048576  // per-expert stride 262144 (rel hi/lo, root hi/lo at +131072)
#define OFF_L2    2097152  // per-expert stride 131072: concat [256][256] hi + lo at +65536

// ======================= helpers =======================
__device__ __forceinline__ uint32_t smem_u32(const void* p){
    uint32_t a;
    asm("{ .reg .u64 t; cvta.to.shared.u64 t, %1; cvt.u32.u64 %0, t; }" : "=r"(a) : "l"(p));
    return a;
}
__device__ __forceinline__ void ldm4(uint32_t* r, uint32_t addr){
    asm volatile("ldmatrix.sync.aligned.m8n8.x4.shared.b16 {%0,%1,%2,%3}, [%4];"
        : "=r"(r[0]), "=r"(r[1]), "=r"(r[2]), "=r"(r[3]) : "r"(addr));
}
__device__ __forceinline__ void mma16816(float* c, const uint32_t* a, const uint32_t* b){
    asm volatile("mma.sync.aligned.m16n8k16.row.col.f32.bf16.bf16.f32 "
        "{%0,%1,%2,%3}, {%4,%5,%6,%7}, {%8,%9}, {%0,%1,%2,%3};"
        : "+f"(c[0]), "+f"(c[1]), "+f"(c[2]), "+f"(c[3])
        : "r"(a[0]), "r"(a[1]), "r"(a[2]), "r"(a[3]), "r"(b[0]), "r"(b[1]));
}
__device__ __forceinline__ void mma_tf32(float* c, const uint32_t* a, const uint32_t* b){
    asm volatile("mma.sync.aligned.m16n8k8.row.col.f32.tf32.tf32.f32 "
        "{%0,%1,%2,%3}, {%4,%5,%6,%7}, {%8,%9}, {%0,%1,%2,%3};"
        : "+f"(c[0]), "+f"(c[1]), "+f"(c[2]), "+f"(c[3])
        : "r"(a[0]), "r"(a[1]), "r"(a[2]), "r"(a[3]), "r"(b[0]), "r"(b[1]));
}
__device__ __forceinline__ uint32_t f2tf(float f){
    uint32_t r;
    asm("cvt.rna.tf32.f32 %0, %1;" : "=r"(r) : "f"(f));
    return r;
}
__device__ __forceinline__ void tf_split(float f, uint32_t& hi, uint32_t& lo){
    hi = f2tf(f);
    lo = f2tf(f - __uint_as_float(hi));
}
__device__ __forceinline__ uint32_t pack_hilo(float v){
    __nv_bfloat16 h = __float2bfloat16(v);
    __nv_bfloat16 l = __float2bfloat16(v - __bfloat162float(h));
    return ((uint32_t)__bfloat16_as_ushort(h) << 16) | (uint32_t)__bfloat16_as_ushort(l);
}
__device__ __forceinline__ float unpack_hilo(uint32_t w){
    float h = __bfloat162float(__ushort_as_bfloat16((unsigned short)(w >> 16)));
    float l = __bfloat162float(__ushort_as_bfloat16((unsigned short)(w & 0xFFFFu)));
    return h + l;
}
__device__ __forceinline__ void cp_async16(uint32_t saddr, const void* gptr){
    asm volatile("cp.async.cg.shared.global [%0], [%1], 16;" :: "r"(saddr), "l"(gptr) : "memory");
}
__device__ __forceinline__ void cp_commit(){
    asm volatile("cp.async.commit_group;" ::: "memory");
}
__device__ __forceinline__ void cp_wait0(){
    asm volatile("cp.async.wait_group 0;" ::: "memory");
}

// ======================= weight prep =======================
__global__ void prep_w(const float* __restrict__ srcp, __nv_bfloat16* __restrict__ dstp,
                       int Ncols, int nSeg, long sstr, long dstr){
    long total = (long)nSeg * Ncols * 256;
    long plane = (long)Ncols * 256;
    for (long i = (long)blockIdx.x*blockDim.x + threadIdx.x; i < total; i += (long)gridDim.x*blockDim.x){
        int k = (int)(i & 255);
        long t = i >> 8;
        int n = (int)(t % Ncols);
        int e = (int)(t / Ncols);
        float v = srcp[e*sstr + (long)k*Ncols + n];
        __nv_bfloat16 h = __float2bfloat16(v);
        float rem = v - __bfloat162float(h);
        dstp[e*dstr + (long)n*256 + k] = h;
        dstp[e*dstr + plane + (long)n*256 + k] = __float2bfloat16(rem);
    }
}

// L0 concat: fp32 [4][256][256] -> bf16 hi [1024][256] + lo plane at +262144
__global__ void prep_wc(const float* __restrict__ src, __nv_bfloat16* __restrict__ dst){
    int i = blockIdx.x*256 + threadIdx.x;       // 0..262143
    int k = i & 255;
    int t = i >> 8;
    int n = t & 255;
    int e = t >> 8;
    float v = src[e*65536 + k*256 + n];
    __nv_bfloat16 h = __float2bfloat16(v);
    long d = ((long)(e*256 + n))*256 + k;
    dst[d] = h;
    dst[262144 + d] = __float2bfloat16(v - __bfloat162float(h));
}

// L2 concat per expert: [W2_rel | W2_root] -> bf16 hi [256][256] + lo at +65536, stride 131072
__global__ void prep_w2c(const float* __restrict__ rel, const float* __restrict__ root,
                         __nv_bfloat16* __restrict__ dst){
    int i = blockIdx.x*256 + threadIdx.x;       // 0..262143 (4 experts x 256 n x 256 k)
    int k = i & 255;
    int t = i >> 8;
    int n = t & 255;
    int e = t >> 8;
    float v = (n < 128) ? rel[e*32768 + k*128 + n] : root[e*32768 + k*128 + (n-128)];
    __nv_bfloat16 h = __float2bfloat16(v);
    long d = (long)e*131072 + (long)n*256 + k;
    dst[d] = h;
    dst[d + 65536] = __float2bfloat16(v - __bfloat162float(h));
}

// fp32 [256,256] row-major -> transposed [N][K]
__global__ void prep_wt(const float* __restrict__ src, float* __restrict__ dst){
    int i = blockIdx.x*256 + threadIdx.x;
    int k = i >> 8, n = i & 255;
    dst[(long)n*256 + k] = src[(long)k*256 + n];
}

// ======================= encoder layer 1: h1 = relu(xs @ W1 + b1), K=6 exact fp32 =======================
__global__ void enc1_kernel(const float* __restrict__ x, const float* __restrict__ W1,
                            const float* __restrict__ b1, float* __restrict__ out){
    int n = blockIdx.x;
    __shared__ float xs[6];
    if (threadIdx.x < 6) xs[threadIdx.x] = x[n*16 + 4 + threadIdx.x];
    __syncthreads();
    float acc = 0.f;
#pragma unroll
    for (int k = 0; k < 6; ++k)
        acc += xs[k] * W1[k*HH + threadIdx.x];
    acc += b1[threadIdx.x];
    out[(long)n*HH + threadIdx.x] = fmaxf(acc, 0.f);
}

// ======================= 3-term tf32 GEMM (fp32-exact class) =======================
#define FBM 128
#define FAS 20
__global__ void __launch_bounds__(256) tf32gemm(
    const float* __restrict__ A, const float* __restrict__ Bt,
    const float* __restrict__ bias, float* __restrict__ C,
    uint32_t* __restrict__ Cp, int M)
{
    __shared__ float As[2][128*FAS];
    __shared__ float Bs[2][64*FAS];
    const int tid = threadIdx.x;
    const int wid = tid >> 5, lane = tid & 31;
    const int wr = wid >> 1, wc = wid & 1;
    const int bm = blockIdx.x * FBM, bn = blockIdx.y * 64;
    const int fr = lane >> 2, fc = lane & 3;

    float acc[2][4][4];
#pragma unroll
    for (int i = 0; i < 2; ++i)
#pragma unroll
        for (int j = 0; j < 4; ++j)
#pragma unroll
            for (int q = 0; q < 4; ++q) acc[i][j][q] = 0.f;

    float ar[8];
    float4 br;
    const int arow = tid >> 1, ac8 = (tid & 1) * 8;
    const int bnr = tid >> 2, bk4 = (tid & 3) * 4;

    auto ldg = [&](int ch){
        int k0 = ch * 16;
        int gr = bm + arow;
        if (gr < M){
            const float* ap = A + (long)gr*256 + k0 + ac8;
            float4 f0 = *(const float4*)ap;
            float4 f1 = *(const float4*)(ap + 4);
            ar[0]=f0.x; ar[1]=f0.y; ar[2]=f0.z; ar[3]=f0.w;
            ar[4]=f1.x; ar[5]=f1.y; ar[6]=f1.z; ar[7]=f1.w;
        } else {
#pragma unroll
            for (int q = 0; q < 8; ++q) ar[q] = 0.f;
        }
        br = *(const float4*)(Bt + (long)(bn + bnr)*256 + k0 + bk4);
    };
    auto sts = [&](int buf){
        float* pa = &As[buf][arow*FAS + ac8];
#pragma unroll
        for (int q = 0; q < 8; ++q) pa[q] = ar[q];
        float* pb = &Bs[buf][bnr*FAS + bk4];
        pb[0]=br.x; pb[1]=br.y; pb[2]=br.z; pb[3]=br.w;
    };
    auto compute = [&](int buf){
#pragma unroll
        for (int ks = 0; ks < 2; ++ks){
            int kk = ks * 8;
            uint32_t ah[2][4], al[2][4];
#pragma unroll
            for (int mt = 0; mt < 2; ++mt){
                int r0 = wr*32 + mt*16 + fr;
                float f0 = As[buf][r0*FAS + kk + fc];
                float f1 = As[buf][(r0+8)*FAS + kk + fc];
                float f2 = As[buf][r0*FAS + kk + fc + 4];
                float f3 = As[buf][(r0+8)*FAS + kk + fc + 4];
                tf_split(f0, ah[mt][0], al[mt][0]);
                tf_split(f1, ah[mt][1], al[mt][1]);
                tf_split(f2, ah[mt][2], al[mt][2]);
                tf_split(f3, ah[mt][3], al[mt][3]);
            }
#pragma unroll
            for (int nt = 0; nt < 4; ++nt){
                int n0 = wc*32 + nt*8 + fr;
                float g0 = Bs[buf][n0*FAS + kk + fc];
                float g1 = Bs[buf][n0*FAS + kk + fc + 4];
                uint32_t bh[2], bl[2];
                tf_split(g0, bh[0], bl[0]);
                tf_split(g1, bh[1], bl[1]);
#pragma unroll
                for (int mt = 0; mt < 2; ++mt){
                    mma_tf32(acc[mt][nt], ah[mt], bh);
                    mma_tf32(acc[mt][nt], al[mt], bh);
                    mma_tf32(acc[mt][nt], ah[mt], bl);
                }
            }
        }
    };

    ldg(0); sts(0); __syncthreads();
    for (int c = 0; c < 16; ++c){
        if (c + 1 < 16) ldg(c + 1);
        compute(c & 1);
        if (c + 1 < 16){ sts((c + 1) & 1); __syncthreads(); }
    }

#pragma unroll
    for (int mt = 0; mt < 2; ++mt){
#pragma unroll
        for (int nt = 0; nt < 4; ++nt){
            int row0 = bm + wr*32 + mt*16 + fr;
            int col  = bn + wc*32 + nt*8 + fc*2;
            float b0 = bias[col];
            float b1 = bias[col + 1];
#pragma unroll
            for (int half = 0; half < 2; ++half){
                int row = row0 + half*8;
                if (row < M){
                    float2 o;
                    o.x = acc[mt][nt][half*2 + 0] + b0;
                    o.y = acc[mt][nt][half*2 + 1] + b1;
                    *(float2*)(C + (long)row*256 + col) = o;
                    if (Cp){
                        uint2 po;
                        po.x = pack_hilo(o.x);
                        po.y = pack_hilo(o.y);
                        *(uint2*)(Cp + (long)row*256 + col) = po;
                    }
                }
            }
        }
    }
}

// ======================= mma.sync split-bf16 dual GEMM, 128x64 tile, expert-batched, cp.async B ===========
#define TBM 128
#define TBN 64
#define TBK 32
#define ARS 80
#define AS_PLANE 10240
#define AS_STAGE 20480
#define BS_PLANE 5120
#define BS_STAGE 10240
#define BS_OFF   40960
#define SMEM_DYN 61440

__global__ void __launch_bounds__(256) tgemm(
    const uint32_t* __restrict__ A0, int lda0,
    const uint32_t* __restrict__ A1, int lda1,
    const __nv_bfloat16* __restrict__ B0, const __nv_bfloat16* __restrict__ B1,
    const float* __restrict__ bias, float* __restrict__ C,
    int Nc, int M, int relu, int out_packed, int accum,
    const float* __restrict__ rowscale, int rs_stride,
    const uint32_t* __restrict__ addin,
    long a0_es, long a1_es, long b_es, long bias_es, long c_es)
{
    extern __shared__ char dsm[];
    const uint32_t sbase = smem_u32(dsm);

    // expert offset via blockIdx.z
    {
        long ex = (long)blockIdx.z;
        A0 += ex * a0_es;
        if (A1) A1 += ex * a1_es;
        B0 += ex * b_es;
        if (B1) B1 += ex * b_es;
        bias += ex * bias_es;
        C += ex * c_es;
    }

    const int tid  = threadIdx.x;
    const int wid  = tid >> 5;
    const int lane = tid & 31;
    const int wr   = wid >> 1;
    const int wc   = wid & 1;
    const int bm   = blockIdx.x * TBM;
    const int bn   = blockIdx.y * TBN;

    const int nch = (A1 != 0) ? 16 : 8;
    const long bplane = (long)Nc * 256;

    float acc[2][4][4];
#pragma unroll
    for (int i = 0; i < 2; ++i)
#pragma unroll
        for (int j = 0; j < 4; ++j)
#pragma unroll
            for (int q = 0; q < 4; ++q) acc[i][j][q] = 0.f;

    uint32_t aw[16];
    const int arow_g = tid >> 1;
    const int acol_g = (tid & 1) * 16;
    const int brow_g = tid >> 2;
    const int bcol_g = (tid & 3) * 8;

    auto ldgA = [&](int c){
        int seg = c >> 3;
        int k0  = (c & 7) * TBK;
        const uint32_t* A = seg ? A1 : A0;
        const int lda = seg ? lda1 : lda0;
        int gr = bm + arow_g;
        if (gr < M){
            const uint32_t* ap = A + (long)gr*lda + k0 + acol_g;
            uint4 u0 = *(const uint4*)ap;
            uint4 u1 = *(const uint4*)(ap + 4);
            uint4 u2 = *(const uint4*)(ap + 8);
            uint4 u3 = *(const uint4*)(ap + 12);
            aw[0]=u0.x; aw[1]=u0.y; aw[2]=u0.z; aw[3]=u0.w;
            aw[4]=u1.x; aw[5]=u1.y; aw[6]=u1.z; aw[7]=u1.w;
            aw[8]=u2.x; aw[9]=u2.y; aw[10]=u2.z; aw[11]=u2.w;
            aw[12]=u3.x; aw[13]=u3.y; aw[14]=u3.z; aw[15]=u3.w;
        } else {
#pragma unroll
            for (int q = 0; q < 16; ++q) aw[q] = 0u;
        }
    };

    auto cpB = [&](int c, int buf){
        int seg = c >> 3;
        int k0  = (c & 7) * TBK;
        const __nv_bfloat16* B = seg ? B1 : B0;
        const __nv_bfloat16* bp = B + (long)(bn + brow_g)*256 + k0 + bcol_g;
        uint32_t pb = sbase + BS_OFF + (uint32_t)buf*BS_STAGE + (uint32_t)(brow_g*ARS + bcol_g*2);
        cp_async16(pb, bp);
        cp_async16(pb + BS_PLANE, bp + bplane);
        cp_commit();
    };

    auto stsA = [&](int buf){
        uint32_t hh[8], ll[8];
#pragma unroll
        for (int q = 0; q < 8; ++q){
            hh[q] = __byte_perm(aw[2*q], aw[2*q+1], 0x7632);
            ll[q] = __byte_perm(aw[2*q], aw[2*q+1], 0x5410);
        }
        char* pa = dsm + buf*AS_STAGE + arow_g*ARS + acol_g*2;
        *(uint4*)pa        = make_uint4(hh[0], hh[1], hh[2], hh[3]);
        *(uint4*)(pa + 16) = make_uint4(hh[4], hh[5], hh[6], hh[7]);
        *(uint4*)(pa + AS_PLANE)      = make_uint4(ll[0], ll[1], ll[2], ll[3]);
        *(uint4*)(pa + AS_PLANE + 16) = make_uint4(ll[4], ll[5], ll[6], ll[7]);
    };

    const int tile = lane >> 3;
    const int trr  = lane & 7;
    const int arow = wr*32 + ((tile & 1) << 3) + trr;
    const int akk0 = ((tile & 2) << 2);
    const int brow = wc*32 + ((tile & 2) << 2) + trr;
    const int bkk0 = ((tile & 1) << 3);

    auto compute = [&](int buf){
        uint32_t aBase = sbase + (uint32_t)buf*AS_STAGE;
        uint32_t bBase = sbase + BS_OFF + (uint32_t)buf*BS_STAGE;
#pragma unroll
        for (int kt = 0; kt < 2; ++kt){
            uint32_t a_hi[2][4], a_lo[2][4], bb[2][4];
            uint32_t ak = (uint32_t)(akk0 + kt*16)*2;
            uint32_t bk = (uint32_t)(bkk0 + kt*16)*2;
            ldm4(a_hi[0], aBase + (uint32_t)(arow)*ARS + ak);
            ldm4(a_hi[1], aBase + (uint32_t)(arow+16)*ARS + ak);
            ldm4(bb[0],   bBase + (uint32_t)(brow)*ARS + bk);
            ldm4(bb[1],   bBase + (uint32_t)(brow+16)*ARS + bk);
#pragma unroll
            for (int mt = 0; mt < 2; ++mt)
#pragma unroll
                for (int nt = 0; nt < 4; ++nt)
                    mma16816(acc[mt][nt], a_hi[mt], &bb[nt>>1][(nt&1)*2]);
            ldm4(a_lo[0], aBase + AS_PLANE + (uint32_t)(arow)*ARS + ak);
            ldm4(a_lo[1], aBase + AS_PLANE + (uint32_t)(arow+16)*ARS + ak);
#pragma unroll
            for (int mt = 0; mt < 2; ++mt)
#pragma unroll
                for (int nt = 0; nt < 4; ++nt)
                    mma16816(acc[mt][nt], a_lo[mt], &bb[nt>>1][(nt&1)*2]);
            ldm4(bb[0],   bBase + BS_PLANE + (uint32_t)(brow)*ARS + bk);
            ldm4(bb[1],   bBase + BS_PLANE + (uint32_t)(brow+16)*ARS + bk);
#pragma unroll
            for (int mt = 0; mt < 2; ++mt)
#pragma unroll
                for (int nt = 0; nt < 4; ++nt)
                    mma16816(acc[mt][nt], a_hi[mt], &bb[nt>>1][(nt&1)*2]);
        }
    };

    ldgA(0);
    cpB(0, 0);
    stsA(0);
    cp_wait0();
    __syncthreads();
    for (int c = 0; c < nch; ++c){
        if (c + 1 < nch){
            ldgA(c + 1);
            cpB(c + 1, (c + 1) & 1);
        }
        compute(c & 1);
        if (c + 1 < nch){
            stsA((c + 1) & 1);
            cp_wait0();
            __syncthreads();
        }
    }

#pragma unroll
    for (int mt = 0; mt < 2; ++mt){
#pragma unroll
        for (int nt = 0; nt < 4; ++nt){
            int row0 = bm + wr*32 + mt*16 + (lane >> 2);
            int col  = bn + wc*32 + nt*8 + (lane & 3)*2;
            float b0 = bias[col];
            float b1 = bias[col + 1];
#pragma unroll
            for (int half = 0; half < 2; ++half){
                int row = row0 + half*8;
                if (row < M){
                    float v0 = acc[mt][nt][half*2 + 0] + b0;
                    float v1 = acc[mt][nt][half*2 + 1] + b1;
                    if (relu){ v0 = fmaxf(v0, 0.f); v1 = fmaxf(v1, 0.f); }
                    if (out_packed){
                        uint2 o;
                        o.x = pack_hilo(v0);
                        o.y = pack_hilo(v1);
                        *(uint2*)((uint32_t*)C + (long)row*Nc + col) = o;
                    } else {
                        if (addin){
                            uint2 ai = *(const uint2*)(addin + (long)row*Nc + col);
                            v0 += unpack_hilo(ai.x);
                            v1 += unpack_hilo(ai.y);
                        }
                        if (rowscale){
                            float rs = rowscale[(long)row*rs_stride];
                            v0 *= rs; v1 *= rs;
                        }
                        float* cp = C + (long)row*Nc + col;
                        if (accum){ v0 += cp[0]; v1 += cp[1]; }
                        float2 o; o.x = v0; o.y = v1;
                        *(float2*)cp = o;
                    }
                }
            }
        }
    }
}

// ---------------- merged histograms: node counts + edge counts + degrees ----------------
__global__ void prep_graph(const int* __restrict__ batch,
                           const int* __restrict__ src, const int* __restrict__ dst){
    __shared__ int sn[GG];
    __shared__ int se[GG];
    if(threadIdx.x < GG){ sn[threadIdx.x] = 0; se[threadIdx.x] = 0; }
    __syncthreads();
    for(int i = blockIdx.x*blockDim.x + threadIdx.x; i < NN; i += gridDim.x*blockDim.x)
        atomicAdd(&sn[batch[i]], 1);
    for(int i = blockIdx.x*blockDim.x + threadIdx.x; i < EE; i += gridDim.x*blockDim.x){
        atomicAdd(&se[batch[src[i]]], 1);
        atomicAdd(&g_deg[dst[i]], 1);
    }
    __syncthreads();
    if(threadIdx.x < GG){
        if(sn[threadIdx.x]) atomicAdd(&g_ncnt[threadIdx.x], sn[threadIdx.x]);
        if(se[threadIdx.x]) atomicAdd(&g_ecnt[threadIdx.x], se[threadIdx.x]);
    }
}

// ---------------- graph stats ----------------
__global__ void stats_kernel(){
    int g = threadIdx.x;
    float n   = fmaxf((float)g_ncnt[g], 1.f);
    float e   = (float)g_ecnt[g];
    float den = e / fmaxf(n*(n-1.f), 1.f);
    float ln  = logf(n);
    __shared__ float sn[GG], se[GG], sd[GG], sl[GG];
    sn[g]=n; se[g]=e; sd[g]=den; sl[g]=ln;
    __syncthreads();
    __shared__ float sc[8];
    if(g == 0){
        float mn=sl[0], mx=sl[0], s0=0, s1=0, s2=0;
        for(int i=0;i<GG;i++){ mn=fminf(mn,sl[i]); mx=fmaxf(mx,sl[i]); s0+=sn[i]; s1+=se[i]; s2+=sd[i]; }
        float m0=s0/GG, m1=s1/GG, m2=s2/GG;
        float q0=0,q1=0,q2=0;
        for(int i=0;i<GG;i++){
            float d0=sn[i]-m0, d1=se[i]-m1, d2=sd[i]-m2;
            q0+=d0*d0; q1+=d1*d1; q2+=d2*d2;
        }
        sc[0]=mn; sc[1]=mx; sc[2]=m0; sc[3]=m1; sc[4]=m2;
        sc[5]=sqrtf(q0/GG); sc[6]=sqrtf(q1/GG); sc[7]=sqrtf(q2/GG);
    }
    __syncthreads();
    g_lognn[g]       = (ln  - sc[0])/(sc[1]-sc[0]+1e-6f);
    g_featsn[g*3+0]  = (n   - sc[2])/(sc[5]+1e-6f);
    g_featsn[g*3+1]  = (e   - sc[3])/(sc[6]+1e-6f);
    g_featsn[g*3+2]  = (den - sc[4])/(sc[7]+1e-6f);
}

// ---------------- CSR build ----------------
__global__ void scan1(){
    __shared__ int sh[1024];
    int i = blockIdx.x*1024 + threadIdx.x;
    int v = (i < NN) ? g_deg[i] : 0;
    sh[threadIdx.x] = v;
    __syncthreads();
    for(int off=1; off<1024; off<<=1){
        int t = sh[threadIdx.x];
        if(threadIdx.x >= off) t += sh[threadIdx.x - off];
        __syncthreads();
        sh[threadIdx.x] = t;
        __syncthreads();
    }
    if(i < NN) g_rowptr[i] = sh[threadIdx.x] - v;
    if(threadIdx.x == 1023) g_bsum[blockIdx.x] = sh[1023];
}

__global__ void scan2(int nb){
    if(threadIdx.x == 0){
        int run = 0;
        for(int b=0;b<nb;b++){ int v=g_bsum[b]; g_bsum[b]=run; run+=v; }
    }
}

__global__ void scan3(){
    int i = blockIdx.x*blockDim.x + threadIdx.x;
    if(i < NN) g_rowptr[i] += g_bsum[i >> 10];
    if(i == 0) g_rowptr[NN] = EE;
}

__global__ void place_edges(const int* __restrict__ src, const int* __restrict__ dst){
    for(int i = blockIdx.x*blockDim.x + threadIdx.x; i < EE; i += gridDim.x*blockDim.x){
        int d = dst[i];
        int idx = g_rowptr[d] + atomicAdd(&g_cur[d], 1);
        g_esrc[idx] = src[i];
    }
}

// ---------------- CSR gather aggregation (packed, grouped) ----------------
__global__ void aggregate_pg(const uint32_t* __restrict__ in, uint32_t* __restrict__ out,
                             int Win, long in_goff, int Wout, long out_goff){
    int n = blockIdx.x;
    const uint32_t* ip = in + (long)blockIdx.y * in_goff;
    uint32_t* op = out + (long)blockIdx.y * out_goff;
    int s0 = g_rowptr[n], s1 = g_rowptr[n+1];
    float a0=0.f, a1=0.f, a2=0.f, a3=0.f, a4=0.f, a5=0.f, a6=0.f, a7=0.f;
    int j = s0;
    for(; j + 8 <= s1; j += 8){
        int i0 = g_esrc[j],   i1 = g_esrc[j+1], i2 = g_esrc[j+2], i3 = g_esrc[j+3];
        int i4 = g_esrc[j+4], i5 = g_esrc[j+5], i6 = g_esrc[j+6], i7 = g_esrc[j+7];
        a0 += unpack_hilo(ip[(long)i0*Win + threadIdx.x]);
        a1 += unpack_hilo(ip[(long)i1*Win + threadIdx.x]);
        a2 += unpack_hilo(ip[(long)i2*Win + threadIdx.x]);
        a3 += unpack_hilo(ip[(long)i3*Win + threadIdx.x]);
        a4 += unpack_hilo(ip[(long)i4*Win + threadIdx.x]);
        a5 += unpack_hilo(ip[(long)i5*Win + threadIdx.x]);
        a6 += unpack_hilo(ip[(long)i6*Win + threadIdx.x]);
        a7 += unpack_hilo(ip[(long)i7*Win + threadIdx.x]);
    }
    for(; j < s1; ++j)
        a0 += unpack_hilo(ip[(long)g_esrc[j]*Win + threadIdx.x]);
    op[(long)n*Wout + threadIdx.x] = pack_hilo(((a0 + a1) + (a2 + a3)) + ((a4 + a5) + (a6 + a7)));
}

// ---------------- final: aggregate t_e + combine across experts ----------------
__global__ void agg_combine(const uint32_t* __restrict__ te, const float* __restrict__ w,
                            const float* __restrict__ b2, float* __restrict__ out){
    int n = blockIdx.x;
    int c = threadIdx.x;          // 0..127
    int s0 = g_rowptr[n], s1 = g_rowptr[n+1];
    float res = 0.f;
#pragma unroll
    for (int e = 0; e < NEXP; ++e){
        const uint32_t* tp = te + (long)e*NN*256;
        float a0=0.f, a1=0.f, a2=0.f, a3=0.f;
        int j = s0;
        for(; j + 4 <= s1; j += 4){
            int i0 = g_esrc[j], i1 = g_esrc[j+1], i2 = g_esrc[j+2], i3 = g_esrc[j+3];
            a0 += unpack_hilo(tp[(long)i0*256 + c]);
            a1 += unpack_hilo(tp[(long)i1*256 + c]);
            a2 += unpack_hilo(tp[(long)i2*256 + c]);
            a3 += unpack_hilo(tp[(long)i3*256 + c]);
        }
        for(; j < s1; ++j)
            a0 += unpack_hilo(tp[(long)g_esrc[j]*256 + c]);
        float agg = (a0 + a1) + (a2 + a3);
        float root = unpack_hilo(tp[(long)n*256 + 128 + c]);
        res += w[n*NEXP + e] * (agg + root + b2[e*OD + c]);
    }
    out[(long)n*OD + c] = res;
}

// ---------------- router (fused sf lookup + K=3 correction) ----------------
__global__ void router_kernel(const float* __restrict__ t, const int* __restrict__ batch,
                              const float* __restrict__ lng, const float* __restrict__ lnb,
                              const float* __restrict__ W2, const float* __restrict__ b2,
                              const float* __restrict__ centers,
                              const float* __restrict__ W1s)
{
    int n = blockIdx.x; int tid = threadIdx.x;
    int lane = tid & 31, wid = tid >> 5;
    int grp = batch[n];
    float s0f = g_featsn[grp*3+0], s1f = g_featsn[grp*3+1], s2f = g_featsn[grp*3+2];
    float v = t[(long)n*HH + tid]
            + s0f * W1s[tid] + s1f * W1s[HH + tid] + s2f * W1s[2*HH + tid];
    float s = v, sq = v*v;
#pragma unroll
    for(int o=16;o>0;o>>=1){
        s  += __shfl_down_sync(0xffffffffu, s,  o);
        sq += __shfl_down_sync(0xffffffffu, sq, o);
    }
    __shared__ float red[8*2];
    __shared__ float red4[8*4];
    __shared__ float bc[2];
    if(lane == 0){ red[wid*2]=s; red[wid*2+1]=sq; }
    __syncthreads();
    if(tid == 0){
        float S=0, Q=0;
        for(int w=0;w<8;w++){ S+=red[w*2]; Q+=red[w*2+1]; }
        float mean = S/HH;
        bc[0]=mean; bc[1]=Q/HH - mean*mean;
    }
    __syncthreads();
    float mean = bc[0], var = bc[1];
    float r = (v - mean)*rsqrtf(var + 1e-5f)*lng[tid] + lnb[tid];
    r = fmaxf(r, 0.f);
    float p[4];
#pragma unroll
    for(int e=0;e<4;e++) p[e] = r * W2[tid*4+e];
#pragma unroll
    for(int o=16;o>0;o>>=1)
#pragma unroll
        for(int e=0;e<4;e++) p[e] += __shfl_down_sync(0xffffffffu, p[e], o);
    if(lane == 0)
        for(int e=0;e<4;e++) red4[wid*4+e] = p[e];
    __syncthreads();
    if(tid == 0){
        float logit[4], probs[4];
        float lnode = g_lognn[grp];
        for(int e=0;e<4;e++){
            float sum = 0;
            for(int w=0;w<8;w++) sum += red4[w*4+e];
            float learned = sum + b2[e];
            float d = lnode - centers[e];
            logit[e] = 0.7f*learned - 0.3f*d*d;
        }
        float mx = logit[0];
        for(int e=1;e<4;e++) mx = fmaxf(mx, logit[e]);
        float ssum = 0;
        for(int e=0;e<4;e++){ probs[e] = expf(logit[e]-mx); ssum += probs[e]; }
        for(int e=0;e<4;e++) probs[e] /= ssum;
        int i0 = 0;
        for(int e=1;e<4;e++) if(probs[e] > probs[i0]) i0 = e;
        int i1 = -1;
        for(int e=0;e<4;e++){
            if(e == i0) continue;
            if(i1 < 0 || probs[e] > probs[i1]) i1 = e;
        }
        float denom = probs[i0] + probs[i1] + 1e-8f;
        float wv[4] = {0.f,0.f,0.f,0.f};
        wv[i0] = probs[i0]/denom;
        wv[i1] = probs[i1]/denom;
        for(int e=0;e<4;e++) g_w[(long)n*4+e] = wv[e];
    }
}

// ---------------- host ----------------
extern "C" void kernel_launch(void* const* d_in, const int* in_sizes, int n_in,
                              void* d_out, int out_size)
{
    const float* x       = (const float*)d_in[0];
    const int*   ei      = (const int*)  d_in[1];
    const int*   batch   = (const int*)  d_in[2];
    const float* enc_W1  = (const float*)d_in[3];
    const float* enc_b1  = (const float*)d_in[4];
    const float* enc_W2  = (const float*)d_in[5];
    const float* enc_b2  = (const float*)d_in[6];
    const float* r_W1    = (const float*)d_in[7];
    const float* r_b1    = (const float*)d_in[8];
    const float* ln_g    = (const float*)d_in[9];
    const float* ln_b    = (const float*)d_in[10];
    const float* r_W2    = (const float*)d_in[11];
    const float* r_b2    = (const float*)d_in[12];
    const float* centers = (const float*)d_in[13];
    const float* W0_rel  = (const float*)d_in[14];
    const float* b0_rel  = (const float*)d_in[15];
    const float* W0_root = (const float*)d_in[16];
    const float* W1_rel  = (const float*)d_in[17];
    const float* b1_rel  = (const float*)d_in[18];
    const float* W1_root = (const float*)d_in[19];
    const float* W2_rel  = (const float*)d_in[20];
    const float* b2_rel  = (const float*)d_in[21];
    const float* W2_root = (const float*)d_in[22];
    const int* src = ei;
    const int* dst = ei + EE;
    float* out = (float*)d_out;

    float *p_h1,*p_h,*p_w,*p_wt,*p_zero;
    uint32_t *p_hp,*p_agg,*p_hE0,*p_hE1,*p_aggE;
    int *p_ncnt,*p_ecnt,*p_deg,*p_cur;
    __nv_bfloat16* p_wb;
    cudaGetSymbolAddress((void**)&p_h1,  g_h1);
    cudaGetSymbolAddress((void**)&p_h,   g_h);
    cudaGetSymbolAddress((void**)&p_hp,  g_hp);
    cudaGetSymbolAddress((void**)&p_agg, g_agg);
    cudaGetSymbolAddress((void**)&p_w,   g_w);
    cudaGetSymbolAddress((void**)&p_hE0, g_hE0);
    cudaGetSymbolAddress((void**)&p_hE1, g_hE1);
    cudaGetSymbolAddress((void**)&p_aggE,g_aggE);
    cudaGetSymbolAddress((void**)&p_ncnt,g_ncnt);
    cudaGetSymbolAddress((void**)&p_ecnt,g_ecnt);
    cudaGetSymbolAddress((void**)&p_deg, g_deg);
    cudaGetSymbolAddress((void**)&p_cur, g_cur);
    cudaGetSymbolAddress((void**)&p_wb,  g_wbuf);
    cudaGetSymbolAddress((void**)&p_wt,  g_wt);
    cudaGetSymbolAddress((void**)&p_zero,g_zero);

    cudaFuncSetAttribute(tgemm, cudaFuncAttributeMaxDynamicSharedMemorySize, SMEM_DYN);

    // ---- weight prep ----
    prep_wt<<<256,256>>>(enc_W2, p_wt);
    prep_wt<<<256,256>>>(r_W1,   p_wt + 65536);
    prep_wc<<<1024,256>>>(W0_rel,  p_wb + OFF_L0C);
    prep_wc<<<1024,256>>>(W0_root, p_wb + OFF_L0CR);
    prep_w<<<256,256>>>(W1_rel,  p_wb + OFF_L1,          256, 4, 65536, 262144);
    prep_w<<<256,256>>>(W1_root, p_wb + OFF_L1 + 131072, 256, 4, 65536, 262144);
    prep_w2c<<<1024,256>>>(W2_rel, W2_root, p_wb + OFF_L2);

    // ---- stats + CSR prep ----
    cudaMemsetAsync(p_ncnt, 0, GG*sizeof(int));
    cudaMemsetAsync(p_ecnt, 0, GG*sizeof(int));
    cudaMemsetAsync(p_deg,  0, NN*sizeof(int));
    cudaMemsetAsync(p_cur,  0, NN*sizeof(int));
    prep_graph<<<784, 256>>>(batch, src, dst);
    stats_kernel<<<1, GG>>>();
    int nscan = (NN+1023)/1024;
    scan1<<<nscan, 1024>>>();
    scan2<<<1, 32>>>(nscan);
    scan3<<<(NN+255)/256, 256>>>();
    place_edges<<<784, 256>>>(src, dst);

    const int TGRIDX = (NN + TBM - 1) / TBM;
    const dim3 fgrid((NN + FBM - 1) / FBM, 4);

    // ---- encoder (exact-class: fused K=6 kernel, then 3xTF32 tensor with fused pack) ----
    enc1_kernel<<<NN, 256>>>(x, enc_W1, enc_b1, p_h1);
    tf32gemm<<<fgrid, 256>>>(p_h1, p_wt, enc_b2, p_h, p_hp, NN);

    // ---- router (3xTF32 main; sf lookup + K=3 correction fused into router kernel) ----
    tf32gemm<<<fgrid, 256>>>(p_h, p_wt + 65536, r_b1, p_h1, (uint32_t*)0, NN);
    router_kernel<<<NN, 256>>>(p_h1, batch, ln_g, ln_b, r_W2, r_b2, centers,
                               r_W1 + HH*HH);

    // ---- aggregate h (packed) ----
    aggregate_pg<<<dim3(NN,1), 256>>>(p_hp, p_agg, 256, 0, 256, 0);

    // ---- expert layer 0: single batched GEMM, Nc=1024, output hE0 as [n][1024] ----
    {
        dim3 grid(TGRIDX, 1024 / TBN, 1);
        tgemm<<<grid, 256, SMEM_DYN>>>(p_agg, 256, p_hp, 256,
                                       p_wb + OFF_L0C, p_wb + OFF_L0CR,
                                       b0_rel, (float*)p_hE0, 1024, NN, 1, 1, 0,
                                       (const float*)0, 0, (const uint32_t*)0,
                                       0, 0, 0, 0, 0);
    }
    // aggregate hE0 per expert: in [n][1024] col-block e*256, out aggE[e][n][256]
    aggregate_pg<<<dim3(NN,4), 256>>>(p_hE0, p_aggE, 1024, 256, 256, (long)NN*256);

    // ---- expert layer 1: one batched launch over 4 experts (blockIdx.z) ----
    {
        dim3 grid(TGRIDX, 256 / TBN, NEXP);
        tgemm<<<grid, 256, SMEM_DYN>>>(p_aggE, 256,
                                       p_hE0, 1024,
                                       p_wb + OFF_L1,
                                       p_wb + OFF_L1 + 131072,
                                       b1_rel, (float*)p_hE1,
                                       HH, NN, 1, 1, 0,
                                       (const float*)0, 0, (const uint32_t*)0,
                                       (long)NN*HH, 256, 262144, HH, (long)NN*HH);
    }

    // ---- expert layer 2, merged, batched: [t_e | root_e] = hE1 @ [W2_rel|W2_root] ----
    {
        dim3 grid(TGRIDX, 256 / TBN, NEXP);
        tgemm<<<grid, 256, SMEM_DYN>>>(p_hE1, 256,
                                       (const uint32_t*)0, 0,
                                       p_wb + OFF_L2, (const __nv_bfloat16*)0,
                                       p_zero, (float*)p_aggE,
                                       256, NN, 0, 1, 0,
                                       (const float*)0, 0, (const uint32_t*)0,
                                       (long)NN*HH, 0, 131072, 0, (long)NN*HH);
    }
    // ---- aggregate t_e + combine across experts -> out (no memset, no RMW) ----
    agg_combine<<<NN, OD>>>(p_aggE, p_w, b2_rel, out);
}

// round 17
// speedup vs baseline: 1.1447x; 1.0588x over previous
#include <cuda_runtime.h>
#include <cuda_bf16.h>
#include <stdint.h>
#include <math.h>

#define NN 50000
#define EE 800000
#define HH 256
#define GG 64
#define NEXP 4
#define OD 128

// ---------------- scratch (device globals: no allocation allowed) ----------------
__device__ __align__(16) float g_h1[NN*HH];
__device__ __align__(16) float g_h[NN*HH];
__device__ __align__(16) uint32_t g_hp[NN*HH];        // h packed hi/lo
__device__ __align__(16) uint32_t g_agg[NN*HH];       // aggregate(h) packed
__device__ __align__(16) float g_w[NN*NEXP];
__device__ __align__(16) uint32_t g_hE0[(long)NEXP*NN*HH];   // packed, used as [NN][1024]
__device__ __align__(16) uint32_t g_hE1[(long)NEXP*NN*HH];   // packed per-expert
__device__ __align__(16) uint32_t g_aggE[(long)NEXP*NN*HH];  // packed (aggE, then te|root)
__device__ int   g_deg[NN];
__device__ int   g_rowptr[NN+1];
__device__ int   g_cur[NN];
__device__ int   g_esrc[EE];
__device__ int   g_bsum[64];
__device__ int   g_ncnt[GG];
__device__ int   g_ecnt[GG];
__device__ float g_featsn[GG*3];
__device__ float g_lognn[GG];
__device__ float g_zero[HH];                          // stays zero
#define WBUF_ELEMS 2883584
__device__ __align__(16) __nv_bfloat16 g_wbuf[WBUF_ELEMS];
__device__ __align__(16) float g_wt[2*65536];         // fp32 W^T: enc_W2, r_W1[:256]

// wbuf layout (elements):
#define OFF_L0C   0        // L0 rel concat [1024][256] hi + lo (524288)
#define OFF_L0CR  524288   // L0 root concat (524288)
#define OFF_L1    1048576  // per-expert stride 262144 (rel hi/lo, root hi/lo at +131072)
#define OFF_L2    2097152  // per-expert stride 131072: concat [256][256] hi + lo at +65536

// ======================= helpers =======================
__device__ __forceinline__ uint32_t smem_u32(const void* p){
    uint32_t a;
    asm("{ .reg .u64 t; cvta.to.shared.u64 t, %1; cvt.u32.u64 %0, t; }" : "=r"(a) : "l"(p));
    return a;
}
__device__ __forceinline__ void ldm4(uint32_t* r, uint32_t addr){
    asm volatile("ldmatrix.sync.aligned.m8n8.x4.shared.b16 {%0,%1,%2,%3}, [%4];"
        : "=r"(r[0]), "=r"(r[1]), "=r"(r[2]), "=r"(r[3]) : "r"(addr));
}
__device__ __forceinline__ void mma16816(float* c, const uint32_t* a, const uint32_t* b){
    asm volatile("mma.sync.aligned.m16n8k16.row.col.f32.bf16.bf16.f32 "
        "{%0,%1,%2,%3}, {%4,%5,%6,%7}, {%8,%9}, {%0,%1,%2,%3};"
        : "+f"(c[0]), "+f"(c[1]), "+f"(c[2]), "+f"(c[3])
        : "r"(a[0]), "r"(a[1]), "r"(a[2]), "r"(a[3]), "r"(b[0]), "r"(b[1]));
}
__device__ __forceinline__ void mma_tf32(float* c, const uint32_t* a, const uint32_t* b){
    asm volatile("mma.sync.aligned.m16n8k8.row.col.f32.tf32.tf32.f32 "
        "{%0,%1,%2,%3}, {%4,%5,%6,%7}, {%8,%9}, {%0,%1,%2,%3};"
        : "+f"(c[0]), "+f"(c[1]), "+f"(c[2]), "+f"(c[3])
        : "r"(a[0]), "r"(a[1]), "r"(a[2]), "r"(a[3]), "r"(b[0]), "r"(b[1]));
}
__device__ __forceinline__ uint32_t f2tf(float f){
    uint32_t r;
    asm("cvt.rna.tf32.f32 %0, %1;" : "=r"(r) : "f"(f));
    return r;
}
__device__ __forceinline__ void tf_split(float f, uint32_t& hi, uint32_t& lo){
    hi = f2tf(f);
    lo = f2tf(f - __uint_as_float(hi));
}
__device__ __forceinline__ uint32_t pack_hilo(float v){
    __nv_bfloat16 h = __float2bfloat16(v);
    __nv_bfloat16 l = __float2bfloat16(v - __bfloat162float(h));
    return ((uint32_t)__bfloat16_as_ushort(h) << 16) | (uint32_t)__bfloat16_as_ushort(l);
}
__device__ __forceinline__ float unpack_hilo(uint32_t w){
    float h = __bfloat162float(__ushort_as_bfloat16((unsigned short)(w >> 16)));
    float l = __bfloat162float(__ushort_as_bfloat16((unsigned short)(w & 0xFFFFu)));
    return h + l;
}
__device__ __forceinline__ void cp_async16(uint32_t saddr, const void* gptr){
    asm volatile("cp.async.cg.shared.global [%0], [%1], 16;" :: "r"(saddr), "l"(gptr) : "memory");
}
__device__ __forceinline__ void cp_commit(){
    asm volatile("cp.async.commit_group;" ::: "memory");
}
__device__ __forceinline__ void cp_wait0(){
    asm volatile("cp.async.wait_group 0;" ::: "memory");
}

// ======================= weight prep =======================
__global__ void prep_w(const float* __restrict__ srcp, __nv_bfloat16* __restrict__ dstp,
                       int Ncols, int nSeg, long sstr, long dstr){
    long total = (long)nSeg * Ncols * 256;
    long plane = (long)Ncols * 256;
    for (long i = (long)blockIdx.x*blockDim.x + threadIdx.x; i < total; i += (long)gridDim.x*blockDim.x){
        int k = (int)(i & 255);
        long t = i >> 8;
        int n = (int)(t % Ncols);
        int e = (int)(t / Ncols);
        float v = srcp[e*sstr + (long)k*Ncols + n];
        __nv_bfloat16 h = __float2bfloat16(v);
        float rem = v - __bfloat162float(h);
        dstp[e*dstr + (long)n*256 + k] = h;
        dstp[e*dstr + plane + (long)n*256 + k] = __float2bfloat16(rem);
    }
}

// L0 concat: fp32 [4][256][256] -> bf16 hi [1024][256] + lo plane at +262144
__global__ void prep_wc(const float* __restrict__ src, __nv_bfloat16* __restrict__ dst){
    int i = blockIdx.x*256 + threadIdx.x;       // 0..262143
    int k = i & 255;
    int t = i >> 8;
    int n = t & 255;
    int e = t >> 8;
    float v = src[e*65536 + k*256 + n];
    __nv_bfloat16 h = __float2bfloat16(v);
    long d = ((long)(e*256 + n))*256 + k;
    dst[d] = h;
    dst[262144 + d] = __float2bfloat16(v - __bfloat162float(h));
}

// L2 concat per expert: [W2_rel | W2_root] -> bf16 hi [256][256] + lo at +65536, stride 131072
__global__ void prep_w2c(const float* __restrict__ rel, const float* __restrict__ root,
                         __nv_bfloat16* __restrict__ dst){
    int i = blockIdx.x*256 + threadIdx.x;       // 0..262143 (4 experts x 256 n x 256 k)
    int k = i & 255;
    int t = i >> 8;
    int n = t & 255;
    int e = t >> 8;
    float v = (n < 128) ? rel[e*32768 + k*128 + n] : root[e*32768 + k*128 + (n-128)];
    __nv_bfloat16 h = __float2bfloat16(v);
    long d = (long)e*131072 + (long)n*256 + k;
    dst[d] = h;
    dst[d + 65536] = __float2bfloat16(v - __bfloat162float(h));
}

// fp32 [256,256] row-major -> transposed [N][K]
__global__ void prep_wt(const float* __restrict__ src, float* __restrict__ dst){
    int i = blockIdx.x*256 + threadIdx.x;
    int k = i >> 8, n = i & 255;
    dst[(long)n*256 + k] = src[(long)k*256 + n];
}

// ======================= encoder layer 1: h1 = relu(xs @ W1 + b1), K=6 exact fp32 =======================
__global__ void enc1_kernel(const float* __restrict__ x, const float* __restrict__ W1,
                            const float* __restrict__ b1, float* __restrict__ out){
    int n = blockIdx.x;
    __shared__ float xs[6];
    if (threadIdx.x < 6) xs[threadIdx.x] = x[n*16 + 4 + threadIdx.x];
    __syncthreads();
    float acc = 0.f;
#pragma unroll
    for (int k = 0; k < 6; ++k)
        acc += xs[k] * W1[k*HH + threadIdx.x];
    acc += b1[threadIdx.x];
    out[(long)n*HH + threadIdx.x] = fmaxf(acc, 0.f);
}

// ======================= 3-term tf32 GEMM (fp32-exact class) =======================
#define FBM 128
#define FAS 20
__global__ void __launch_bounds__(256) tf32gemm(
    const float* __restrict__ A, const float* __restrict__ Bt,
    const float* __restrict__ bias, float* __restrict__ C,
    uint32_t* __restrict__ Cp, int M)
{
    __shared__ float As[2][128*FAS];
    __shared__ float Bs[2][64*FAS];
    const int tid = threadIdx.x;
    const int wid = tid >> 5, lane = tid & 31;
    const int wr = wid >> 1, wc = wid & 1;
    const int bm = blockIdx.x * FBM, bn = blockIdx.y * 64;
    const int fr = lane >> 2, fc = lane & 3;

    float acc[2][4][4];
#pragma unroll
    for (int i = 0; i < 2; ++i)
#pragma unroll
        for (int j = 0; j < 4; ++j)
#pragma unroll
            for (int q = 0; q < 4; ++q) acc[i][j][q] = 0.f;

    float ar[8];
    float4 br;
    const int arow = tid >> 1, ac8 = (tid & 1) * 8;
    const int bnr = tid >> 2, bk4 = (tid & 3) * 4;

    auto ldg = [&](int ch){
        int k0 = ch * 16;
        int gr = bm + arow;
        if (gr < M){
            const float* ap = A + (long)gr*256 + k0 + ac8;
            float4 f0 = *(const float4*)ap;
            float4 f1 = *(const float4*)(ap + 4);
            ar[0]=f0.x; ar[1]=f0.y; ar[2]=f0.z; ar[3]=f0.w;
            ar[4]=f1.x; ar[5]=f1.y; ar[6]=f1.z; ar[7]=f1.w;
        } else {
#pragma unroll
            for (int q = 0; q < 8; ++q) ar[q] = 0.f;
        }
        br = *(const float4*)(Bt + (long)(bn + bnr)*256 + k0 + bk4);
    };
    auto sts = [&](int buf){
        float* pa = &As[buf][arow*FAS + ac8];
#pragma unroll
        for (int q = 0; q < 8; ++q) pa[q] = ar[q];
        float* pb = &Bs[buf][bnr*FAS + bk4];
        pb[0]=br.x; pb[1]=br.y; pb[2]=br.z; pb[3]=br.w;
    };
    auto compute = [&](int buf){
#pragma unroll
        for (int ks = 0; ks < 2; ++ks){
            int kk = ks * 8;
            uint32_t ah[2][4], al[2][4];
#pragma unroll
            for (int mt = 0; mt < 2; ++mt){
                int r0 = wr*32 + mt*16 + fr;
                float f0 = As[buf][r0*FAS + kk + fc];
                float f1 = As[buf][(r0+8)*FAS + kk + fc];
                float f2 = As[buf][r0*FAS + kk + fc + 4];
                float f3 = As[buf][(r0+8)*FAS + kk + fc + 4];
                tf_split(f0, ah[mt][0], al[mt][0]);
                tf_split(f1, ah[mt][1], al[mt][1]);
                tf_split(f2, ah[mt][2], al[mt][2]);
                tf_split(f3, ah[mt][3], al[mt][3]);
            }
#pragma unroll
            for (int nt = 0; nt < 4; ++nt){
                int n0 = wc*32 + nt*8 + fr;
                float g0 = Bs[buf][n0*FAS + kk + fc];
                float g1 = Bs[buf][n0*FAS + kk + fc + 4];
                uint32_t bh[2], bl[2];
                tf_split(g0, bh[0], bl[0]);
                tf_split(g1, bh[1], bl[1]);
#pragma unroll
                for (int mt = 0; mt < 2; ++mt){
                    mma_tf32(acc[mt][nt], ah[mt], bh);
                    mma_tf32(acc[mt][nt], al[mt], bh);
                    mma_tf32(acc[mt][nt], ah[mt], bl);
                }
            }
        }
    };

    ldg(0); sts(0); __syncthreads();
    for (int c = 0; c < 16; ++c){
        if (c + 1 < 16) ldg(c + 1);
        compute(c & 1);
        if (c + 1 < 16){ sts((c + 1) & 1); __syncthreads(); }
    }

#pragma unroll
    for (int mt = 0; mt < 2; ++mt){
#pragma unroll
        for (int nt = 0; nt < 4; ++nt){
            int row0 = bm + wr*32 + mt*16 + fr;
            int col  = bn + wc*32 + nt*8 + fc*2;
            float b0 = bias[col];
            float b1 = bias[col + 1];
#pragma unroll
            for (int half = 0; half < 2; ++half){
                int row = row0 + half*8;
                if (row < M){
                    float2 o;
                    o.x = acc[mt][nt][half*2 + 0] + b0;
                    o.y = acc[mt][nt][half*2 + 1] + b1;
                    *(float2*)(C + (long)row*256 + col) = o;
                    if (Cp){
                        uint2 po;
                        po.x = pack_hilo(o.x);
                        po.y = pack_hilo(o.y);
                        *(uint2*)(Cp + (long)row*256 + col) = po;
                    }
                }
            }
        }
    }
}

// ======================= mma.sync split-bf16 dual GEMM, 128x64 tile, expert-batched, cp.async B ===========
#define TBM 128
#define TBN 64
#define TBK 32
#define ARS 80
#define AS_PLANE 10240
#define AS_STAGE 20480
#define BS_PLANE 5120
#define BS_STAGE 10240
#define BS_OFF   40960
#define SMEM_DYN 61440

__global__ void __launch_bounds__(256) tgemm(
    const uint32_t* __restrict__ A0, int lda0,
    const uint32_t* __restrict__ A1, int lda1,
    const __nv_bfloat16* __restrict__ B0, const __nv_bfloat16* __restrict__ B1,
    const float* __restrict__ bias, float* __restrict__ C,
    int Nc, int M, int relu, int out_packed, int accum,
    const float* __restrict__ rowscale, int rs_stride,
    const uint32_t* __restrict__ addin,
    long a0_es, long a1_es, long b_es, long bias_es, long c_es)
{
    extern __shared__ char dsm[];
    const uint32_t sbase = smem_u32(dsm);

    // expert offset via blockIdx.z
    {
        long ex = (long)blockIdx.z;
        A0 += ex * a0_es;
        if (A1) A1 += ex * a1_es;
        B0 += ex * b_es;
        if (B1) B1 += ex * b_es;
        bias += ex * bias_es;
        C += ex * c_es;
    }

    const int tid  = threadIdx.x;
    const int wid  = tid >> 5;
    const int lane = tid & 31;
    const int wr   = wid >> 1;
    const int wc   = wid & 1;
    const int bm   = blockIdx.x * TBM;
    const int bn   = blockIdx.y * TBN;

    const int nch = (A1 != 0) ? 16 : 8;
    const long bplane = (long)Nc * 256;

    float acc[2][4][4];
#pragma unroll
    for (int i = 0; i < 2; ++i)
#pragma unroll
        for (int j = 0; j < 4; ++j)
#pragma unroll
            for (int q = 0; q < 4; ++q) acc[i][j][q] = 0.f;

    uint32_t aw[16];
    const int arow_g = tid >> 1;
    const int acol_g = (tid & 1) * 16;
    const int brow_g = tid >> 2;
    const int bcol_g = (tid & 3) * 8;

    auto ldgA = [&](int c){
        int seg = c >> 3;
        int k0  = (c & 7) * TBK;
        const uint32_t* A = seg ? A1 : A0;
        const int lda = seg ? lda1 : lda0;
        int gr = bm + arow_g;
        if (gr < M){
            const uint32_t* ap = A + (long)gr*lda + k0 + acol_g;
            uint4 u0 = *(const uint4*)ap;
            uint4 u1 = *(const uint4*)(ap + 4);
            uint4 u2 = *(const uint4*)(ap + 8);
            uint4 u3 = *(const uint4*)(ap + 12);
            aw[0]=u0.x; aw[1]=u0.y; aw[2]=u0.z; aw[3]=u0.w;
            aw[4]=u1.x; aw[5]=u1.y; aw[6]=u1.z; aw[7]=u1.w;
            aw[8]=u2.x; aw[9]=u2.y; aw[10]=u2.z; aw[11]=u2.w;
            aw[12]=u3.x; aw[13]=u3.y; aw[14]=u3.z; aw[15]=u3.w;
        } else {
#pragma unroll
            for (int q = 0; q < 16; ++q) aw[q] = 0u;
        }
    };

    auto cpB = [&](int c, int buf){
        int seg = c >> 3;
        int k0  = (c & 7) * TBK;
        const __nv_bfloat16* B = seg ? B1 : B0;
        const __nv_bfloat16* bp = B + (long)(bn + brow_g)*256 + k0 + bcol_g;
        uint32_t pb = sbase + BS_OFF + (uint32_t)buf*BS_STAGE + (uint32_t)(brow_g*ARS + bcol_g*2);
        cp_async16(pb, bp);
        cp_async16(pb + BS_PLANE, bp + bplane);
        cp_commit();
    };

    auto stsA = [&](int buf){
        uint32_t hh[8], ll[8];
#pragma unroll
        for (int q = 0; q < 8; ++q){
            hh[q] = __byte_perm(aw[2*q], aw[2*q+1], 0x7632);
            ll[q] = __byte_perm(aw[2*q], aw[2*q+1], 0x5410);
        }
        char* pa = dsm + buf*AS_STAGE + arow_g*ARS + acol_g*2;
        *(uint4*)pa        = make_uint4(hh[0], hh[1], hh[2], hh[3]);
        *(uint4*)(pa + 16) = make_uint4(hh[4], hh[5], hh[6], hh[7]);
        *(uint4*)(pa + AS_PLANE)      = make_uint4(ll[0], ll[1], ll[2], ll[3]);
        *(uint4*)(pa + AS_PLANE + 16) = make_uint4(ll[4], ll[5], ll[6], ll[7]);
    };

    const int tile = lane >> 3;
    const int trr  = lane & 7;
    const int arow = wr*32 + ((tile & 1) << 3) + trr;
    const int akk0 = ((tile & 2) << 2);
    const int brow = wc*32 + ((tile & 2) << 2) + trr;
    const int bkk0 = ((tile & 1) << 3);

    auto compute = [&](int buf){
        uint32_t aBase = sbase + (uint32_t)buf*AS_STAGE;
        uint32_t bBase = sbase + BS_OFF + (uint32_t)buf*BS_STAGE;
#pragma unroll
        for (int kt = 0; kt < 2; ++kt){
            uint32_t a_hi[2][4], a_lo[2][4], bb[2][4];
            uint32_t ak = (uint32_t)(akk0 + kt*16)*2;
            uint32_t bk = (uint32_t)(bkk0 + kt*16)*2;
            ldm4(a_hi[0], aBase + (uint32_t)(arow)*ARS + ak);
            ldm4(a_hi[1], aBase + (uint32_t)(arow+16)*ARS + ak);
            ldm4(bb[0],   bBase + (uint32_t)(brow)*ARS + bk);
            ldm4(bb[1],   bBase + (uint32_t)(brow+16)*ARS + bk);
#pragma unroll
            for (int mt = 0; mt < 2; ++mt)
#pragma unroll
                for (int nt = 0; nt < 4; ++nt)
                    mma16816(acc[mt][nt], a_hi[mt], &bb[nt>>1][(nt&1)*2]);
            ldm4(a_lo[0], aBase + AS_PLANE + (uint32_t)(arow)*ARS + ak);
            ldm4(a_lo[1], aBase + AS_PLANE + (uint32_t)(arow+16)*ARS + ak);
#pragma unroll
            for (int mt = 0; mt < 2; ++mt)
#pragma unroll
                for (int nt = 0; nt < 4; ++nt)
                    mma16816(acc[mt][nt], a_lo[mt], &bb[nt>>1][(nt&1)*2]);
            ldm4(bb[0],   bBase + BS_PLANE + (uint32_t)(brow)*ARS + bk);
            ldm4(bb[1],   bBase + BS_PLANE + (uint32_t)(brow+16)*ARS + bk);
#pragma unroll
            for (int mt = 0; mt < 2; ++mt)
#pragma unroll
                for (int nt = 0; nt < 4; ++nt)
                    mma16816(acc[mt][nt], a_hi[mt], &bb[nt>>1][(nt&1)*2]);
        }
    };

    ldgA(0);
    cpB(0, 0);
    stsA(0);
    cp_wait0();
    __syncthreads();
    for (int c = 0; c < nch; ++c){
        if (c + 1 < nch){
            ldgA(c + 1);
            cpB(c + 1, (c + 1) & 1);
        }
        compute(c & 1);
        if (c + 1 < nch){
            stsA((c + 1) & 1);
            cp_wait0();
            __syncthreads();
        }
    }

#pragma unroll
    for (int mt = 0; mt < 2; ++mt){
#pragma unroll
        for (int nt = 0; nt < 4; ++nt){
            int row0 = bm + wr*32 + mt*16 + (lane >> 2);
            int col  = bn + wc*32 + nt*8 + (lane & 3)*2;
            float b0 = bias[col];
            float b1 = bias[col + 1];
#pragma unroll
            for (int half = 0; half < 2; ++half){
                int row = row0 + half*8;
                if (row < M){
                    float v0 = acc[mt][nt][half*2 + 0] + b0;
                    float v1 = acc[mt][nt][half*2 + 1] + b1;
                    if (relu){ v0 = fmaxf(v0, 0.f); v1 = fmaxf(v1, 0.f); }
                    if (out_packed){
                        uint2 o;
                        o.x = pack_hilo(v0);
                        o.y = pack_hilo(v1);
                        *(uint2*)((uint32_t*)C + (long)row*Nc + col) = o;
                    } else {
                        if (addin){
                            uint2 ai = *(const uint2*)(addin + (long)row*Nc + col);
                            v0 += unpack_hilo(ai.x);
                            v1 += unpack_hilo(ai.y);
                        }
                        if (rowscale){
                            float rs = rowscale[(long)row*rs_stride];
                            v0 *= rs; v1 *= rs;
                        }
                        float* cp = C + (long)row*Nc + col;
                        if (accum){ v0 += cp[0]; v1 += cp[1]; }
                        float2 o; o.x = v0; o.y = v1;
                        *(float2*)cp = o;
                    }
                }
            }
        }
    }
}

// ---------------- merged histograms: node counts + edge counts + degrees ----------------
__global__ void prep_graph(const int* __restrict__ batch,
                           const int* __restrict__ src, const int* __restrict__ dst){
    __shared__ int sn[GG];
    __shared__ int se[GG];
    if(threadIdx.x < GG){ sn[threadIdx.x] = 0; se[threadIdx.x] = 0; }
    __syncthreads();
    for(int i = blockIdx.x*blockDim.x + threadIdx.x; i < NN; i += gridDim.x*blockDim.x)
        atomicAdd(&sn[batch[i]], 1);
    for(int i = blockIdx.x*blockDim.x + threadIdx.x; i < EE; i += gridDim.x*blockDim.x){
        atomicAdd(&se[batch[src[i]]], 1);
        atomicAdd(&g_deg[dst[i]], 1);
    }
    __syncthreads();
    if(threadIdx.x < GG){
        if(sn[threadIdx.x]) atomicAdd(&g_ncnt[threadIdx.x], sn[threadIdx.x]);
        if(se[threadIdx.x]) atomicAdd(&g_ecnt[threadIdx.x], se[threadIdx.x]);
    }
}

// ---------------- graph stats ----------------
__global__ void stats_kernel(){
    int g = threadIdx.x;
    float n   = fmaxf((float)g_ncnt[g], 1.f);
    float e   = (float)g_ecnt[g];
    float den = e / fmaxf(n*(n-1.f), 1.f);
    float ln  = logf(n);
    __shared__ float sn[GG], se[GG], sd[GG], sl[GG];
    sn[g]=n; se[g]=e; sd[g]=den; sl[g]=ln;
    __syncthreads();
    __shared__ float sc[8];
    if(g == 0){
        float mn=sl[0], mx=sl[0], s0=0, s1=0, s2=0;
        for(int i=0;i<GG;i++){ mn=fminf(mn,sl[i]); mx=fmaxf(mx,sl[i]); s0+=sn[i]; s1+=se[i]; s2+=sd[i]; }
        float m0=s0/GG, m1=s1/GG, m2=s2/GG;
        float q0=0,q1=0,q2=0;
        for(int i=0;i<GG;i++){
            float d0=sn[i]-m0, d1=se[i]-m1, d2=sd[i]-m2;
            q0+=d0*d0; q1+=d1*d1; q2+=d2*d2;
        }
        sc[0]=mn; sc[1]=mx; sc[2]=m0; sc[3]=m1; sc[4]=m2;
        sc[5]=sqrtf(q0/GG); sc[6]=sqrtf(q1/GG); sc[7]=sqrtf(q2/GG);
    }
    __syncthreads();
    g_lognn[g]       = (ln  - sc[0])/(sc[1]-sc[0]+1e-6f);
    g_featsn[g*3+0]  = (n   - sc[2])/(sc[5]+1e-6f);
    g_featsn[g*3+1]  = (e   - sc[3])/(sc[6]+1e-6f);
    g_featsn[g*3+2]  = (den - sc[4])/(sc[7]+1e-6f);
}

// ---------------- CSR build ----------------
__global__ void scan1(){
    __shared__ int sh[1024];
    int i = blockIdx.x*1024 + threadIdx.x;
    int v = (i < NN) ? g_deg[i] : 0;
    sh[threadIdx.x] = v;
    __syncthreads();
    for(int off=1; off<1024; off<<=1){
        int t = sh[threadIdx.x];
        if(threadIdx.x >= off) t += sh[threadIdx.x - off];
        __syncthreads();
        sh[threadIdx.x] = t;
        __syncthreads();
    }
    if(i < NN) g_rowptr[i] = sh[threadIdx.x] - v;
    if(threadIdx.x == 1023) g_bsum[blockIdx.x] = sh[1023];
}

__global__ void scan2(int nb){
    if(threadIdx.x == 0){
        int run = 0;
        for(int b=0;b<nb;b++){ int v=g_bsum[b]; g_bsum[b]=run; run+=v; }
    }
}

__global__ void scan3(){
    int i = blockIdx.x*blockDim.x + threadIdx.x;
    if(i < NN) g_rowptr[i] += g_bsum[i >> 10];
    if(i == 0) g_rowptr[NN] = EE;
}

__global__ void place_edges(const int* __restrict__ src, const int* __restrict__ dst){
    for(int i = blockIdx.x*blockDim.x + threadIdx.x; i < EE; i += gridDim.x*blockDim.x){
        int d = dst[i];
        int idx = g_rowptr[d] + atomicAdd(&g_cur[d], 1);
        g_esrc[idx] = src[i];
    }
}

// ---------------- CSR gather aggregation (packed, grouped) ----------------
__global__ void aggregate_pg(const uint32_t* __restrict__ in, uint32_t* __restrict__ out,
                             int Win, long in_goff, int Wout, long out_goff){
    int n = blockIdx.x;
    const uint32_t* ip = in + (long)blockIdx.y * in_goff;
    uint32_t* op = out + (long)blockIdx.y * out_goff;
    int s0 = g_rowptr[n], s1 = g_rowptr[n+1];
    float a0=0.f, a1=0.f, a2=0.f, a3=0.f, a4=0.f, a5=0.f, a6=0.f, a7=0.f;
    int j = s0;
    for(; j + 8 <= s1; j += 8){
        int i0 = g_esrc[j],   i1 = g_esrc[j+1], i2 = g_esrc[j+2], i3 = g_esrc[j+3];
        int i4 = g_esrc[j+4], i5 = g_esrc[j+5], i6 = g_esrc[j+6], i7 = g_esrc[j+7];
        a0 += unpack_hilo(ip[(long)i0*Win + threadIdx.x]);
        a1 += unpack_hilo(ip[(long)i1*Win + threadIdx.x]);
        a2 += unpack_hilo(ip[(long)i2*Win + threadIdx.x]);
        a3 += unpack_hilo(ip[(long)i3*Win + threadIdx.x]);
        a4 += unpack_hilo(ip[(long)i4*Win + threadIdx.x]);
        a5 += unpack_hilo(ip[(long)i5*Win + threadIdx.x]);
        a6 += unpack_hilo(ip[(long)i6*Win + threadIdx.x]);
        a7 += unpack_hilo(ip[(long)i7*Win + threadIdx.x]);
    }
    for(; j < s1; ++j)
        a0 += unpack_hilo(ip[(long)g_esrc[j]*Win + threadIdx.x]);
    op[(long)n*Wout + threadIdx.x] = pack_hilo(((a0 + a1) + (a2 + a3)) + ((a4 + a5) + (a6 + a7)));
}

// ---------------- final: aggregate t_e + combine across experts (top-2 sparse) ----------------
__global__ void agg_combine(const uint32_t* __restrict__ te, const float* __restrict__ w,
                            const float* __restrict__ b2, float* __restrict__ out){
    int n = blockIdx.x;
    int c = threadIdx.x;          // 0..127
    int s0 = g_rowptr[n], s1 = g_rowptr[n+1];
    float res = 0.f;
    for (int e = 0; e < NEXP; ++e){
        float we = w[n*NEXP + e];
        if (we == 0.f) continue;                  // top-2 sparsity: exact zero weight
        const uint32_t* tp = te + (long)e*NN*256;
        float a0=0.f, a1=0.f, a2=0.f, a3=0.f;
        int j = s0;
        for(; j + 4 <= s1; j += 4){
            int i0 = g_esrc[j], i1 = g_esrc[j+1], i2 = g_esrc[j+2], i3 = g_esrc[j+3];
            a0 += unpack_hilo(tp[(long)i0*256 + c]);
            a1 += unpack_hilo(tp[(long)i1*256 + c]);
            a2 += unpack_hilo(tp[(long)i2*256 + c]);
            a3 += unpack_hilo(tp[(long)i3*256 + c]);
        }
        for(; j < s1; ++j)
            a0 += unpack_hilo(tp[(long)g_esrc[j]*256 + c]);
        float agg = (a0 + a1) + (a2 + a3);
        float root = unpack_hilo(tp[(long)n*256 + 128 + c]);
        res += we * (agg + root + b2[e*OD + c]);
    }
    out[(long)n*OD + c] = res;
}

// ---------------- router (fused sf lookup + K=3 correction) ----------------
__global__ void router_kernel(const float* __restrict__ t, const int* __restrict__ batch,
                              const float* __restrict__ lng, const float* __restrict__ lnb,
                              const float* __restrict__ W2, const float* __restrict__ b2,
                              const float* __restrict__ centers,
                              const float* __restrict__ W1s)
{
    int n = blockIdx.x; int tid = threadIdx.x;
    int lane = tid & 31, wid = tid >> 5;
    int grp = batch[n];
    float s0f = g_featsn[grp*3+0], s1f = g_featsn[grp*3+1], s2f = g_featsn[grp*3+2];
    float v = t[(long)n*HH + tid]
            + s0f * W1s[tid] + s1f * W1s[HH + tid] + s2f * W1s[2*HH + tid];
    float s = v, sq = v*v;
#pragma unroll
    for(int o=16;o>0;o>>=1){
        s  += __shfl_down_sync(0xffffffffu, s,  o);
        sq += __shfl_down_sync(0xffffffffu, sq, o);
    }
    __shared__ float red[8*2];
    __shared__ float red4[8*4];
    __shared__ float bc[2];
    if(lane == 0){ red[wid*2]=s; red[wid*2+1]=sq; }
    __syncthreads();
    if(tid == 0){
        float S=0, Q=0;
        for(int w=0;w<8;w++){ S+=red[w*2]; Q+=red[w*2+1]; }
        float mean = S/HH;
        bc[0]=mean; bc[1]=Q/HH - mean*mean;
    }
    __syncthreads();
    float mean = bc[0], var = bc[1];
    float r = (v - mean)*rsqrtf(var + 1e-5f)*lng[tid] + lnb[tid];
    r = fmaxf(r, 0.f);
    float p[4];
#pragma unroll
    for(int e=0;e<4;e++) p[e] = r * W2[tid*4+e];
#pragma unroll
    for(int o=16;o>0;o>>=1)
#pragma unroll
        for(int e=0;e<4;e++) p[e] += __shfl_down_sync(0xffffffffu, p[e], o);
    if(lane == 0)
        for(int e=0;e<4;e++) red4[wid*4+e] = p[e];
    __syncthreads();
    if(tid == 0){
        float logit[4], probs[4];
        float lnode = g_lognn[grp];
        for(int e=0;e<4;e++){
            float sum = 0;
            for(int w=0;w<8;w++) sum += red4[w*4+e];
            float learned = sum + b2[e];
            float d = lnode - centers[e];
            logit[e] = 0.7f*learned - 0.3f*d*d;
        }
        float mx = logit[0];
        for(int e=1;e<4;e++) mx = fmaxf(mx, logit[e]);
        float ssum = 0;
        for(int e=0;e<4;e++){ probs[e] = expf(logit[e]-mx); ssum += probs[e]; }
        for(int e=0;e<4;e++) probs[e] /= ssum;
        int i0 = 0;
        for(int e=1;e<4;e++) if(probs[e] > probs[i0]) i0 = e;
        int i1 = -1;
        for(int e=0;e<4;e++){
            if(e == i0) continue;
            if(i1 < 0 || probs[e] > probs[i1]) i1 = e;
        }
        float denom = probs[i0] + probs[i1] + 1e-8f;
        float wv[4] = {0.f,0.f,0.f,0.f};
        wv[i0] = probs[i0]/denom;
        wv[i1] = probs[i1]/denom;
        for(int e=0;e<4;e++) g_w[(long)n*4+e] = wv[e];
    }
}

// ---------------- host ----------------
extern "C" void kernel_launch(void* const* d_in, const int* in_sizes, int n_in,
                              void* d_out, int out_size)
{
    const float* x       = (const float*)d_in[0];
    const int*   ei      = (const int*)  d_in[1];
    const int*   batch   = (const int*)  d_in[2];
    const float* enc_W1  = (const float*)d_in[3];
    const float* enc_b1  = (const float*)d_in[4];
    const float* enc_W2  = (const float*)d_in[5];
    const float* enc_b2  = (const float*)d_in[6];
    const float* r_W1    = (const float*)d_in[7];
    const float* r_b1    = (const float*)d_in[8];
    const float* ln_g    = (const float*)d_in[9];
    const float* ln_b    = (const float*)d_in[10];
    const float* r_W2    = (const float*)d_in[11];
    const float* r_b2    = (const float*)d_in[12];
    const float* centers = (const float*)d_in[13];
    const float* W0_rel  = (const float*)d_in[14];
    const float* b0_rel  = (const float*)d_in[15];
    const float* W0_root = (const float*)d_in[16];
    const float* W1_rel  = (const float*)d_in[17];
    const float* b1_rel  = (const float*)d_in[18];
    const float* W1_root = (const float*)d_in[19];
    const float* W2_rel  = (const float*)d_in[20];
    const float* b2_rel  = (const float*)d_in[21];
    const float* W2_root = (const float*)d_in[22];
    const int* src = ei;
    const int* dst = ei + EE;
    float* out = (float*)d_out;

    float *p_h1,*p_h,*p_w,*p_wt,*p_zero;
    uint32_t *p_hp,*p_agg,*p_hE0,*p_hE1,*p_aggE;
    int *p_ncnt,*p_ecnt,*p_deg,*p_cur;
    __nv_bfloat16* p_wb;
    cudaGetSymbolAddress((void**)&p_h1,  g_h1);
    cudaGetSymbolAddress((void**)&p_h,   g_h);
    cudaGetSymbolAddress((void**)&p_hp,  g_hp);
    cudaGetSymbolAddress((void**)&p_agg, g_agg);
    cudaGetSymbolAddress((void**)&p_w,   g_w);
    cudaGetSymbolAddress((void**)&p_hE0, g_hE0);
    cudaGetSymbolAddress((void**)&p_hE1, g_hE1);
    cudaGetSymbolAddress((void**)&p_aggE,g_aggE);
    cudaGetSymbolAddress((void**)&p_ncnt,g_ncnt);
    cudaGetSymbolAddress((void**)&p_ecnt,g_ecnt);
    cudaGetSymbolAddress((void**)&p_deg, g_deg);
    cudaGetSymbolAddress((void**)&p_cur, g_cur);
    cudaGetSymbolAddress((void**)&p_wb,  g_wbuf);
    cudaGetSymbolAddress((void**)&p_wt,  g_wt);
    cudaGetSymbolAddress((void**)&p_zero,g_zero);

    cudaFuncSetAttribute(tgemm, cudaFuncAttributeMaxDynamicSharedMemorySize, SMEM_DYN);

    // ---- weight prep ----
    prep_wt<<<256,256>>>(enc_W2, p_wt);
    prep_wt<<<256,256>>>(r_W1,   p_wt + 65536);
    prep_wc<<<1024,256>>>(W0_rel,  p_wb + OFF_L0C);
    prep_wc<<<1024,256>>>(W0_root, p_wb + OFF_L0CR);
    prep_w<<<256,256>>>(W1_rel,  p_wb + OFF_L1,          256, 4, 65536, 262144);
    prep_w<<<256,256>>>(W1_root, p_wb + OFF_L1 + 131072, 256, 4, 65536, 262144);
    prep_w2c<<<1024,256>>>(W2_rel, W2_root, p_wb + OFF_L2);

    // ---- stats + CSR prep ----
    cudaMemsetAsync(p_ncnt, 0, GG*sizeof(int));
    cudaMemsetAsync(p_ecnt, 0, GG*sizeof(int));
    cudaMemsetAsync(p_deg,  0, NN*sizeof(int));
    cudaMemsetAsync(p_cur,  0, NN*sizeof(int));
    prep_graph<<<784, 256>>>(batch, src, dst);
    stats_kernel<<<1, GG>>>();
    int nscan = (NN+1023)/1024;
    scan1<<<nscan, 1024>>>();
    scan2<<<1, 32>>>(nscan);
    scan3<<<(NN+255)/256, 256>>>();
    place_edges<<<784, 256>>>(src, dst);

    const int TGRIDX = (NN + TBM - 1) / TBM;
    const dim3 fgrid((NN + FBM - 1) / FBM, 4);

    // ---- encoder (exact-class: fused K=6 kernel, then 3xTF32 tensor with fused pack) ----
    enc1_kernel<<<NN, 256>>>(x, enc_W1, enc_b1, p_h1);
    tf32gemm<<<fgrid, 256>>>(p_h1, p_wt, enc_b2, p_h, p_hp, NN);

    // ---- router (3xTF32 main; sf lookup + K=3 correction fused into router kernel) ----
    tf32gemm<<<fgrid, 256>>>(p_h, p_wt + 65536, r_b1, p_h1, (uint32_t*)0, NN);
    router_kernel<<<NN, 256>>>(p_h1, batch, ln_g, ln_b, r_W2, r_b2, centers,
                               r_W1 + HH*HH);

    // ---- aggregate h (packed) ----
    aggregate_pg<<<dim3(NN,1), 256>>>(p_hp, p_agg, 256, 0, 256, 0);

    // ---- expert layer 0: single batched GEMM, Nc=1024, output hE0 as [n][1024] ----
    {
        dim3 grid(TGRIDX, 1024 / TBN, 1);
        tgemm<<<grid, 256, SMEM_DYN>>>(p_agg, 256, p_hp, 256,
                                       p_wb + OFF_L0C, p_wb + OFF_L0CR,
                                       b0_rel, (float*)p_hE0, 1024, NN, 1, 1, 0,
                                       (const float*)0, 0, (const uint32_t*)0,
                                       0, 0, 0, 0, 0);
    }
    // aggregate hE0 per expert: in [n][1024] col-block e*256, out aggE[e][n][256]
    aggregate_pg<<<dim3(NN,4), 256>>>(p_hE0, p_aggE, 1024, 256, 256, (long)NN*256);

    // ---- expert layer 1: one batched launch over 4 experts (blockIdx.z) ----
    {
        dim3 grid(TGRIDX, 256 / TBN, NEXP);
        tgemm<<<grid, 256, SMEM_DYN>>>(p_aggE, 256,
                                       p_hE0, 1024,
                                       p_wb + OFF_L1,
                                       p_wb + OFF_L1 + 131072,
                                       b1_rel, (float*)p_hE1,
                                       HH, NN, 1, 1, 0,
                                       (const float*)0, 0, (const uint32_t*)0,
                                       (long)NN*HH, 256, 262144, HH, (long)NN*HH);
    }

    // ---- expert layer 2, merged, batched: [t_e | root_e] = hE1 @ [W2_rel|W2_root] ----
    {
        dim3 grid(TGRIDX, 256 / TBN, NEXP);
        tgemm<<<grid, 256, SMEM_DYN>>>(p_hE1, 256,
                                       (const uint32_t*)0, 0,
                                       p_wb + OFF_L2, (const __nv_bfloat16*)0,
                                       p_zero, (float*)p_aggE,
                                       256, NN, 0, 1, 0,
                                       (const float*)0, 0, (const uint32_t*)0,
                                       (long)NN*HH, 0, 131072, 0, (long)NN*HH);
    }
    // ---- aggregate t_e + combine across experts -> out (top-2 sparse, no memset, no RMW) ----
    agg_combine<<<NN, OD>>>(p_aggE, p_w, b2_rel, out);
}